// round 4
// baseline (speedup 1.0000x reference)
#include <cuda_runtime.h>
#include <cstdint>

#define N_NODES 100000
#define N_EDGES 500000
#define HID 128
#define OUTD 349
#define NET 8
#define BN_EPS 1e-5f

// ---------------- scratch (static device globals; no allocation) ----------
__device__ float g_h[N_NODES * HID];     // input-linear output, later y = prelu(bn(x))
__device__ float g_x[N_NODES * HID];     // conv0 output + residual (BN input)
__device__ float g_agg0[N_NODES * HID];  // scatter target layer 0
__device__ float g_agg1[N_NODES * HID];  // scatter target layer 1
__device__ float g_ew0[N_EDGES], g_ew1[N_EDGES];
__device__ float g_deg0[N_NODES], g_deg1[N_NODES];
__device__ float g_rws[2 * NET];
__device__ float g_sum[HID], g_sumsq[HID];
__device__ float g_bnscale[HID], g_bnshift[HID];

// ---------------- tiny prep ----------------------------------------------
__global__ void k_rws(const float* __restrict__ rw0,
                      const float* __restrict__ rw1) {
    int i = threadIdx.x;
    if (i < NET) {
        float v = rw0[i] * 100.0f;
        g_rws[i] = (v >= 0.0f) ? v : 0.01f * v;
    } else if (i < 2 * NET) {
        float v = rw1[i - NET] * 100.0f;
        g_rws[i] = (v >= 0.0f) ? v : 0.01f * v;
    }
}

__global__ void k_zero_small() {
    int i = blockIdx.x * blockDim.x + threadIdx.x;
    if (i < N_NODES) { g_deg0[i] = 0.0f; g_deg1[i] = 0.0f; }
    if (i < HID)     { g_sum[i] = 0.0f;  g_sumsq[i] = 0.0f; }
}

__global__ void k_zero_aggs() {
    const int total = N_NODES * HID / 4;
    float4 z = {0.f, 0.f, 0.f, 0.f};
    for (int i = blockIdx.x * blockDim.x + threadIdx.x; i < total;
         i += gridDim.x * blockDim.x) {
        ((float4*)g_agg0)[i] = z;
        ((float4*)g_agg1)[i] = z;
    }
}

// edge_index is int32 [2, E]; edge_type int32 [E]
__global__ void k_deg(const int* __restrict__ ei,
                      const int* __restrict__ et) {
    int e = blockIdx.x * blockDim.x + threadIdx.x;
    if (e >= N_EDGES) return;
    int c = ei[N_EDGES + e];
    int t = et[e];
    atomicAdd(&g_deg0[c], g_rws[t]);
    atomicAdd(&g_deg1[c], g_rws[NET + t]);
}

__global__ void k_ew(const int* __restrict__ ei,
                     const int* __restrict__ et) {
    int e = blockIdx.x * blockDim.x + threadIdx.x;
    if (e >= N_EDGES) return;
    int t = et[e];
    int c = ei[N_EDGES + e];
    g_ew0[e] = g_rws[t] / fabsf(g_deg0[c]);
    g_ew1[e] = g_rws[NET + t] / fabsf(g_deg1[c]);
}

// ---------------- GEMMs: BM=64, BN=128, K=128, 256 threads, 8x4/thread ----
// smem: As[64][128] (32KB) + Ws[128][128] (64KB) = 96KB dynamic

// input linear: two passes. pass t: A[n] = (node_type[n]==t) ? x_t[lidx[n]] : 0
// pass0: g_h = A0 @ W0 ; pass1: g_h += A1 @ W1 + b_{type[n]}
__global__ __launch_bounds__(256) void k_gemm_input(
    const float* __restrict__ x0, const float* __restrict__ x1,
    const int* __restrict__ ntype, const int* __restrict__ lidx,
    const float* __restrict__ W, const float* __restrict__ b0,
    const float* __restrict__ b1, int pass) {
    extern __shared__ float smem[];
    float* As = smem;
    float* Ws = smem + 64 * 128;
    const int m0 = blockIdx.x * 64;

    const float4* W4 = (const float4*)W;
    for (int idx = threadIdx.x; idx < 128 * 32; idx += 256)
        ((float4*)Ws)[idx] = W4[idx];

    for (int idx = threadIdx.x; idx < 64 * 32; idx += 256) {
        int row = idx >> 5, kk = idx & 31;
        int gr = m0 + row;
        float4 v = {0.f, 0.f, 0.f, 0.f};
        if (gr < N_NODES) {
            int t = ntype[gr];
            if (t == pass) {
                int l = lidx[gr];
                const float4* src =
                    (const float4*)((pass == 0 ? x0 : x1) + (size_t)l * 128);
                v = src[kk];
            }
        }
        ((float4*)As)[idx] = v;
    }
    __syncthreads();

    const int cg = threadIdx.x & 31, rg = threadIdx.x >> 5;
    const int c0 = cg * 4, r0 = rg * 8;
    float acc[8][4] = {};
    const float4* As4 = (const float4*)As;
    const float4* Ws4 = (const float4*)Ws;
#pragma unroll
    for (int kk = 0; kk < 32; kk++) {
        float4 wv[4];
#pragma unroll
        for (int i = 0; i < 4; i++) wv[i] = Ws4[(kk * 4 + i) * 32 + cg];
        const float* w = (const float*)wv;
#pragma unroll
        for (int r = 0; r < 8; r++) {
            float4 av = As4[(r0 + r) * 32 + kk];
#pragma unroll
            for (int c = 0; c < 4; c++)
                acc[r][c] += av.x * w[0 * 4 + c] + av.y * w[1 * 4 + c] +
                             av.z * w[2 * 4 + c] + av.w * w[3 * 4 + c];
        }
    }

#pragma unroll
    for (int r = 0; r < 8; r++) {
        int gr = m0 + r0 + r;
        if (gr >= N_NODES) continue;
        float4* Crow = (float4*)(g_h + (size_t)gr * HID + c0);
        float4 res = {acc[r][0], acc[r][1], acc[r][2], acc[r][3]};
        if (pass == 1) {
            float4 old = *Crow;
            int t = ntype[gr];
            const float* bb = (t ? b1 : b0) + c0;
            res.x += old.x + bb[0];
            res.y += old.y + bb[1];
            res.z += old.z + bb[2];
            res.w += old.w + bb[3];
        }
        *Crow = res;
    }
}

// g_x = g_agg0 @ conv0_w + conv0_b + g_h (residual)
__global__ __launch_bounds__(256) void k_gemm0(const float* __restrict__ W,
                                               const float* __restrict__ b) {
    extern __shared__ float smem[];
    float* As = smem;
    float* Ws = smem + 64 * 128;
    const int m0 = blockIdx.x * 64;

    const float4* W4 = (const float4*)W;
    for (int idx = threadIdx.x; idx < 128 * 32; idx += 256)
        ((float4*)Ws)[idx] = W4[idx];
    for (int idx = threadIdx.x; idx < 64 * 32; idx += 256) {
        int row = idx >> 5, kk = idx & 31;
        int gr = m0 + row;
        float4 v = {0.f, 0.f, 0.f, 0.f};
        if (gr < N_NODES) v = ((const float4*)(g_agg0 + (size_t)gr * HID))[kk];
        ((float4*)As)[idx] = v;
    }
    __syncthreads();

    const int cg = threadIdx.x & 31, rg = threadIdx.x >> 5;
    const int c0 = cg * 4, r0 = rg * 8;
    float acc[8][4] = {};
    const float4* As4 = (const float4*)As;
    const float4* Ws4 = (const float4*)Ws;
#pragma unroll
    for (int kk = 0; kk < 32; kk++) {
        float4 wv[4];
#pragma unroll
        for (int i = 0; i < 4; i++) wv[i] = Ws4[(kk * 4 + i) * 32 + cg];
        const float* w = (const float*)wv;
#pragma unroll
        for (int r = 0; r < 8; r++) {
            float4 av = As4[(r0 + r) * 32 + kk];
#pragma unroll
            for (int c = 0; c < 4; c++)
                acc[r][c] += av.x * w[0 * 4 + c] + av.y * w[1 * 4 + c] +
                             av.z * w[2 * 4 + c] + av.w * w[3 * 4 + c];
        }
    }
#pragma unroll
    for (int r = 0; r < 8; r++) {
        int gr = m0 + r0 + r;
        if (gr >= N_NODES) continue;
        float4 hres = *(const float4*)(g_h + (size_t)gr * HID + c0);
        float4 res;
        res.x = acc[r][0] + b[c0 + 0] + hres.x;
        res.y = acc[r][1] + b[c0 + 1] + hres.y;
        res.z = acc[r][2] + b[c0 + 2] + hres.z;
        res.w = acc[r][3] + b[c0 + 3] + hres.w;
        *(float4*)(g_x + (size_t)gr * HID + c0) = res;
    }
}

// out = g_agg1 @ conv1_w + conv1_b   (OUTD=349 columns, 3 column blocks)
__global__ __launch_bounds__(256) void k_gemm1(const float* __restrict__ W,
                                               const float* __restrict__ b,
                                               float* __restrict__ out) {
    extern __shared__ float smem[];
    float* As = smem;
    float* Ws = smem + 64 * 128;
    const int m0 = blockIdx.x * 64;
    const int n0 = blockIdx.y * 128;
    const int nc = (OUTD - n0 < 128) ? (OUTD - n0) : 128;

    for (int idx = threadIdx.x; idx < 128 * 128; idx += 256) {
        int k = idx >> 7, c = idx & 127;
        Ws[idx] = (c < nc) ? W[k * OUTD + n0 + c] : 0.0f;
    }
    for (int idx = threadIdx.x; idx < 64 * 32; idx += 256) {
        int row = idx >> 5, kk = idx & 31;
        int gr = m0 + row;
        float4 v = {0.f, 0.f, 0.f, 0.f};
        if (gr < N_NODES) v = ((const float4*)(g_agg1 + (size_t)gr * HID))[kk];
        ((float4*)As)[idx] = v;
    }
    __syncthreads();

    const int cg = threadIdx.x & 31, rg = threadIdx.x >> 5;
    const int c0 = cg * 4, r0 = rg * 8;
    float acc[8][4] = {};
    const float4* As4 = (const float4*)As;
    const float4* Ws4 = (const float4*)Ws;
#pragma unroll
    for (int kk = 0; kk < 32; kk++) {
        float4 wv[4];
#pragma unroll
        for (int i = 0; i < 4; i++) wv[i] = Ws4[(kk * 4 + i) * 32 + cg];
        const float* w = (const float*)wv;
#pragma unroll
        for (int r = 0; r < 8; r++) {
            float4 av = As4[(r0 + r) * 32 + kk];
#pragma unroll
            for (int c = 0; c < 4; c++)
                acc[r][c] += av.x * w[0 * 4 + c] + av.y * w[1 * 4 + c] +
                             av.z * w[2 * 4 + c] + av.w * w[3 * 4 + c];
        }
    }
#pragma unroll
    for (int r = 0; r < 8; r++) {
        int gr = m0 + r0 + r;
        if (gr >= N_NODES) continue;
        float* Crow = out + (size_t)gr * OUTD;
#pragma unroll
        for (int c = 0; c < 4; c++) {
            int col = n0 + c0 + c;
            if (col < OUTD) Crow[col] = acc[r][c] + b[col];
        }
    }
}

// ---------------- scatter: agg[col] += ew[e] * h[row], 128 thr/edge --------
__global__ void k_scatter(const int* __restrict__ ei, int layer) {
    long long idx = blockIdx.x * (long long)blockDim.x + threadIdx.x;
    int e = (int)(idx >> 7);
    int j = (int)(idx & 127);
    if (e >= N_EDGES) return;
    const float* ew = (layer == 0) ? g_ew0 : g_ew1;
    float* dst = (layer == 0) ? g_agg0 : g_agg1;
    float w = __ldg(&ew[e]);
    int r = ei[e];
    int c = ei[N_EDGES + e];
    float v = w * __ldg(&g_h[(size_t)r * HID + j]);
    atomicAdd(dst + (size_t)c * HID + j, v);
}

// ---------------- BN -------------------------------------------------------
__global__ __launch_bounds__(128) void k_stats() {
    int j = threadIdx.x;
    float s = 0.f, s2 = 0.f;
    for (int n = blockIdx.x; n < N_NODES; n += gridDim.x) {
        float v = g_x[(size_t)n * HID + j];
        s += v;
        s2 += v * v;
    }
    atomicAdd(&g_sum[j], s);
    atomicAdd(&g_sumsq[j], s2);
}

__global__ void k_bnfinal(const float* __restrict__ gamma,
                          const float* __restrict__ beta) {
    int j = threadIdx.x;
    if (j >= HID) return;
    float mean = g_sum[j] / (float)N_NODES;
    float var = g_sumsq[j] / (float)N_NODES - mean * mean;
    float sc = gamma[j] * rsqrtf(var + BN_EPS);
    g_bnscale[j] = sc;
    g_bnshift[j] = beta[j] - mean * sc;
}

// y = prelu(bn(x)) -> overwrite g_h (h is dead after gemm0)
__global__ void k_bnapply(const float* __restrict__ prelu_a) {
    const float a = prelu_a[0];
    const int total = N_NODES * HID / 4;
    for (int i = blockIdx.x * blockDim.x + threadIdx.x; i < total;
         i += gridDim.x * blockDim.x) {
        int kk = i & 31;  // column group within row (HID/4 = 32)
        float4 x = ((const float4*)g_x)[i];
        float4 sc = ((const float4*)g_bnscale)[kk];
        float4 sh = ((const float4*)g_bnshift)[kk];
        float4 v;
        v.x = x.x * sc.x + sh.x;
        v.y = x.y * sc.y + sh.y;
        v.z = x.z * sc.z + sh.z;
        v.w = x.w * sc.w + sh.w;
        v.x = (v.x >= 0.f) ? v.x : a * v.x;
        v.y = (v.y >= 0.f) ? v.y : a * v.y;
        v.z = (v.z >= 0.f) ? v.z : a * v.z;
        v.w = (v.w >= 0.f) ? v.w : a * v.w;
        ((float4*)g_h)[i] = v;
    }
}

// ---------------- log_softmax (in place on d_out) --------------------------
__global__ __launch_bounds__(128) void k_logsoftmax(float* __restrict__ out) {
    int n = blockIdx.x;
    float* row = out + (size_t)n * OUTD;
    int j = threadIdx.x;
    float v0 = row[j];
    float v1 = (j + 128 < OUTD) ? row[j + 128] : -1e30f;
    float v2 = (j + 256 < OUTD) ? row[j + 256] : -1e30f;
    __shared__ float red[128];
    float m = fmaxf(v0, fmaxf(v1, v2));
    red[j] = m;
    __syncthreads();
#pragma unroll
    for (int s = 64; s > 0; s >>= 1) {
        if (j < s) red[j] = fmaxf(red[j], red[j + s]);
        __syncthreads();
    }
    float mx = red[0];
    __syncthreads();
    float e = expf(v0 - mx);
    if (j + 128 < OUTD) e += expf(v1 - mx);
    if (j + 256 < OUTD) e += expf(v2 - mx);
    red[j] = e;
    __syncthreads();
#pragma unroll
    for (int s = 64; s > 0; s >>= 1) {
        if (j < s) red[j] += red[j + s];
        __syncthreads();
    }
    float lse = logf(red[0]) + mx;
    row[j] = v0 - lse;
    if (j + 128 < OUTD) row[j + 128] = v1 - lse;
    if (j + 256 < OUTD) row[j + 256] = v2 - lse;
}

// ---------------- launch ---------------------------------------------------
extern "C" void kernel_launch(void* const* d_in, const int* in_sizes, int n_in,
                              void* d_out, int out_size) {
    const float* x0 = (const float*)d_in[0];
    const float* x1 = (const float*)d_in[1];
    const int* edge_index = (const int*)d_in[2];   // int32 per harness contract
    const int* edge_type = (const int*)d_in[3];
    const int* node_type = (const int*)d_in[4];
    const int* lidx = (const int*)d_in[5];
    const float* lin0_w = (const float*)d_in[6];
    const float* lin0_b = (const float*)d_in[7];
    const float* lin1_w = (const float*)d_in[8];
    const float* lin1_b = (const float*)d_in[9];
    const float* conv0_w = (const float*)d_in[10];
    const float* conv0_b = (const float*)d_in[11];
    const float* conv0_rw = (const float*)d_in[12];
    const float* conv1_w = (const float*)d_in[13];
    const float* conv1_b = (const float*)d_in[14];
    const float* conv1_rw = (const float*)d_in[15];
    const float* bn_g = (const float*)d_in[16];
    const float* bn_b = (const float*)d_in[17];
    const float* prelu_a = (const float*)d_in[18];
    float* out = (float*)d_out;

    const int SMEM = (64 * 128 + 128 * 128) * 4;  // 96KB
    cudaFuncSetAttribute(k_gemm_input, cudaFuncAttributeMaxDynamicSharedMemorySize, SMEM);
    cudaFuncSetAttribute(k_gemm0, cudaFuncAttributeMaxDynamicSharedMemorySize, SMEM);
    cudaFuncSetAttribute(k_gemm1, cudaFuncAttributeMaxDynamicSharedMemorySize, SMEM);

    const int MB = (N_NODES + 63) / 64;  // 1563

    k_rws<<<1, 32>>>(conv0_rw, conv1_rw);
    k_zero_small<<<(N_NODES + 255) / 256, 256>>>();
    k_zero_aggs<<<2048, 256>>>();
    k_deg<<<(N_EDGES + 255) / 256, 256>>>(edge_index, edge_type);
    k_ew<<<(N_EDGES + 255) / 256, 256>>>(edge_index, edge_type);

    k_gemm_input<<<MB, 256, SMEM>>>(x0, x1, node_type, lidx, lin0_w, lin0_b, lin1_b, 0);
    k_gemm_input<<<MB, 256, SMEM>>>(x0, x1, node_type, lidx, lin1_w, lin0_b, lin1_b, 1);

    const int SC_BLOCKS = (int)(((long long)N_EDGES * 128 + 255) / 256);

    // layer 0: scatter in HID space, then GEMM (+bias+residual)
    k_scatter<<<SC_BLOCKS, 256>>>(edge_index, 0);
    k_gemm0<<<MB, 256, SMEM>>>(conv0_w, conv0_b);

    k_stats<<<512, 128>>>();
    k_bnfinal<<<1, 128>>>(bn_g, bn_b);
    k_bnapply<<<2048, 256>>>(prelu_a);

    // layer 1: scatter in HID space, then GEMM to 349 outputs
    k_scatter<<<SC_BLOCKS, 256>>>(edge_index, 1);
    k_gemm1<<<dim3(MB, 3), 256, SMEM>>>(conv1_w, conv1_b, out);

    k_logsoftmax<<<N_NODES, 128>>>(out);
}

// round 5
// speedup vs baseline: 1.3050x; 1.3050x over previous
#include <cuda_runtime.h>
#include <cstdint>

#define N_NODES 100000
#define N_EDGES 500000
#define HID 128
#define OUTD 349
#define NET 8
#define BN_EPS 1e-5f

// ---------------- scratch (static device globals; no allocation) ----------
__device__ float g_h[N_NODES * HID];     // input-linear output, later y = prelu(bn(x))
__device__ float g_x[N_NODES * HID];     // conv0 output + residual (BN input)
__device__ float g_agg0[N_NODES * HID];  // scatter target layer 0
__device__ float g_agg1[N_NODES * HID];  // scatter target layer 1
__device__ float g_ew0[N_EDGES], g_ew1[N_EDGES];
__device__ float g_deg0[N_NODES], g_deg1[N_NODES];
__device__ float g_rws[2 * NET];
__device__ float g_sum[HID], g_sumsq[HID];
__device__ float g_bnscale[HID], g_bnshift[HID];
__device__ int   g_cnt[2];
__device__ int   g_list0[N_NODES], g_list1[N_NODES];

// ---------------- tiny prep ----------------------------------------------
__global__ void k_rws(const float* __restrict__ rw0,
                      const float* __restrict__ rw1) {
    int i = threadIdx.x;
    if (i < NET) {
        float v = rw0[i] * 100.0f;
        g_rws[i] = (v >= 0.0f) ? v : 0.01f * v;
    } else if (i < 2 * NET) {
        float v = rw1[i - NET] * 100.0f;
        g_rws[i] = (v >= 0.0f) ? v : 0.01f * v;
    }
}

__global__ void k_zero_small() {
    int i = blockIdx.x * blockDim.x + threadIdx.x;
    if (i < N_NODES) { g_deg0[i] = 0.0f; g_deg1[i] = 0.0f; }
    if (i < HID)     { g_sum[i] = 0.0f;  g_sumsq[i] = 0.0f; }
    if (i < 2)       { g_cnt[i] = 0; }
}

__global__ void k_zero_aggs() {
    const int total = N_NODES * HID / 4;
    float4 z = {0.f, 0.f, 0.f, 0.f};
    for (int i = blockIdx.x * blockDim.x + threadIdx.x; i < total;
         i += gridDim.x * blockDim.x) {
        ((float4*)g_agg0)[i] = z;
        ((float4*)g_agg1)[i] = z;
    }
}

__global__ void k_partition(const int* __restrict__ ntype) {
    int n = blockIdx.x * blockDim.x + threadIdx.x;
    if (n >= N_NODES) return;
    int t = ntype[n];
    int p = atomicAdd(&g_cnt[t], 1);
    if (t == 0) g_list0[p] = n; else g_list1[p] = n;
}

// edge_index is int32 [2, E]; edge_type int32 [E]
__global__ void k_deg(const int* __restrict__ ei,
                      const int* __restrict__ et) {
    int e = blockIdx.x * blockDim.x + threadIdx.x;
    if (e >= N_EDGES) return;
    int c = ei[N_EDGES + e];
    int t = et[e];
    atomicAdd(&g_deg0[c], g_rws[t]);
    atomicAdd(&g_deg1[c], g_rws[NET + t]);
}

__global__ void k_ew(const int* __restrict__ ei,
                     const int* __restrict__ et) {
    int e = blockIdx.x * blockDim.x + threadIdx.x;
    if (e >= N_EDGES) return;
    int t = et[e];
    int c = ei[N_EDGES + e];
    g_ew0[e] = g_rws[t] / fabsf(g_deg0[c]);
    g_ew1[e] = g_rws[NET + t] / fabsf(g_deg1[c]);
}

// ---------------- GEMMs: BM=64, BN=128, K=128, 256 threads, 8x4/thread ----
// smem: As[64][128] (32KB) + Ws[128][128] (64KB) = 96KB dynamic

// input linear, compacted: rows = g_list{pass}[m0..m0+63], only cnt rows real.
// h[n] = x_pass[lidx[n]] @ W_pass + b_pass   (rows disjoint across passes)
__global__ __launch_bounds__(256) void k_gemm_input(
    const float* __restrict__ xk, const int* __restrict__ lidx,
    const float* __restrict__ W, const float* __restrict__ b, int pass) {
    const int cnt = g_cnt[pass];
    const int m0 = blockIdx.x * 64;
    if (m0 >= cnt) return;
    const int* list = (pass == 0) ? g_list0 : g_list1;

    extern __shared__ float smem[];
    float* As = smem;
    float* Ws = smem + 64 * 128;

    const float4* W4 = (const float4*)W;
    for (int idx = threadIdx.x; idx < 128 * 32; idx += 256)
        ((float4*)Ws)[idx] = W4[idx];

    for (int idx = threadIdx.x; idx < 64 * 32; idx += 256) {
        int row = idx >> 5, kk = idx & 31;
        int lr = m0 + row;
        float4 v = {0.f, 0.f, 0.f, 0.f};
        if (lr < cnt) {
            int n = list[lr];
            int l = lidx[n];
            v = ((const float4*)(xk + (size_t)l * 128))[kk];
        }
        ((float4*)As)[idx] = v;
    }
    __syncthreads();

    const int cg = threadIdx.x & 31, rg = threadIdx.x >> 5;
    const int c0 = cg * 4, r0 = rg * 8;
    float acc[8][4] = {};
    const float4* As4 = (const float4*)As;
    const float4* Ws4 = (const float4*)Ws;
#pragma unroll
    for (int kk = 0; kk < 32; kk++) {
        float4 wv[4];
#pragma unroll
        for (int i = 0; i < 4; i++) wv[i] = Ws4[(kk * 4 + i) * 32 + cg];
        const float* w = (const float*)wv;
#pragma unroll
        for (int r = 0; r < 8; r++) {
            float4 av = As4[(r0 + r) * 32 + kk];
#pragma unroll
            for (int c = 0; c < 4; c++)
                acc[r][c] += av.x * w[0 * 4 + c] + av.y * w[1 * 4 + c] +
                             av.z * w[2 * 4 + c] + av.w * w[3 * 4 + c];
        }
    }

    float4 bb = *(const float4*)(b + c0);
#pragma unroll
    for (int r = 0; r < 8; r++) {
        int lr = m0 + r0 + r;
        if (lr >= cnt) continue;
        int n = list[lr];
        float4 res = {acc[r][0] + bb.x, acc[r][1] + bb.y,
                      acc[r][2] + bb.z, acc[r][3] + bb.w};
        *(float4*)(g_h + (size_t)n * HID + c0) = res;
    }
}

// g_x = g_agg0 @ conv0_w + conv0_b + g_h (residual)
__global__ __launch_bounds__(256) void k_gemm0(const float* __restrict__ W,
                                               const float* __restrict__ b) {
    extern __shared__ float smem[];
    float* As = smem;
    float* Ws = smem + 64 * 128;
    const int m0 = blockIdx.x * 64;

    const float4* W4 = (const float4*)W;
    for (int idx = threadIdx.x; idx < 128 * 32; idx += 256)
        ((float4*)Ws)[idx] = W4[idx];
    for (int idx = threadIdx.x; idx < 64 * 32; idx += 256) {
        int row = idx >> 5, kk = idx & 31;
        int gr = m0 + row;
        float4 v = {0.f, 0.f, 0.f, 0.f};
        if (gr < N_NODES) v = ((const float4*)(g_agg0 + (size_t)gr * HID))[kk];
        ((float4*)As)[idx] = v;
    }
    __syncthreads();

    const int cg = threadIdx.x & 31, rg = threadIdx.x >> 5;
    const int c0 = cg * 4, r0 = rg * 8;
    float acc[8][4] = {};
    const float4* As4 = (const float4*)As;
    const float4* Ws4 = (const float4*)Ws;
#pragma unroll
    for (int kk = 0; kk < 32; kk++) {
        float4 wv[4];
#pragma unroll
        for (int i = 0; i < 4; i++) wv[i] = Ws4[(kk * 4 + i) * 32 + cg];
        const float* w = (const float*)wv;
#pragma unroll
        for (int r = 0; r < 8; r++) {
            float4 av = As4[(r0 + r) * 32 + kk];
#pragma unroll
            for (int c = 0; c < 4; c++)
                acc[r][c] += av.x * w[0 * 4 + c] + av.y * w[1 * 4 + c] +
                             av.z * w[2 * 4 + c] + av.w * w[3 * 4 + c];
        }
    }
#pragma unroll
    for (int r = 0; r < 8; r++) {
        int gr = m0 + r0 + r;
        if (gr >= N_NODES) continue;
        float4 hres = *(const float4*)(g_h + (size_t)gr * HID + c0);
        float4 res;
        res.x = acc[r][0] + b[c0 + 0] + hres.x;
        res.y = acc[r][1] + b[c0 + 1] + hres.y;
        res.z = acc[r][2] + b[c0 + 2] + hres.z;
        res.w = acc[r][3] + b[c0 + 3] + hres.w;
        *(float4*)(g_x + (size_t)gr * HID + c0) = res;
    }
}

// out = g_agg1 @ conv1_w + conv1_b   (OUTD=349 columns, 3 column blocks)
__global__ __launch_bounds__(256) void k_gemm1(const float* __restrict__ W,
                                               const float* __restrict__ b,
                                               float* __restrict__ out) {
    extern __shared__ float smem[];
    float* As = smem;
    float* Ws = smem + 64 * 128;
    const int m0 = blockIdx.x * 64;
    const int n0 = blockIdx.y * 128;
    const int nc = (OUTD - n0 < 128) ? (OUTD - n0) : 128;

    for (int idx = threadIdx.x; idx < 128 * 128; idx += 256) {
        int k = idx >> 7, c = idx & 127;
        Ws[idx] = (c < nc) ? W[k * OUTD + n0 + c] : 0.0f;
    }
    for (int idx = threadIdx.x; idx < 64 * 32; idx += 256) {
        int row = idx >> 5, kk = idx & 31;
        int gr = m0 + row;
        float4 v = {0.f, 0.f, 0.f, 0.f};
        if (gr < N_NODES) v = ((const float4*)(g_agg1 + (size_t)gr * HID))[kk];
        ((float4*)As)[idx] = v;
    }
    __syncthreads();

    const int cg = threadIdx.x & 31, rg = threadIdx.x >> 5;
    const int c0 = cg * 4, r0 = rg * 8;
    float acc[8][4] = {};
    const float4* As4 = (const float4*)As;
    const float4* Ws4 = (const float4*)Ws;
#pragma unroll
    for (int kk = 0; kk < 32; kk++) {
        float4 wv[4];
#pragma unroll
        for (int i = 0; i < 4; i++) wv[i] = Ws4[(kk * 4 + i) * 32 + cg];
        const float* w = (const float*)wv;
#pragma unroll
        for (int r = 0; r < 8; r++) {
            float4 av = As4[(r0 + r) * 32 + kk];
#pragma unroll
            for (int c = 0; c < 4; c++)
                acc[r][c] += av.x * w[0 * 4 + c] + av.y * w[1 * 4 + c] +
                             av.z * w[2 * 4 + c] + av.w * w[3 * 4 + c];
        }
    }
#pragma unroll
    for (int r = 0; r < 8; r++) {
        int gr = m0 + r0 + r;
        if (gr >= N_NODES) continue;
        float* Crow = out + (size_t)gr * OUTD;
#pragma unroll
        for (int c = 0; c < 4; c++) {
            int col = n0 + c0 + c;
            if (col < OUTD) Crow[col] = acc[r][c] + b[col];
        }
    }
}

// ---------------- scatter: agg[col] += ew[e] * h[row] ----------------------
// one warp per edge, one float4 per lane, vector red (16M reds/layer)
__global__ void k_scatter(const int* __restrict__ ei, int layer) {
    int gt = blockIdx.x * blockDim.x + threadIdx.x;
    int e = gt >> 5;
    int lane = gt & 31;
    if (e >= N_EDGES) return;
    const float* ew = (layer == 0) ? g_ew0 : g_ew1;
    float* dst = (layer == 0) ? g_agg0 : g_agg1;
    float w = __ldg(&ew[e]);
    int r = __ldg(&ei[e]);
    int c = __ldg(&ei[N_EDGES + e]);
    float4 v = ((const float4*)(g_h + (size_t)r * HID))[lane];
    v.x *= w; v.y *= w; v.z *= w; v.w *= w;
    float* addr = dst + (size_t)c * HID + lane * 4;
    asm volatile("red.global.add.v4.f32 [%0], {%1,%2,%3,%4};"
                 :: "l"(addr), "f"(v.x), "f"(v.y), "f"(v.z), "f"(v.w)
                 : "memory");
}

// ---------------- BN -------------------------------------------------------
__global__ __launch_bounds__(128) void k_stats() {
    int j = threadIdx.x;
    float s = 0.f, s2 = 0.f;
    for (int n = blockIdx.x; n < N_NODES; n += gridDim.x) {
        float v = g_x[(size_t)n * HID + j];
        s += v;
        s2 += v * v;
    }
    atomicAdd(&g_sum[j], s);
    atomicAdd(&g_sumsq[j], s2);
}

__global__ void k_bnfinal(const float* __restrict__ gamma,
                          const float* __restrict__ beta) {
    int j = threadIdx.x;
    if (j >= HID) return;
    float mean = g_sum[j] / (float)N_NODES;
    float var = g_sumsq[j] / (float)N_NODES - mean * mean;
    float sc = gamma[j] * rsqrtf(var + BN_EPS);
    g_bnscale[j] = sc;
    g_bnshift[j] = beta[j] - mean * sc;
}

// y = prelu(bn(x)) -> overwrite g_h (h is dead after gemm0)
__global__ void k_bnapply(const float* __restrict__ prelu_a) {
    const float a = prelu_a[0];
    const int total = N_NODES * HID / 4;
    for (int i = blockIdx.x * blockDim.x + threadIdx.x; i < total;
         i += gridDim.x * blockDim.x) {
        int kk = i & 31;  // column group within row (HID/4 = 32)
        float4 x = ((const float4*)g_x)[i];
        float4 sc = ((const float4*)g_bnscale)[kk];
        float4 sh = ((const float4*)g_bnshift)[kk];
        float4 v;
        v.x = x.x * sc.x + sh.x;
        v.y = x.y * sc.y + sh.y;
        v.z = x.z * sc.z + sh.z;
        v.w = x.w * sc.w + sh.w;
        v.x = (v.x >= 0.f) ? v.x : a * v.x;
        v.y = (v.y >= 0.f) ? v.y : a * v.y;
        v.z = (v.z >= 0.f) ? v.z : a * v.z;
        v.w = (v.w >= 0.f) ? v.w : a * v.w;
        ((float4*)g_h)[i] = v;
    }
}

// ---------------- log_softmax (in place on d_out) --------------------------
__global__ __launch_bounds__(128) void k_logsoftmax(float* __restrict__ out) {
    int n = blockIdx.x;
    float* row = out + (size_t)n * OUTD;
    int j = threadIdx.x;
    float v0 = row[j];
    float v1 = (j + 128 < OUTD) ? row[j + 128] : -1e30f;
    float v2 = (j + 256 < OUTD) ? row[j + 256] : -1e30f;
    __shared__ float red[128];
    float m = fmaxf(v0, fmaxf(v1, v2));
    red[j] = m;
    __syncthreads();
#pragma unroll
    for (int s = 64; s > 0; s >>= 1) {
        if (j < s) red[j] = fmaxf(red[j], red[j + s]);
        __syncthreads();
    }
    float mx = red[0];
    __syncthreads();
    float e = expf(v0 - mx);
    if (j + 128 < OUTD) e += expf(v1 - mx);
    if (j + 256 < OUTD) e += expf(v2 - mx);
    red[j] = e;
    __syncthreads();
#pragma unroll
    for (int s = 64; s > 0; s >>= 1) {
        if (j < s) red[j] += red[j + s];
        __syncthreads();
    }
    float lse = logf(red[0]) + mx;
    row[j] = v0 - lse;
    if (j + 128 < OUTD) row[j + 128] = v1 - lse;
    if (j + 256 < OUTD) row[j + 256] = v2 - lse;
}

// ---------------- launch ---------------------------------------------------
extern "C" void kernel_launch(void* const* d_in, const int* in_sizes, int n_in,
                              void* d_out, int out_size) {
    const float* x0 = (const float*)d_in[0];
    const float* x1 = (const float*)d_in[1];
    const int* edge_index = (const int*)d_in[2];
    const int* edge_type = (const int*)d_in[3];
    const int* node_type = (const int*)d_in[4];
    const int* lidx = (const int*)d_in[5];
    const float* lin0_w = (const float*)d_in[6];
    const float* lin0_b = (const float*)d_in[7];
    const float* lin1_w = (const float*)d_in[8];
    const float* lin1_b = (const float*)d_in[9];
    const float* conv0_w = (const float*)d_in[10];
    const float* conv0_b = (const float*)d_in[11];
    const float* conv0_rw = (const float*)d_in[12];
    const float* conv1_w = (const float*)d_in[13];
    const float* conv1_b = (const float*)d_in[14];
    const float* conv1_rw = (const float*)d_in[15];
    const float* bn_g = (const float*)d_in[16];
    const float* bn_b = (const float*)d_in[17];
    const float* prelu_a = (const float*)d_in[18];
    float* out = (float*)d_out;

    const int SMEM = (64 * 128 + 128 * 128) * 4;  // 96KB
    cudaFuncSetAttribute(k_gemm_input, cudaFuncAttributeMaxDynamicSharedMemorySize, SMEM);
    cudaFuncSetAttribute(k_gemm0, cudaFuncAttributeMaxDynamicSharedMemorySize, SMEM);
    cudaFuncSetAttribute(k_gemm1, cudaFuncAttributeMaxDynamicSharedMemorySize, SMEM);

    const int MB = (N_NODES + 63) / 64;  // 1563

    k_rws<<<1, 32>>>(conv0_rw, conv1_rw);
    k_zero_small<<<(N_NODES + 255) / 256, 256>>>();
    k_zero_aggs<<<2048, 256>>>();
    k_partition<<<(N_NODES + 255) / 256, 256>>>(node_type);
    k_deg<<<(N_EDGES + 255) / 256, 256>>>(edge_index, edge_type);
    k_ew<<<(N_EDGES + 255) / 256, 256>>>(edge_index, edge_type);

    // compacted input linears (each covers only its type's rows)
    k_gemm_input<<<MB, 256, SMEM>>>(x0, lidx, lin0_w, lin0_b, 0);
    k_gemm_input<<<MB, 256, SMEM>>>(x1, lidx, lin1_w, lin1_b, 1);

    const int SC_BLOCKS = (int)(((long long)N_EDGES * 32 + 255) / 256);

    // layer 0: scatter in HID space, then GEMM (+bias+residual)
    k_scatter<<<SC_BLOCKS, 256>>>(edge_index, 0);
    k_gemm0<<<MB, 256, SMEM>>>(conv0_w, conv0_b);

    k_stats<<<512, 128>>>();
    k_bnfinal<<<1, 128>>>(bn_g, bn_b);
    k_bnapply<<<2048, 256>>>(prelu_a);

    // layer 1: scatter in HID space, then GEMM to 349 outputs
    k_scatter<<<SC_BLOCKS, 256>>>(edge_index, 1);
    k_gemm1<<<dim3(MB, 3), 256, SMEM>>>(conv1_w, conv1_b, out);

    k_logsoftmax<<<N_NODES, 128>>>(out);
}

// round 7
// speedup vs baseline: 1.7952x; 1.3756x over previous
#include <cuda_runtime.h>
#include <cuda_bf16.h>
#include <cstdint>

#define N_NODES 100000
#define N_EDGES 500000
#define HID 128
#define OUTD 349
#define NET 8
#define BN_EPS 1e-5f
#define MTILE 128
#define NTILES_M ((N_NODES + MTILE - 1) / MTILE)  // 782

// ---------------- scratch (static device globals; no allocation) ----------
__device__ float g_h[N_NODES * HID];     // input-linear output, later y = prelu(bn(x))
__device__ float g_x[N_NODES * HID];     // conv0 out + residual (BN input)
__device__ float g_agg0[N_NODES * HID];  // scatter target layer 0
__device__ float g_agg1[N_NODES * HID];  // scatter target layer 1
__device__ float g_ew0[N_EDGES], g_ew1[N_EDGES];
__device__ float g_deg0[N_NODES], g_deg1[N_NODES];
__device__ float g_rws[2 * NET];
__device__ float g_sum[HID], g_sumsq[HID];
__device__ float g_bnscale[HID], g_bnshift[HID];
__device__ int   g_cnt[2];
__device__ int   g_list0[N_NODES], g_list1[N_NODES];

// bf16 hi/lo weight images, layout [tile][k=128][n=128] row-major
__device__ __nv_bfloat16 g_wI0h[16384], g_wI0l[16384];       // lin0_w
__device__ __nv_bfloat16 g_wI1h[16384], g_wI1l[16384];       // lin1_w
__device__ __nv_bfloat16 g_wC0h[16384], g_wC0l[16384];       // conv0_w
__device__ __nv_bfloat16 g_wC1h[3 * 16384], g_wC1l[3 * 16384];  // conv1_w (3 tiles)

// ---------------- mma.sync GEMM machinery ----------------------------------
// CTA computes a 128(M) x 128(N) x 128(K) tile product with bf16x3 compensation.
// smem: A hi/lo [128 rows][272B stride], B hi/lo [128 k-rows][272B stride]
#define ROWB 272                    // 136 bf16 padded row (conflict-free LDSM)
#define OFF_A_HI 0
#define OFF_A_LO 34816
#define OFF_B_HI 69632
#define OFF_B_LO 104448
#define SMEM_MMA 139264

__device__ __forceinline__ uint32_t smem_u32(const void* p) {
    uint32_t a;
    asm("{ .reg .u64 t; cvta.to.shared.u64 t, %1; cvt.u32.u64 %0, t; }"
        : "=r"(a) : "l"(p));
    return a;
}

__device__ __forceinline__ void ldsm4(uint32_t addr, uint32_t* r) {
    asm volatile("ldmatrix.sync.aligned.m8n8.x4.shared.b16 {%0,%1,%2,%3}, [%4];"
                 : "=r"(r[0]), "=r"(r[1]), "=r"(r[2]), "=r"(r[3]) : "r"(addr));
}
__device__ __forceinline__ void ldsm2t(uint32_t addr, uint32_t* r) {
    asm volatile("ldmatrix.sync.aligned.m8n8.x2.trans.shared.b16 {%0,%1}, [%2];"
                 : "=r"(r[0]), "=r"(r[1]) : "r"(addr));
}
__device__ __forceinline__ void mma16816(float* d, const uint32_t* a, const uint32_t* b) {
    asm volatile(
        "mma.sync.aligned.m16n8k16.row.col.f32.bf16.bf16.f32 "
        "{%0,%1,%2,%3}, {%4,%5,%6,%7}, {%8,%9}, {%0,%1,%2,%3};"
        : "+f"(d[0]), "+f"(d[1]), "+f"(d[2]), "+f"(d[3])
        : "r"(a[0]), "r"(a[1]), "r"(a[2]), "r"(a[3]), "r"(b[0]), "r"(b[1]));
}

// stage 64 fp32 (half a row) as bf16 hi/lo into padded A tiles
__device__ __forceinline__ void stage_half(char* smem, int row, int half,
                                           const float* src) {
    uint32_t off = (uint32_t)row * ROWB + half * 128;
#pragma unroll
    for (int g = 0; g < 8; g++) {
        float f[8];
        if (src) {
            float4 a = ((const float4*)src)[g * 2];
            float4 b = ((const float4*)src)[g * 2 + 1];
            f[0] = a.x; f[1] = a.y; f[2] = a.z; f[3] = a.w;
            f[4] = b.x; f[5] = b.y; f[6] = b.z; f[7] = b.w;
        } else {
#pragma unroll
            for (int i = 0; i < 8; i++) f[i] = 0.f;
        }
        uint32_t hp[4], lp[4];
#pragma unroll
        for (int i = 0; i < 4; i++) {
            __nv_bfloat16 h0 = __float2bfloat16(f[2 * i]);
            __nv_bfloat16 h1 = __float2bfloat16(f[2 * i + 1]);
            float l0 = f[2 * i] - __bfloat162float(h0);
            float l1 = f[2 * i + 1] - __bfloat162float(h1);
            __nv_bfloat162 hh = __halves2bfloat162(h0, h1);
            __nv_bfloat162 ll = __halves2bfloat162(__float2bfloat16(l0),
                                                   __float2bfloat16(l1));
            hp[i] = *reinterpret_cast<uint32_t*>(&hh);
            lp[i] = *reinterpret_cast<uint32_t*>(&ll);
        }
        *reinterpret_cast<uint4*>(smem + OFF_A_HI + off + g * 16) =
            make_uint4(hp[0], hp[1], hp[2], hp[3]);
        *reinterpret_cast<uint4*>(smem + OFF_A_LO + off + g * 16) =
            make_uint4(lp[0], lp[1], lp[2], lp[3]);
    }
}

// copy one pre-split B tile (hi/lo [k][n] images) into padded smem rows
__device__ __forceinline__ void stage_b(char* smem, const __nv_bfloat16* bh,
                                        const __nv_bfloat16* bl, int tid) {
    const uint4* h4 = (const uint4*)bh;
    const uint4* l4 = (const uint4*)bl;
    for (int i = tid; i < 2048; i += 256) {
        int k = i >> 4, s = i & 15;
        *(uint4*)(smem + OFF_B_HI + k * ROWB + s * 16) = h4[i];
        *(uint4*)(smem + OFF_B_LO + k * ROWB + s * 16) = l4[i];
    }
}

// core: 8 warps, warp (wm=w&1, wn=w>>1) computes rows wm*64..+63, cols wn*32..+31
__device__ __forceinline__ void mma_core(uint32_t sb, float acc[16][4]) {
    int lane = threadIdx.x & 31;
    int w = threadIdx.x >> 5;
    int wm = w & 1, wn = w >> 1;
    uint32_t aaddr[4], baddr[4];
#pragma unroll
    for (int mt = 0; mt < 4; mt++)
        aaddr[mt] = sb + OFF_A_HI +
                    (uint32_t)(wm * 64 + mt * 16 + (lane & 15)) * ROWB +
                    (lane >> 4) * 16;
#pragma unroll
    for (int nt = 0; nt < 4; nt++)
        baddr[nt] = sb + OFF_B_HI + (uint32_t)(lane & 15) * ROWB +
                    (wn * 32 + nt * 8) * 2;
#pragma unroll 2
    for (int ks = 0; ks < 8; ks++) {
        uint32_t bh[4][2], bl[4][2];
#pragma unroll
        for (int nt = 0; nt < 4; nt++) {
            uint32_t ba = baddr[nt] + ks * (16 * ROWB);
            ldsm2t(ba, bh[nt]);
            ldsm2t(ba + (OFF_B_LO - OFF_B_HI), bl[nt]);
        }
#pragma unroll
        for (int mt = 0; mt < 4; mt++) {
            uint32_t ah[4], al[4];
            uint32_t aa = aaddr[mt] + ks * 32;
            ldsm4(aa, ah);
            ldsm4(aa + (OFF_A_LO - OFF_A_HI), al);
#pragma unroll
            for (int nt = 0; nt < 4; nt++) {
                mma16816(acc[mt * 4 + nt], ah, bh[nt]);
                mma16816(acc[mt * 4 + nt], ah, bl[nt]);
                mma16816(acc[mt * 4 + nt], al, bh[nt]);
            }
        }
    }
}

// ---------------- tiny prep ----------------------------------------------
__global__ void k_rws(const float* __restrict__ rw0, const float* __restrict__ rw1) {
    int i = threadIdx.x;
    if (i < NET) {
        float v = rw0[i] * 100.0f;
        g_rws[i] = (v >= 0.0f) ? v : 0.01f * v;
    } else if (i < 2 * NET) {
        float v = rw1[i - NET] * 100.0f;
        g_rws[i] = (v >= 0.0f) ? v : 0.01f * v;
    }
}

__global__ void k_zero_small() {
    int i = blockIdx.x * blockDim.x + threadIdx.x;
    if (i < N_NODES) { g_deg0[i] = 0.0f; g_deg1[i] = 0.0f; }
    if (i < HID)     { g_sum[i] = 0.0f;  g_sumsq[i] = 0.0f; }
    if (i < 2)       { g_cnt[i] = 0; }
}

__global__ void k_zero_aggs() {
    const int total = N_NODES * HID / 4;
    float4 z = {0.f, 0.f, 0.f, 0.f};
    for (int i = blockIdx.x * blockDim.x + threadIdx.x; i < total;
         i += gridDim.x * blockDim.x) {
        ((float4*)g_agg0)[i] = z;
        ((float4*)g_agg1)[i] = z;
    }
}

// warp-aggregated two-way partition
__global__ void k_partition(const int* __restrict__ ntype) {
    int n = blockIdx.x * blockDim.x + threadIdx.x;
    bool valid = n < N_NODES;
    int t = valid ? ntype[n] : -1;
    int lane = threadIdx.x & 31;
#pragma unroll
    for (int tt = 0; tt < 2; tt++) {
        unsigned m = __ballot_sync(0xffffffffu, t == tt);
        if (t == tt) {
            int leader = __ffs(m) - 1;
            int pos = 0;
            if (lane == leader) pos = atomicAdd(&g_cnt[tt], __popc(m));
            pos = __shfl_sync(m, pos, leader);
            pos += __popc(m & ((1u << lane) - 1u));
            if (tt == 0) g_list0[pos] = n; else g_list1[pos] = n;
        }
    }
}

__global__ void k_deg(const int* __restrict__ ei, const int* __restrict__ et) {
    int e = blockIdx.x * blockDim.x + threadIdx.x;
    if (e >= N_EDGES) return;
    int c = ei[N_EDGES + e];
    int t = et[e];
    atomicAdd(&g_deg0[c], g_rws[t]);
    atomicAdd(&g_deg1[c], g_rws[NET + t]);
}

__global__ void k_ew(const int* __restrict__ ei, const int* __restrict__ et) {
    int e = blockIdx.x * blockDim.x + threadIdx.x;
    if (e >= N_EDGES) return;
    int t = et[e];
    int c = ei[N_EDGES + e];
    g_ew0[e] = g_rws[t] / fabsf(g_deg0[c]);
    g_ew1[e] = g_rws[NET + t] / fabsf(g_deg1[c]);
}

// split W (fp32 [K=128][ncols]) into bf16 hi/lo tile images [t][k][n]
__global__ void k_prep(const float* __restrict__ W, int ncols, int ntiles, int which) {
    int idx = blockIdx.x * blockDim.x + threadIdx.x;
    if (idx >= ntiles * 16384) return;
    __nv_bfloat16 *hi, *lo;
    switch (which) {
        case 0: hi = g_wI0h; lo = g_wI0l; break;
        case 1: hi = g_wI1h; lo = g_wI1l; break;
        case 2: hi = g_wC0h; lo = g_wC0l; break;
        default: hi = g_wC1h; lo = g_wC1l; break;
    }
    int t = idx >> 14;
    int rem = idx & 16383;
    int k = rem >> 7;
    int n = rem & 127;
    int col = t * 128 + n;
    float v = (col < ncols) ? W[(size_t)k * ncols + col] : 0.f;
    __nv_bfloat16 h = __float2bfloat16(v);
    hi[idx] = h;
    lo[idx] = __float2bfloat16(v - __bfloat162float(h));
}

// ---------------- mma GEMM kernels ----------------------------------------

// input linear (compacted rows of one type): h[n] = x_k[lidx[n]] @ W + b
__global__ __launch_bounds__(256) void k_mma_input(
    const float* __restrict__ xk, const int* __restrict__ lidx,
    const float* __restrict__ b, int pass) {
    const int cnt = g_cnt[pass];
    const int m0 = blockIdx.x * MTILE;
    if (m0 >= cnt) return;
    const int* list = pass ? g_list1 : g_list0;
    extern __shared__ char smem[];
    int tid = threadIdx.x;

    stage_b(smem, pass ? g_wI1h : g_wI0h, pass ? g_wI1l : g_wI0l, tid);
    {
        int row = tid >> 1, half = tid & 1;
        int lr = m0 + row;
        const float* src = nullptr;
        if (lr < cnt) src = xk + (size_t)lidx[list[lr]] * HID + half * 64;
        stage_half(smem, row, half, src);
    }
    __syncthreads();

    float acc[16][4] = {};
    mma_core(smem_u32(smem), acc);

    int lane = tid & 31, w = tid >> 5, wm = w & 1, wn = w >> 1;
#pragma unroll
    for (int mt = 0; mt < 4; mt++)
#pragma unroll
        for (int half = 0; half < 2; half++) {
            int lr = m0 + wm * 64 + mt * 16 + (lane >> 2) + half * 8;
            if (lr >= cnt) continue;
            float* dst = g_h + (size_t)list[lr] * HID;
#pragma unroll
            for (int nt = 0; nt < 4; nt++) {
                int c = wn * 32 + nt * 8 + (lane & 3) * 2;
                float2 bb = *(const float2*)(b + c);
                float2 o = {acc[mt * 4 + nt][half * 2 + 0] + bb.x,
                            acc[mt * 4 + nt][half * 2 + 1] + bb.y};
                *(float2*)(dst + c) = o;
            }
        }
}

// g_x = g_agg0 @ conv0_w + b + g_h (residual)
__global__ __launch_bounds__(256) void k_mma_gemm0(const float* __restrict__ b) {
    const int m0 = blockIdx.x * MTILE;
    extern __shared__ char smem[];
    int tid = threadIdx.x;

    stage_b(smem, g_wC0h, g_wC0l, tid);
    {
        int row = tid >> 1, half = tid & 1;
        int gr = m0 + row;
        const float* src =
            (gr < N_NODES) ? (g_agg0 + (size_t)gr * HID + half * 64) : nullptr;
        stage_half(smem, row, half, src);
    }
    __syncthreads();

    float acc[16][4] = {};
    mma_core(smem_u32(smem), acc);

    int lane = tid & 31, w = tid >> 5, wm = w & 1, wn = w >> 1;
#pragma unroll
    for (int mt = 0; mt < 4; mt++)
#pragma unroll
        for (int half = 0; half < 2; half++) {
            int gr = m0 + wm * 64 + mt * 16 + (lane >> 2) + half * 8;
            if (gr >= N_NODES) continue;
            float* dst = g_x + (size_t)gr * HID;
            const float* hres = g_h + (size_t)gr * HID;
#pragma unroll
            for (int nt = 0; nt < 4; nt++) {
                int c = wn * 32 + nt * 8 + (lane & 3) * 2;
                float2 bb = *(const float2*)(b + c);
                float2 hv = *(const float2*)(hres + c);
                float2 o = {acc[mt * 4 + nt][half * 2 + 0] + bb.x + hv.x,
                            acc[mt * 4 + nt][half * 2 + 1] + bb.y + hv.y};
                *(float2*)(dst + c) = o;
            }
        }
}

// out[:, n0:n0+128] = g_agg1 @ conv1_w tile + b
__global__ __launch_bounds__(256) void k_mma_gemm1(const float* __restrict__ b,
                                                   float* __restrict__ out) {
    const int m0 = blockIdx.x * MTILE;
    const int n0 = blockIdx.y * 128;
    extern __shared__ char smem[];
    int tid = threadIdx.x;

    stage_b(smem, g_wC1h + (size_t)blockIdx.y * 16384,
            g_wC1l + (size_t)blockIdx.y * 16384, tid);
    {
        int row = tid >> 1, half = tid & 1;
        int gr = m0 + row;
        const float* src =
            (gr < N_NODES) ? (g_agg1 + (size_t)gr * HID + half * 64) : nullptr;
        stage_half(smem, row, half, src);
    }
    __syncthreads();

    float acc[16][4] = {};
    mma_core(smem_u32(smem), acc);

    int lane = tid & 31, w = tid >> 5, wm = w & 1, wn = w >> 1;
#pragma unroll
    for (int mt = 0; mt < 4; mt++)
#pragma unroll
        for (int half = 0; half < 2; half++) {
            int gr = m0 + wm * 64 + mt * 16 + (lane >> 2) + half * 8;
            if (gr >= N_NODES) continue;
            float* dst = out + (size_t)gr * OUTD;
#pragma unroll
            for (int nt = 0; nt < 4; nt++) {
                int c = n0 + wn * 32 + nt * 8 + (lane & 3) * 2;
                if (c < OUTD)
                    dst[c] = acc[mt * 4 + nt][half * 2 + 0] + b[c];
                if (c + 1 < OUTD)
                    dst[c + 1] = acc[mt * 4 + nt][half * 2 + 1] + b[c + 1];
            }
        }
}

// ---------------- scatter: agg[col] += ew[e] * h[row] ----------------------
__global__ void k_scatter(const int* __restrict__ ei, int layer) {
    int gt = blockIdx.x * blockDim.x + threadIdx.x;
    int e = gt >> 5;
    int lane = gt & 31;
    if (e >= N_EDGES) return;
    const float* ew = (layer == 0) ? g_ew0 : g_ew1;
    float* dst = (layer == 0) ? g_agg0 : g_agg1;
    float w = __ldg(&ew[e]);
    int r = __ldg(&ei[e]);
    int c = __ldg(&ei[N_EDGES + e]);
    float4 v = ((const float4*)(g_h + (size_t)r * HID))[lane];
    v.x *= w; v.y *= w; v.z *= w; v.w *= w;
    float* addr = dst + (size_t)c * HID + lane * 4;
    asm volatile("red.global.add.v4.f32 [%0], {%1,%2,%3,%4};"
                 :: "l"(addr), "f"(v.x), "f"(v.y), "f"(v.z), "f"(v.w)
                 : "memory");
}

// ---------------- BN -------------------------------------------------------
__global__ __launch_bounds__(128) void k_stats() {
    int j = threadIdx.x;
    float s = 0.f, s2 = 0.f;
    for (int n = blockIdx.x; n < N_NODES; n += gridDim.x) {
        float v = g_x[(size_t)n * HID + j];
        s += v;
        s2 += v * v;
    }
    atomicAdd(&g_sum[j], s);
    atomicAdd(&g_sumsq[j], s2);
}

__global__ void k_bnfinal(const float* __restrict__ gamma,
                          const float* __restrict__ beta) {
    int j = threadIdx.x;
    if (j >= HID) return;
    float mean = g_sum[j] / (float)N_NODES;
    float var = g_sumsq[j] / (float)N_NODES - mean * mean;
    float sc = gamma[j] * rsqrtf(var + BN_EPS);
    g_bnscale[j] = sc;
    g_bnshift[j] = beta[j] - mean * sc;
}

__global__ void k_bnapply(const float* __restrict__ prelu_a) {
    const float a = prelu_a[0];
    const int total = N_NODES * HID / 4;
    for (int i = blockIdx.x * blockDim.x + threadIdx.x; i < total;
         i += gridDim.x * blockDim.x) {
        int kk = i & 31;
        float4 x = ((const float4*)g_x)[i];
        float4 sc = ((const float4*)g_bnscale)[kk];
        float4 sh = ((const float4*)g_bnshift)[kk];
        float4 v;
        v.x = x.x * sc.x + sh.x;
        v.y = x.y * sc.y + sh.y;
        v.z = x.z * sc.z + sh.z;
        v.w = x.w * sc.w + sh.w;
        v.x = (v.x >= 0.f) ? v.x : a * v.x;
        v.y = (v.y >= 0.f) ? v.y : a * v.y;
        v.z = (v.z >= 0.f) ? v.z : a * v.z;
        v.w = (v.w >= 0.f) ? v.w : a * v.w;
        ((float4*)g_h)[i] = v;
    }
}

// ---------------- log_softmax (in place on d_out) --------------------------
__global__ __launch_bounds__(128) void k_logsoftmax(float* __restrict__ out) {
    int n = blockIdx.x;
    float* row = out + (size_t)n * OUTD;
    int j = threadIdx.x;
    float v0 = row[j];
    float v1 = (j + 128 < OUTD) ? row[j + 128] : -1e30f;
    float v2 = (j + 256 < OUTD) ? row[j + 256] : -1e30f;
    __shared__ float red[128];
    float m = fmaxf(v0, fmaxf(v1, v2));
    red[j] = m;
    __syncthreads();
#pragma unroll
    for (int s = 64; s > 0; s >>= 1) {
        if (j < s) red[j] = fmaxf(red[j], red[j + s]);
        __syncthreads();
    }
    float mx = red[0];
    __syncthreads();
    float e = expf(v0 - mx);
    if (j + 128 < OUTD) e += expf(v1 - mx);
    if (j + 256 < OUTD) e += expf(v2 - mx);
    red[j] = e;
    __syncthreads();
#pragma unroll
    for (int s = 64; s > 0; s >>= 1) {
        if (j < s) red[j] += red[j + s];
        __syncthreads();
    }
    float lse = logf(red[0]) + mx;
    row[j] = v0 - lse;
    if (j + 128 < OUTD) row[j + 128] = v1 - lse;
    if (j + 256 < OUTD) row[j + 256] = v2 - lse;
}

// ---------------- launch ---------------------------------------------------
extern "C" void kernel_launch(void* const* d_in, const int* in_sizes, int n_in,
                              void* d_out, int out_size) {
    const float* x0 = (const float*)d_in[0];
    const float* x1 = (const float*)d_in[1];
    const int* edge_index = (const int*)d_in[2];
    const int* edge_type = (const int*)d_in[3];
    const int* node_type = (const int*)d_in[4];
    const int* lidx = (const int*)d_in[5];
    const float* lin0_w = (const float*)d_in[6];
    const float* lin0_b = (const float*)d_in[7];
    const float* lin1_w = (const float*)d_in[8];
    const float* lin1_b = (const float*)d_in[9];
    const float* conv0_w = (const float*)d_in[10];
    const float* conv0_b = (const float*)d_in[11];
    const float* conv0_rw = (const float*)d_in[12];
    const float* conv1_w = (const float*)d_in[13];
    const float* conv1_b = (const float*)d_in[14];
    const float* conv1_rw = (const float*)d_in[15];
    const float* bn_g = (const float*)d_in[16];
    const float* bn_b = (const float*)d_in[17];
    const float* prelu_a = (const float*)d_in[18];
    float* out = (float*)d_out;

    cudaFuncSetAttribute(k_mma_input, cudaFuncAttributeMaxDynamicSharedMemorySize, SMEM_MMA);
    cudaFuncSetAttribute(k_mma_gemm0, cudaFuncAttributeMaxDynamicSharedMemorySize, SMEM_MMA);
    cudaFuncSetAttribute(k_mma_gemm1, cudaFuncAttributeMaxDynamicSharedMemorySize, SMEM_MMA);

    k_rws<<<1, 32>>>(conv0_rw, conv1_rw);
    k_zero_small<<<(N_NODES + 255) / 256, 256>>>();
    k_zero_aggs<<<2048, 256>>>();
    k_partition<<<(N_NODES + 255) / 256, 256>>>(node_type);
    k_deg<<<(N_EDGES + 255) / 256, 256>>>(edge_index, edge_type);
    k_ew<<<(N_EDGES + 255) / 256, 256>>>(edge_index, edge_type);

    // weight hi/lo images
    k_prep<<<64, 256>>>(lin0_w, HID, 1, 0);
    k_prep<<<64, 256>>>(lin1_w, HID, 1, 1);
    k_prep<<<64, 256>>>(conv0_w, HID, 1, 2);
    k_prep<<<192, 256>>>(conv1_w, OUTD, 3, 3);

    // input linears (compacted by node type)
    k_mma_input<<<NTILES_M, 256, SMEM_MMA>>>(x0, lidx, lin0_b, 0);
    k_mma_input<<<NTILES_M, 256, SMEM_MMA>>>(x1, lidx, lin1_b, 1);

    const int SC_BLOCKS = (int)(((long long)N_EDGES * 32 + 255) / 256);

    // layer 0
    k_scatter<<<SC_BLOCKS, 256>>>(edge_index, 0);
    k_mma_gemm0<<<NTILES_M, 256, SMEM_MMA>>>(conv0_b);

    k_stats<<<512, 128>>>();
    k_bnfinal<<<1, 128>>>(bn_g, bn_b);
    k_bnapply<<<2048, 256>>>(prelu_a);

    // layer 1
    k_scatter<<<SC_BLOCKS, 256>>>(edge_index, 1);
    k_mma_gemm1<<<dim3(NTILES_M, 3), 256, SMEM_MMA>>>(conv1_b, out);

    k_logsoftmax<<<N_NODES, 128>>>(out);
}

// round 8
// speedup vs baseline: 2.1520x; 1.1987x over previous
#include <cuda_runtime.h>
#include <cuda_bf16.h>
#include <cstdint>

#define N_NODES 100000
#define N_EDGES 500000
#define HID 128
#define OUTD 349
#define NET 8
#define BN_EPS 1e-5f
#define MTILE 64
#define NTILES_M ((N_NODES + MTILE - 1) / MTILE)  // 1563

// ---------------- scratch (static device globals; no allocation) ----------
__device__ float g_h[N_NODES * HID];     // input-linear output (residual source)
__device__ float g_x[N_NODES * HID];     // conv0 out + residual (BN input)
__device__ float g_agg0[N_NODES * HID];  // scatter target layer 0
__device__ float g_agg1[N_NODES * HID];  // scatter target layer 1
__device__ float g_ew0[N_EDGES], g_ew1[N_EDGES];
__device__ float g_deg0[N_NODES], g_deg1[N_NODES];
__device__ float g_rws[2 * NET];
__device__ float g_sum[HID], g_sumsq[HID];
__device__ float g_bnscale[HID], g_bnshift[HID];
__device__ int   g_cnt[2];
__device__ int   g_list0[N_NODES], g_list1[N_NODES];

// bf16 hi/lo weight images, layout [tile][k=128][n=128] row-major
__device__ __nv_bfloat16 g_wI0h[16384], g_wI0l[16384];       // lin0_w
__device__ __nv_bfloat16 g_wI1h[16384], g_wI1l[16384];       // lin1_w
__device__ __nv_bfloat16 g_wC0h[16384], g_wC0l[16384];       // conv0_w
__device__ __nv_bfloat16 g_wC1h[3 * 16384], g_wC1l[3 * 16384];  // conv1_w (3 tiles)

// ---------------- mma.sync GEMM machinery ----------------------------------
// CTA computes a 64(M) x 128(N) x 128(K) tile with bf16x3 compensation.
#define ROWB 272                    // 136 bf16 padded row (conflict-free LDSM)
#define OFF_A_HI 0
#define OFF_A_LO 17408
#define OFF_B_HI 34816
#define OFF_B_LO 69632
#define SMEM_MMA 104448             // 102KB -> 2 CTAs/SM

__device__ __forceinline__ uint32_t smem_u32(const void* p) {
    uint32_t a;
    asm("{ .reg .u64 t; cvta.to.shared.u64 t, %1; cvt.u32.u64 %0, t; }"
        : "=r"(a) : "l"(p));
    return a;
}

__device__ __forceinline__ void ldsm4(uint32_t addr, uint32_t* r) {
    asm volatile("ldmatrix.sync.aligned.m8n8.x4.shared.b16 {%0,%1,%2,%3}, [%4];"
                 : "=r"(r[0]), "=r"(r[1]), "=r"(r[2]), "=r"(r[3]) : "r"(addr));
}
__device__ __forceinline__ void ldsm2t(uint32_t addr, uint32_t* r) {
    asm volatile("ldmatrix.sync.aligned.m8n8.x2.trans.shared.b16 {%0,%1}, [%2];"
                 : "=r"(r[0]), "=r"(r[1]) : "r"(addr));
}
__device__ __forceinline__ void mma16816(float* d, const uint32_t* a, const uint32_t* b) {
    asm volatile(
        "mma.sync.aligned.m16n8k16.row.col.f32.bf16.bf16.f32 "
        "{%0,%1,%2,%3}, {%4,%5,%6,%7}, {%8,%9}, {%0,%1,%2,%3};"
        : "+f"(d[0]), "+f"(d[1]), "+f"(d[2]), "+f"(d[3])
        : "r"(a[0]), "r"(a[1]), "r"(a[2]), "r"(a[3]), "r"(b[0]), "r"(b[1]));
}

// stage 32 fp32 (quarter row) as bf16 hi/lo into padded A tiles
__device__ __forceinline__ void stage_quarter(char* smem, int row, int q,
                                              const float* src) {
    uint32_t off = (uint32_t)row * ROWB + q * 64;
#pragma unroll
    for (int g = 0; g < 4; g++) {
        float f[8];
        if (src) {
            float4 a = ((const float4*)src)[g * 2];
            float4 b = ((const float4*)src)[g * 2 + 1];
            f[0] = a.x; f[1] = a.y; f[2] = a.z; f[3] = a.w;
            f[4] = b.x; f[5] = b.y; f[6] = b.z; f[7] = b.w;
        } else {
#pragma unroll
            for (int i = 0; i < 8; i++) f[i] = 0.f;
        }
        uint32_t hp[4], lp[4];
#pragma unroll
        for (int i = 0; i < 4; i++) {
            __nv_bfloat16 h0 = __float2bfloat16(f[2 * i]);
            __nv_bfloat16 h1 = __float2bfloat16(f[2 * i + 1]);
            float l0 = f[2 * i] - __bfloat162float(h0);
            float l1 = f[2 * i + 1] - __bfloat162float(h1);
            __nv_bfloat162 hh = __halves2bfloat162(h0, h1);
            __nv_bfloat162 ll = __halves2bfloat162(__float2bfloat16(l0),
                                                   __float2bfloat16(l1));
            hp[i] = *reinterpret_cast<uint32_t*>(&hh);
            lp[i] = *reinterpret_cast<uint32_t*>(&ll);
        }
        *reinterpret_cast<uint4*>(smem + OFF_A_HI + off + g * 16) =
            make_uint4(hp[0], hp[1], hp[2], hp[3]);
        *reinterpret_cast<uint4*>(smem + OFF_A_LO + off + g * 16) =
            make_uint4(lp[0], lp[1], lp[2], lp[3]);
    }
}

// copy one pre-split B tile (hi/lo [k][n] images) into padded smem rows
__device__ __forceinline__ void stage_b(char* smem, const __nv_bfloat16* bh,
                                        const __nv_bfloat16* bl, int tid) {
    const uint4* h4 = (const uint4*)bh;
    const uint4* l4 = (const uint4*)bl;
    for (int i = tid; i < 2048; i += 256) {
        int k = i >> 4, s = i & 15;
        *(uint4*)(smem + OFF_B_HI + k * ROWB + s * 16) = h4[i];
        *(uint4*)(smem + OFF_B_LO + k * ROWB + s * 16) = l4[i];
    }
}

// core: 8 warps; warp (wm=w&1, wn=w>>1): rows wm*32..+31, cols wn*32..+31
__device__ __forceinline__ void mma_core(uint32_t sb, float acc[8][4]) {
    int lane = threadIdx.x & 31;
    int w = threadIdx.x >> 5;
    int wm = w & 1, wn = w >> 1;
    uint32_t aaddr[2], baddr[4];
#pragma unroll
    for (int mt = 0; mt < 2; mt++)
        aaddr[mt] = sb + OFF_A_HI +
                    (uint32_t)(wm * 32 + mt * 16 + (lane & 15)) * ROWB +
                    (lane >> 4) * 16;
#pragma unroll
    for (int nt = 0; nt < 4; nt++)
        baddr[nt] = sb + OFF_B_HI + (uint32_t)(lane & 15) * ROWB +
                    (wn * 32 + nt * 8) * 2;
#pragma unroll 2
    for (int ks = 0; ks < 8; ks++) {
        uint32_t bh[4][2], bl[4][2];
#pragma unroll
        for (int nt = 0; nt < 4; nt++) {
            uint32_t ba = baddr[nt] + ks * (16 * ROWB);
            ldsm2t(ba, bh[nt]);
            ldsm2t(ba + (OFF_B_LO - OFF_B_HI), bl[nt]);
        }
#pragma unroll
        for (int mt = 0; mt < 2; mt++) {
            uint32_t ah[4], al[4];
            uint32_t aa = aaddr[mt] + ks * 32;
            ldsm4(aa, ah);
            ldsm4(aa + (OFF_A_LO - OFF_A_HI), al);
#pragma unroll
            for (int nt = 0; nt < 4; nt++) {
                mma16816(acc[mt * 4 + nt], ah, bh[nt]);
                mma16816(acc[mt * 4 + nt], ah, bl[nt]);
                mma16816(acc[mt * 4 + nt], al, bh[nt]);
            }
        }
    }
}

// ---------------- tiny prep ----------------------------------------------
__global__ void k_rws(const float* __restrict__ rw0, const float* __restrict__ rw1) {
    int i = threadIdx.x;
    if (i < NET) {
        float v = rw0[i] * 100.0f;
        g_rws[i] = (v >= 0.0f) ? v : 0.01f * v;
    } else if (i < 2 * NET) {
        float v = rw1[i - NET] * 100.0f;
        g_rws[i] = (v >= 0.0f) ? v : 0.01f * v;
    }
}

__global__ void k_zero_small() {
    int i = blockIdx.x * blockDim.x + threadIdx.x;
    if (i < N_NODES) { g_deg0[i] = 0.0f; g_deg1[i] = 0.0f; }
    if (i < HID)     { g_sum[i] = 0.0f;  g_sumsq[i] = 0.0f; }
    if (i < 2)       { g_cnt[i] = 0; }
}

__global__ void k_zero_aggs() {
    const int total = N_NODES * HID / 4;
    float4 z = {0.f, 0.f, 0.f, 0.f};
    for (int i = blockIdx.x * blockDim.x + threadIdx.x; i < total;
         i += gridDim.x * blockDim.x) {
        ((float4*)g_agg0)[i] = z;
        ((float4*)g_agg1)[i] = z;
    }
}

// warp-aggregated two-way partition
__global__ void k_partition(const int* __restrict__ ntype) {
    int n = blockIdx.x * blockDim.x + threadIdx.x;
    bool valid = n < N_NODES;
    int t = valid ? ntype[n] : -1;
    int lane = threadIdx.x & 31;
#pragma unroll
    for (int tt = 0; tt < 2; tt++) {
        unsigned m = __ballot_sync(0xffffffffu, t == tt);
        if (t == tt) {
            int leader = __ffs(m) - 1;
            int pos = 0;
            if (lane == leader) pos = atomicAdd(&g_cnt[tt], __popc(m));
            pos = __shfl_sync(m, pos, leader);
            pos += __popc(m & ((1u << lane) - 1u));
            if (tt == 0) g_list0[pos] = n; else g_list1[pos] = n;
        }
    }
}

__global__ void k_deg(const int* __restrict__ ei, const int* __restrict__ et) {
    int e = blockIdx.x * blockDim.x + threadIdx.x;
    if (e >= N_EDGES) return;
    int c = ei[N_EDGES + e];
    int t = et[e];
    atomicAdd(&g_deg0[c], g_rws[t]);
    atomicAdd(&g_deg1[c], g_rws[NET + t]);
}

__global__ void k_ew(const int* __restrict__ ei, const int* __restrict__ et) {
    int e = blockIdx.x * blockDim.x + threadIdx.x;
    if (e >= N_EDGES) return;
    int t = et[e];
    int c = ei[N_EDGES + e];
    g_ew0[e] = g_rws[t] / fabsf(g_deg0[c]);
    g_ew1[e] = g_rws[NET + t] / fabsf(g_deg1[c]);
}

// split W (fp32 [K=128][ncols]) into bf16 hi/lo tile images [t][k][n]
__global__ void k_prep(const float* __restrict__ W, int ncols, int ntiles, int which) {
    int idx = blockIdx.x * blockDim.x + threadIdx.x;
    if (idx >= ntiles * 16384) return;
    __nv_bfloat16 *hi, *lo;
    switch (which) {
        case 0: hi = g_wI0h; lo = g_wI0l; break;
        case 1: hi = g_wI1h; lo = g_wI1l; break;
        case 2: hi = g_wC0h; lo = g_wC0l; break;
        default: hi = g_wC1h; lo = g_wC1l; break;
    }
    int t = idx >> 14;
    int rem = idx & 16383;
    int k = rem >> 7;
    int n = rem & 127;
    int col = t * 128 + n;
    float v = (col < ncols) ? W[(size_t)k * ncols + col] : 0.f;
    __nv_bfloat16 h = __float2bfloat16(v);
    hi[idx] = h;
    lo[idx] = __float2bfloat16(v - __bfloat162float(h));
}

// ---------------- mma GEMM kernels ----------------------------------------

// input linear (compacted rows of one type): h[n] = x_k[lidx[n]] @ W + b
__global__ __launch_bounds__(256) void k_mma_input(
    const float* __restrict__ xk, const int* __restrict__ lidx,
    const float* __restrict__ b, int pass) {
    const int cnt = g_cnt[pass];
    const int m0 = blockIdx.x * MTILE;
    if (m0 >= cnt) return;
    const int* list = pass ? g_list1 : g_list0;
    extern __shared__ char smem[];
    int tid = threadIdx.x;

    stage_b(smem, pass ? g_wI1h : g_wI0h, pass ? g_wI1l : g_wI0l, tid);
    {
        int row = tid >> 2, q = tid & 3;
        int lr = m0 + row;
        const float* src = nullptr;
        if (lr < cnt) src = xk + (size_t)lidx[list[lr]] * HID + q * 32;
        stage_quarter(smem, row, q, src);
    }
    __syncthreads();

    float acc[8][4] = {};
    mma_core(smem_u32(smem), acc);

    int lane = tid & 31, w = tid >> 5, wm = w & 1, wn = w >> 1;
#pragma unroll
    for (int mt = 0; mt < 2; mt++)
#pragma unroll
        for (int half = 0; half < 2; half++) {
            int lr = m0 + wm * 32 + mt * 16 + (lane >> 2) + half * 8;
            if (lr >= cnt) continue;
            float* dst = g_h + (size_t)list[lr] * HID;
#pragma unroll
            for (int nt = 0; nt < 4; nt++) {
                int c = wn * 32 + nt * 8 + (lane & 3) * 2;
                float2 bb = *(const float2*)(b + c);
                float2 o = {acc[mt * 4 + nt][half * 2 + 0] + bb.x,
                            acc[mt * 4 + nt][half * 2 + 1] + bb.y};
                *(float2*)(dst + c) = o;
            }
        }
}

// g_x = g_agg0 @ conv0_w + b + g_h (residual)
__global__ __launch_bounds__(256) void k_mma_gemm0(const float* __restrict__ b) {
    const int m0 = blockIdx.x * MTILE;
    extern __shared__ char smem[];
    int tid = threadIdx.x;

    stage_b(smem, g_wC0h, g_wC0l, tid);
    {
        int row = tid >> 2, q = tid & 3;
        int gr = m0 + row;
        const float* src =
            (gr < N_NODES) ? (g_agg0 + (size_t)gr * HID + q * 32) : nullptr;
        stage_quarter(smem, row, q, src);
    }
    __syncthreads();

    float acc[8][4] = {};
    mma_core(smem_u32(smem), acc);

    int lane = tid & 31, w = tid >> 5, wm = w & 1, wn = w >> 1;
#pragma unroll
    for (int mt = 0; mt < 2; mt++)
#pragma unroll
        for (int half = 0; half < 2; half++) {
            int gr = m0 + wm * 32 + mt * 16 + (lane >> 2) + half * 8;
            if (gr >= N_NODES) continue;
            float* dst = g_x + (size_t)gr * HID;
            const float* hres = g_h + (size_t)gr * HID;
#pragma unroll
            for (int nt = 0; nt < 4; nt++) {
                int c = wn * 32 + nt * 8 + (lane & 3) * 2;
                float2 bb = *(const float2*)(b + c);
                float2 hv = *(const float2*)(hres + c);
                float2 o = {acc[mt * 4 + nt][half * 2 + 0] + bb.x + hv.x,
                            acc[mt * 4 + nt][half * 2 + 1] + bb.y + hv.y};
                *(float2*)(dst + c) = o;
            }
        }
}

// out = g_agg1 @ conv1_w + b : A staged once, loop 3 N-tiles in-kernel
__global__ __launch_bounds__(256) void k_mma_gemm1(const float* __restrict__ b,
                                                   float* __restrict__ out) {
    const int m0 = blockIdx.x * MTILE;
    extern __shared__ char smem[];
    int tid = threadIdx.x;

    {
        int row = tid >> 2, q = tid & 3;
        int gr = m0 + row;
        const float* src =
            (gr < N_NODES) ? (g_agg1 + (size_t)gr * HID + q * 32) : nullptr;
        stage_quarter(smem, row, q, src);
    }

    int lane = tid & 31, w = tid >> 5, wm = w & 1, wn = w >> 1;

    for (int ny = 0; ny < 3; ny++) {
        if (ny) __syncthreads();  // prior mma reads of B done
        stage_b(smem, g_wC1h + (size_t)ny * 16384, g_wC1l + (size_t)ny * 16384, tid);
        __syncthreads();

        float acc[8][4] = {};
        mma_core(smem_u32(smem), acc);

        int n0 = ny * 128;
#pragma unroll
        for (int mt = 0; mt < 2; mt++)
#pragma unroll
            for (int half = 0; half < 2; half++) {
                int gr = m0 + wm * 32 + mt * 16 + (lane >> 2) + half * 8;
                if (gr >= N_NODES) continue;
                float* dst = out + (size_t)gr * OUTD;
#pragma unroll
                for (int nt = 0; nt < 4; nt++) {
                    int c = n0 + wn * 32 + nt * 8 + (lane & 3) * 2;
                    if (c < OUTD)
                        dst[c] = acc[mt * 4 + nt][half * 2 + 0] + b[c];
                    if (c + 1 < OUTD)
                        dst[c + 1] = acc[mt * 4 + nt][half * 2 + 1] + b[c + 1];
                }
            }
    }
}

// ---------------- scatter: agg[col] += ew[e] * y[row] ----------------------
// layer 0: y = g_h. layer 1: y = prelu(bn(g_x)) computed on the fly.
__global__ void k_scatter(const int* __restrict__ ei,
                          const float* __restrict__ prelu_a, int layer) {
    int gt = blockIdx.x * blockDim.x + threadIdx.x;
    int e = gt >> 5;
    int lane = gt & 31;
    if (e >= N_EDGES) return;
    const float* ew = (layer == 0) ? g_ew0 : g_ew1;
    float* dst = (layer == 0) ? g_agg0 : g_agg1;
    float wgt = __ldg(&ew[e]);
    int r = __ldg(&ei[e]);
    int c = __ldg(&ei[N_EDGES + e]);
    float4 v;
    if (layer == 0) {
        v = ((const float4*)(g_h + (size_t)r * HID))[lane];
    } else {
        float4 x = ((const float4*)(g_x + (size_t)r * HID))[lane];
        float4 sc = ((const float4*)g_bnscale)[lane];
        float4 sh = ((const float4*)g_bnshift)[lane];
        float a = __ldg(prelu_a);
        v.x = x.x * sc.x + sh.x;
        v.y = x.y * sc.y + sh.y;
        v.z = x.z * sc.z + sh.z;
        v.w = x.w * sc.w + sh.w;
        v.x = (v.x >= 0.f) ? v.x : a * v.x;
        v.y = (v.y >= 0.f) ? v.y : a * v.y;
        v.z = (v.z >= 0.f) ? v.z : a * v.z;
        v.w = (v.w >= 0.f) ? v.w : a * v.w;
    }
    v.x *= wgt; v.y *= wgt; v.z *= wgt; v.w *= wgt;
    float* addr = dst + (size_t)c * HID + lane * 4;
    asm volatile("red.global.add.v4.f32 [%0], {%1,%2,%3,%4};"
                 :: "l"(addr), "f"(v.x), "f"(v.y), "f"(v.z), "f"(v.w)
                 : "memory");
}

// ---------------- BN -------------------------------------------------------
__global__ __launch_bounds__(128) void k_stats() {
    int j = threadIdx.x;
    float s = 0.f, s2 = 0.f;
    for (int n = blockIdx.x; n < N_NODES; n += gridDim.x) {
        float v = g_x[(size_t)n * HID + j];
        s += v;
        s2 += v * v;
    }
    atomicAdd(&g_sum[j], s);
    atomicAdd(&g_sumsq[j], s2);
}

__global__ void k_bnfinal(const float* __restrict__ gamma,
                          const float* __restrict__ beta) {
    int j = threadIdx.x;
    if (j >= HID) return;
    float mean = g_sum[j] / (float)N_NODES;
    float var = g_sumsq[j] / (float)N_NODES - mean * mean;
    float sc = gamma[j] * rsqrtf(var + BN_EPS);
    g_bnscale[j] = sc;
    g_bnshift[j] = beta[j] - mean * sc;
}

// ---------------- log_softmax (in place on d_out) --------------------------
__global__ __launch_bounds__(128) void k_logsoftmax(float* __restrict__ out) {
    int n = blockIdx.x;
    float* row = out + (size_t)n * OUTD;
    int j = threadIdx.x;
    float v0 = row[j];
    float v1 = (j + 128 < OUTD) ? row[j + 128] : -1e30f;
    float v2 = (j + 256 < OUTD) ? row[j + 256] : -1e30f;
    __shared__ float red[128];
    float m = fmaxf(v0, fmaxf(v1, v2));
    red[j] = m;
    __syncthreads();
#pragma unroll
    for (int s = 64; s > 0; s >>= 1) {
        if (j < s) red[j] = fmaxf(red[j], red[j + s]);
        __syncthreads();
    }
    float mx = red[0];
    __syncthreads();
    float e = expf(v0 - mx);
    if (j + 128 < OUTD) e += expf(v1 - mx);
    if (j + 256 < OUTD) e += expf(v2 - mx);
    red[j] = e;
    __syncthreads();
#pragma unroll
    for (int s = 64; s > 0; s >>= 1) {
        if (j < s) red[j] += red[j + s];
        __syncthreads();
    }
    float lse = logf(red[0]) + mx;
    row[j] = v0 - lse;
    if (j + 128 < OUTD) row[j + 128] = v1 - lse;
    if (j + 256 < OUTD) row[j + 256] = v2 - lse;
}

// ---------------- launch ---------------------------------------------------
extern "C" void kernel_launch(void* const* d_in, const int* in_sizes, int n_in,
                              void* d_out, int out_size) {
    const float* x0 = (const float*)d_in[0];
    const float* x1 = (const float*)d_in[1];
    const int* edge_index = (const int*)d_in[2];
    const int* edge_type = (const int*)d_in[3];
    const int* node_type = (const int*)d_in[4];
    const int* lidx = (const int*)d_in[5];
    const float* lin0_w = (const float*)d_in[6];
    const float* lin0_b = (const float*)d_in[7];
    const float* lin1_w = (const float*)d_in[8];
    const float* lin1_b = (const float*)d_in[9];
    const float* conv0_w = (const float*)d_in[10];
    const float* conv0_b = (const float*)d_in[11];
    const float* conv0_rw = (const float*)d_in[12];
    const float* conv1_w = (const float*)d_in[13];
    const float* conv1_b = (const float*)d_in[14];
    const float* conv1_rw = (const float*)d_in[15];
    const float* bn_g = (const float*)d_in[16];
    const float* bn_b = (const float*)d_in[17];
    const float* prelu_a = (const float*)d_in[18];
    float* out = (float*)d_out;

    cudaFuncSetAttribute(k_mma_input, cudaFuncAttributeMaxDynamicSharedMemorySize, SMEM_MMA);
    cudaFuncSetAttribute(k_mma_gemm0, cudaFuncAttributeMaxDynamicSharedMemorySize, SMEM_MMA);
    cudaFuncSetAttribute(k_mma_gemm1, cudaFuncAttributeMaxDynamicSharedMemorySize, SMEM_MMA);

    k_rws<<<1, 32>>>(conv0_rw, conv1_rw);
    k_zero_small<<<(N_NODES + 255) / 256, 256>>>();
    k_zero_aggs<<<2048, 256>>>();
    k_partition<<<(N_NODES + 255) / 256, 256>>>(node_type);
    k_deg<<<(N_EDGES + 255) / 256, 256>>>(edge_index, edge_type);
    k_ew<<<(N_EDGES + 255) / 256, 256>>>(edge_index, edge_type);

    // weight hi/lo images
    k_prep<<<64, 256>>>(lin0_w, HID, 1, 0);
    k_prep<<<64, 256>>>(lin1_w, HID, 1, 1);
    k_prep<<<64, 256>>>(conv0_w, HID, 1, 2);
    k_prep<<<192, 256>>>(conv1_w, OUTD, 3, 3);

    // input linears (compacted by node type)
    k_mma_input<<<NTILES_M, 256, SMEM_MMA>>>(x0, lidx, lin0_b, 0);
    k_mma_input<<<NTILES_M, 256, SMEM_MMA>>>(x1, lidx, lin1_b, 1);

    const int SC_BLOCKS = (int)(((long long)N_EDGES * 32 + 255) / 256);

    // layer 0
    k_scatter<<<SC_BLOCKS, 256>>>(edge_index, prelu_a, 0);
    k_mma_gemm0<<<NTILES_M, 256, SMEM_MMA>>>(conv0_b);

    k_stats<<<512, 128>>>();
    k_bnfinal<<<1, 128>>>(bn_g, bn_b);

    // layer 1 (BN+PReLU fused into scatter load)
    k_scatter<<<SC_BLOCKS, 256>>>(edge_index, prelu_a, 1);
    k_mma_gemm1<<<NTILES_M, 256, SMEM_MMA>>>(conv1_b, out);

    k_logsoftmax<<<N_NODES, 128>>>(out);
}

// round 9
// speedup vs baseline: 2.4268x; 1.1277x over previous
#include <cuda_runtime.h>
#include <cuda_bf16.h>
#include <cstdint>

#define N_NODES 100000
#define N_EDGES 500000
#define HID 128
#define OUTD 349
#define NET 8
#define BN_EPS 1e-5f
#define MTILE 64
#define NTILES_M ((N_NODES + MTILE - 1) / MTILE)  // 1563

// ---------------- scratch (static device globals; no allocation) ----------
__device__ float g_h[N_NODES * HID];     // input-linear output (residual source)
__device__ float g_x[N_NODES * HID];     // conv0 out + residual (BN input)
__device__ float g_agg0[N_NODES * HID];  // scatter target layer 0
__device__ float g_agg1[N_NODES * HID];  // scatter target layer 1
__device__ float g_ew0[N_EDGES], g_ew1[N_EDGES];
__device__ float g_deg0[N_NODES], g_deg1[N_NODES];
__device__ float g_rws[2 * NET];
__device__ float g_sum[HID], g_sumsq[HID];
__device__ float g_bnscale[HID], g_bnshift[HID];
__device__ int   g_cnt[2];
__device__ int   g_list0[N_NODES], g_list1[N_NODES];

// bf16 hi/lo weight images, layout [tile][k=128][n=128] row-major
__device__ __nv_bfloat16 g_wI0h[16384], g_wI0l[16384];       // lin0_w
__device__ __nv_bfloat16 g_wI1h[16384], g_wI1l[16384];       // lin1_w
__device__ __nv_bfloat16 g_wC0h[16384], g_wC0l[16384];       // conv0_w
__device__ __nv_bfloat16 g_wC1h[3 * 16384], g_wC1l[3 * 16384];  // conv1_w (3 tiles)

// ---------------- mma.sync GEMM machinery ----------------------------------
#define ROWB 272                    // 136 bf16 padded row (conflict-free LDSM)
#define OFF_A_HI 0
#define OFF_A_LO 17408
#define OFF_B_HI 34816
#define OFF_B_LO 69632
#define SMEM_MMA 104448             // 102KB -> 2 CTAs/SM

__device__ __forceinline__ uint32_t smem_u32(const void* p) {
    uint32_t a;
    asm("{ .reg .u64 t; cvta.to.shared.u64 t, %1; cvt.u32.u64 %0, t; }"
        : "=r"(a) : "l"(p));
    return a;
}

__device__ __forceinline__ void ldsm4(uint32_t addr, uint32_t* r) {
    asm volatile("ldmatrix.sync.aligned.m8n8.x4.shared.b16 {%0,%1,%2,%3}, [%4];"
                 : "=r"(r[0]), "=r"(r[1]), "=r"(r[2]), "=r"(r[3]) : "r"(addr));
}
__device__ __forceinline__ void ldsm2t(uint32_t addr, uint32_t* r) {
    asm volatile("ldmatrix.sync.aligned.m8n8.x2.trans.shared.b16 {%0,%1}, [%2];"
                 : "=r"(r[0]), "=r"(r[1]) : "r"(addr));
}
__device__ __forceinline__ void mma16816(float* d, const uint32_t* a, const uint32_t* b) {
    asm volatile(
        "mma.sync.aligned.m16n8k16.row.col.f32.bf16.bf16.f32 "
        "{%0,%1,%2,%3}, {%4,%5,%6,%7}, {%8,%9}, {%0,%1,%2,%3};"
        : "+f"(d[0]), "+f"(d[1]), "+f"(d[2]), "+f"(d[3])
        : "r"(a[0]), "r"(a[1]), "r"(a[2]), "r"(a[3]), "r"(b[0]), "r"(b[1]));
}

// packed hi/lo split: two floats -> bf16x2 hi + bf16x2 lo (6 instructions)
__device__ __forceinline__ void cvt_hilo(float f0, float f1,
                                         uint32_t& hi2, uint32_t& lo2) {
    asm("cvt.rn.bf16x2.f32 %0, %1, %2;" : "=r"(hi2) : "f"(f1), "f"(f0));
    float h0 = __uint_as_float(hi2 << 16);          // bf16 lo half -> f32
    float h1 = __uint_as_float(hi2 & 0xffff0000u);  // bf16 hi half -> f32
    float l0 = f0 - h0, l1 = f1 - h1;
    asm("cvt.rn.bf16x2.f32 %0, %1, %2;" : "=r"(lo2) : "f"(l1), "f"(l0));
}

// stage 32 fp32 (quarter row) as bf16 hi/lo into padded A tiles
__device__ __forceinline__ void stage_quarter(char* smem, int row, int q,
                                              const float* src) {
    uint32_t off = (uint32_t)row * ROWB + q * 64;
#pragma unroll
    for (int g = 0; g < 4; g++) {
        float f[8];
        if (src) {
            float4 a = ((const float4*)src)[g * 2];
            float4 b = ((const float4*)src)[g * 2 + 1];
            f[0] = a.x; f[1] = a.y; f[2] = a.z; f[3] = a.w;
            f[4] = b.x; f[5] = b.y; f[6] = b.z; f[7] = b.w;
        } else {
#pragma unroll
            for (int i = 0; i < 8; i++) f[i] = 0.f;
        }
        uint32_t hp[4], lp[4];
#pragma unroll
        for (int i = 0; i < 4; i++) cvt_hilo(f[2 * i], f[2 * i + 1], hp[i], lp[i]);
        *reinterpret_cast<uint4*>(smem + OFF_A_HI + off + g * 16) =
            make_uint4(hp[0], hp[1], hp[2], hp[3]);
        *reinterpret_cast<uint4*>(smem + OFF_A_LO + off + g * 16) =
            make_uint4(lp[0], lp[1], lp[2], lp[3]);
    }
}

// copy one pre-split B tile (hi/lo [k][n] images) into padded smem rows
__device__ __forceinline__ void stage_b(char* smem, const __nv_bfloat16* bh,
                                        const __nv_bfloat16* bl, int tid) {
    const uint4* h4 = (const uint4*)bh;
    const uint4* l4 = (const uint4*)bl;
    for (int i = tid; i < 2048; i += 256) {
        int k = i >> 4, s = i & 15;
        *(uint4*)(smem + OFF_B_HI + k * ROWB + s * 16) = h4[i];
        *(uint4*)(smem + OFF_B_LO + k * ROWB + s * 16) = l4[i];
    }
}

// core: 8 warps; warp (wm=w&1, wn=w>>1): rows wm*32..+31, cols wn*32..+31
__device__ __forceinline__ void mma_core(uint32_t sb, float acc[8][4]) {
    int lane = threadIdx.x & 31;
    int w = threadIdx.x >> 5;
    int wm = w & 1, wn = w >> 1;
    uint32_t aaddr[2], baddr[4];
#pragma unroll
    for (int mt = 0; mt < 2; mt++)
        aaddr[mt] = sb + OFF_A_HI +
                    (uint32_t)(wm * 32 + mt * 16 + (lane & 15)) * ROWB +
                    (lane >> 4) * 16;
#pragma unroll
    for (int nt = 0; nt < 4; nt++)
        baddr[nt] = sb + OFF_B_HI + (uint32_t)(lane & 15) * ROWB +
                    (wn * 32 + nt * 8) * 2;
#pragma unroll 2
    for (int ks = 0; ks < 8; ks++) {
        uint32_t bh[4][2], bl[4][2];
#pragma unroll
        for (int nt = 0; nt < 4; nt++) {
            uint32_t ba = baddr[nt] + ks * (16 * ROWB);
            ldsm2t(ba, bh[nt]);
            ldsm2t(ba + (OFF_B_LO - OFF_B_HI), bl[nt]);
        }
#pragma unroll
        for (int mt = 0; mt < 2; mt++) {
            uint32_t ah[4], al[4];
            uint32_t aa = aaddr[mt] + ks * 32;
            ldsm4(aa, ah);
            ldsm4(aa + (OFF_A_LO - OFF_A_HI), al);
#pragma unroll
            for (int nt = 0; nt < 4; nt++) {
                mma16816(acc[mt * 4 + nt], ah, bh[nt]);
                mma16816(acc[mt * 4 + nt], ah, bl[nt]);
                mma16816(acc[mt * 4 + nt], al, bh[nt]);
            }
        }
    }
}

// ---------------- prep ----------------------------------------------------
// zeroing + relation-weight leaky-relu in one kernel
__global__ void k_init(const float* __restrict__ rw0, const float* __restrict__ rw1) {
    int i = blockIdx.x * blockDim.x + threadIdx.x;
    if (i < N_NODES) { g_deg0[i] = 0.0f; g_deg1[i] = 0.0f; }
    if (i < HID)     { g_sum[i] = 0.0f;  g_sumsq[i] = 0.0f; }
    if (i < 2)       { g_cnt[i] = 0; }
    if (i < NET) {
        float v = rw0[i] * 100.0f;
        g_rws[i] = (v >= 0.0f) ? v : 0.01f * v;
    } else if (i < 2 * NET) {
        float v = rw1[i - NET] * 100.0f;
        g_rws[i] = (v >= 0.0f) ? v : 0.01f * v;
    }
}

__global__ void k_zero_aggs() {
    const int total = N_NODES * HID / 4;
    float4 z = {0.f, 0.f, 0.f, 0.f};
    for (int i = blockIdx.x * blockDim.x + threadIdx.x; i < total;
         i += gridDim.x * blockDim.x) {
        ((float4*)g_agg0)[i] = z;
        ((float4*)g_agg1)[i] = z;
    }
}

// warp-aggregated two-way partition
__global__ void k_partition(const int* __restrict__ ntype) {
    int n = blockIdx.x * blockDim.x + threadIdx.x;
    bool valid = n < N_NODES;
    int t = valid ? ntype[n] : -1;
    int lane = threadIdx.x & 31;
#pragma unroll
    for (int tt = 0; tt < 2; tt++) {
        unsigned m = __ballot_sync(0xffffffffu, t == tt);
        if (t == tt) {
            int leader = __ffs(m) - 1;
            int pos = 0;
            if (lane == leader) pos = atomicAdd(&g_cnt[tt], __popc(m));
            pos = __shfl_sync(m, pos, leader);
            pos += __popc(m & ((1u << lane) - 1u));
            if (tt == 0) g_list0[pos] = n; else g_list1[pos] = n;
        }
    }
}

__global__ void k_deg(const int* __restrict__ ei, const int* __restrict__ et) {
    int e = blockIdx.x * blockDim.x + threadIdx.x;
    if (e >= N_EDGES) return;
    int c = ei[N_EDGES + e];
    int t = et[e];
    atomicAdd(&g_deg0[c], g_rws[t]);
    atomicAdd(&g_deg1[c], g_rws[NET + t]);
}

__global__ void k_ew(const int* __restrict__ ei, const int* __restrict__ et) {
    int e = blockIdx.x * blockDim.x + threadIdx.x;
    if (e >= N_EDGES) return;
    int t = et[e];
    int c = ei[N_EDGES + e];
    g_ew0[e] = g_rws[t] / fabsf(g_deg0[c]);
    g_ew1[e] = g_rws[NET + t] / fabsf(g_deg1[c]);
}

// all weight hi/lo images in one launch (6 tile-images)
__global__ void k_prep_all(const float* __restrict__ lin0_w,
                           const float* __restrict__ lin1_w,
                           const float* __restrict__ conv0_w,
                           const float* __restrict__ conv1_w) {
    int idx = blockIdx.x * blockDim.x + threadIdx.x;
    if (idx >= 6 * 16384) return;
    int img = idx >> 14;
    int rem = idx & 16383;
    int k = rem >> 7, n = rem & 127;
    const float* W;
    int ncols, col, off;
    __nv_bfloat16 *hi, *lo;
    if (img == 0)      { W = lin0_w;  ncols = HID;  col = n; hi = g_wI0h; lo = g_wI0l; off = rem; }
    else if (img == 1) { W = lin1_w;  ncols = HID;  col = n; hi = g_wI1h; lo = g_wI1l; off = rem; }
    else if (img == 2) { W = conv0_w; ncols = HID;  col = n; hi = g_wC0h; lo = g_wC0l; off = rem; }
    else { int t = img - 3; W = conv1_w; ncols = OUTD; col = t * 128 + n;
           hi = g_wC1h; lo = g_wC1l; off = t * 16384 + rem; }
    float v = (col < ncols) ? W[(size_t)k * ncols + col] : 0.f;
    __nv_bfloat16 h = __float2bfloat16(v);
    hi[off] = h;
    lo[off] = __float2bfloat16(v - __bfloat162float(h));
}

// ---------------- mma GEMM kernels ----------------------------------------

// input linear (compacted rows of one type): h[n] = x_k[lidx[n]] @ W + b
__global__ __launch_bounds__(256) void k_mma_input(
    const float* __restrict__ xk, const int* __restrict__ lidx,
    const float* __restrict__ b, int pass) {
    const int cnt = g_cnt[pass];
    const int m0 = blockIdx.x * MTILE;
    if (m0 >= cnt) return;
    const int* list = pass ? g_list1 : g_list0;
    extern __shared__ char smem[];
    int tid = threadIdx.x;

    stage_b(smem, pass ? g_wI1h : g_wI0h, pass ? g_wI1l : g_wI0l, tid);
    {
        int row = tid >> 2, q = tid & 3;
        int lr = m0 + row;
        const float* src = nullptr;
        if (lr < cnt) src = xk + (size_t)lidx[list[lr]] * HID + q * 32;
        stage_quarter(smem, row, q, src);
    }
    __syncthreads();

    float acc[8][4] = {};
    mma_core(smem_u32(smem), acc);

    int lane = tid & 31, w = tid >> 5, wm = w & 1, wn = w >> 1;
#pragma unroll
    for (int mt = 0; mt < 2; mt++)
#pragma unroll
        for (int half = 0; half < 2; half++) {
            int lr = m0 + wm * 32 + mt * 16 + (lane >> 2) + half * 8;
            if (lr >= cnt) continue;
            float* dst = g_h + (size_t)list[lr] * HID;
#pragma unroll
            for (int nt = 0; nt < 4; nt++) {
                int c = wn * 32 + nt * 8 + (lane & 3) * 2;
                float2 bb = *(const float2*)(b + c);
                float2 o = {acc[mt * 4 + nt][half * 2 + 0] + bb.x,
                            acc[mt * 4 + nt][half * 2 + 1] + bb.y};
                *(float2*)(dst + c) = o;
            }
        }
}

// g_x = g_agg0 @ conv0_w + b + g_h (residual); BN stats fused in epilogue
__global__ __launch_bounds__(256) void k_mma_gemm0(const float* __restrict__ b) {
    const int m0 = blockIdx.x * MTILE;
    extern __shared__ char smem[];
    int tid = threadIdx.x;

    stage_b(smem, g_wC0h, g_wC0l, tid);
    {
        int row = tid >> 2, q = tid & 3;
        int gr = m0 + row;
        const float* src =
            (gr < N_NODES) ? (g_agg0 + (size_t)gr * HID + q * 32) : nullptr;
        stage_quarter(smem, row, q, src);
    }
    __syncthreads();

    float acc[8][4] = {};
    mma_core(smem_u32(smem), acc);

    int lane = tid & 31, w = tid >> 5, wm = w & 1, wn = w >> 1;
    float s[4][2] = {}, s2[4][2] = {};
#pragma unroll
    for (int mt = 0; mt < 2; mt++)
#pragma unroll
        for (int half = 0; half < 2; half++) {
            int gr = m0 + wm * 32 + mt * 16 + (lane >> 2) + half * 8;
            if (gr >= N_NODES) continue;
            float* dst = g_x + (size_t)gr * HID;
            const float* hres = g_h + (size_t)gr * HID;
#pragma unroll
            for (int nt = 0; nt < 4; nt++) {
                int c = wn * 32 + nt * 8 + (lane & 3) * 2;
                float2 bb = *(const float2*)(b + c);
                float2 hv = *(const float2*)(hres + c);
                float2 o = {acc[mt * 4 + nt][half * 2 + 0] + bb.x + hv.x,
                            acc[mt * 4 + nt][half * 2 + 1] + bb.y + hv.y};
                *(float2*)(dst + c) = o;
                s[nt][0] += o.x;  s2[nt][0] += o.x * o.x;
                s[nt][1] += o.y;  s2[nt][1] += o.y * o.y;
            }
        }
    // reduce over the 8 row-groups (lane bits 2-4) within the warp
#pragma unroll
    for (int d = 4; d < 32; d <<= 1)
#pragma unroll
        for (int nt = 0; nt < 4; nt++) {
            s[nt][0]  += __shfl_xor_sync(0xffffffffu, s[nt][0],  d);
            s[nt][1]  += __shfl_xor_sync(0xffffffffu, s[nt][1],  d);
            s2[nt][0] += __shfl_xor_sync(0xffffffffu, s2[nt][0], d);
            s2[nt][1] += __shfl_xor_sync(0xffffffffu, s2[nt][1], d);
        }
    if ((lane >> 2) == 0) {
#pragma unroll
        for (int nt = 0; nt < 4; nt++) {
            int c = wn * 32 + nt * 8 + (lane & 3) * 2;
            atomicAdd(&g_sum[c],       s[nt][0]);
            atomicAdd(&g_sum[c + 1],   s[nt][1]);
            atomicAdd(&g_sumsq[c],     s2[nt][0]);
            atomicAdd(&g_sumsq[c + 1], s2[nt][1]);
        }
    }
}

// out = g_agg1 @ conv1_w + b : A staged once, loop 3 N-tiles in-kernel
__global__ __launch_bounds__(256) void k_mma_gemm1(const float* __restrict__ b,
                                                   float* __restrict__ out) {
    const int m0 = blockIdx.x * MTILE;
    extern __shared__ char smem[];
    int tid = threadIdx.x;

    {
        int row = tid >> 2, q = tid & 3;
        int gr = m0 + row;
        const float* src =
            (gr < N_NODES) ? (g_agg1 + (size_t)gr * HID + q * 32) : nullptr;
        stage_quarter(smem, row, q, src);
    }

    int lane = tid & 31, w = tid >> 5, wm = w & 1, wn = w >> 1;

    for (int ny = 0; ny < 3; ny++) {
        if (ny) __syncthreads();  // prior mma reads of B done
        stage_b(smem, g_wC1h + (size_t)ny * 16384, g_wC1l + (size_t)ny * 16384, tid);
        __syncthreads();

        float acc[8][4] = {};
        mma_core(smem_u32(smem), acc);

        int n0 = ny * 128;
#pragma unroll
        for (int mt = 0; mt < 2; mt++)
#pragma unroll
            for (int half = 0; half < 2; half++) {
                int gr = m0 + wm * 32 + mt * 16 + (lane >> 2) + half * 8;
                if (gr >= N_NODES) continue;
                float* dst = out + (size_t)gr * OUTD;
#pragma unroll
                for (int nt = 0; nt < 4; nt++) {
                    int c = n0 + wn * 32 + nt * 8 + (lane & 3) * 2;
                    if (c < OUTD)
                        dst[c] = acc[mt * 4 + nt][half * 2 + 0] + b[c];
                    if (c + 1 < OUTD)
                        dst[c + 1] = acc[mt * 4 + nt][half * 2 + 1] + b[c + 1];
                }
            }
    }
}

// ---------------- scatter: agg[col] += ew[e] * y[row] ----------------------
// layer 0: y = g_h. layer 1: y = prelu(bn(g_x)) computed on the fly.
__global__ void k_scatter(const int* __restrict__ ei,
                          const float* __restrict__ prelu_a, int layer) {
    int gt = blockIdx.x * blockDim.x + threadIdx.x;
    int e = gt >> 5;
    int lane = gt & 31;
    if (e >= N_EDGES) return;
    const float* ew = (layer == 0) ? g_ew0 : g_ew1;
    float* dst = (layer == 0) ? g_agg0 : g_agg1;
    float wgt = __ldg(&ew[e]);
    int r = __ldg(&ei[e]);
    int c = __ldg(&ei[N_EDGES + e]);
    float4 v;
    if (layer == 0) {
        v = ((const float4*)(g_h + (size_t)r * HID))[lane];
    } else {
        float4 x = ((const float4*)(g_x + (size_t)r * HID))[lane];
        float4 sc = ((const float4*)g_bnscale)[lane];
        float4 sh = ((const float4*)g_bnshift)[lane];
        float a = __ldg(prelu_a);
        v.x = x.x * sc.x + sh.x;
        v.y = x.y * sc.y + sh.y;
        v.z = x.z * sc.z + sh.z;
        v.w = x.w * sc.w + sh.w;
        v.x = (v.x >= 0.f) ? v.x : a * v.x;
        v.y = (v.y >= 0.f) ? v.y : a * v.y;
        v.z = (v.z >= 0.f) ? v.z : a * v.z;
        v.w = (v.w >= 0.f) ? v.w : a * v.w;
    }
    v.x *= wgt; v.y *= wgt; v.z *= wgt; v.w *= wgt;
    float* addr = dst + (size_t)c * HID + lane * 4;
    asm volatile("red.global.add.v4.f32 [%0], {%1,%2,%3,%4};"
                 :: "l"(addr), "f"(v.x), "f"(v.y), "f"(v.z), "f"(v.w)
                 : "memory");
}

// ---------------- BN finalize ----------------------------------------------
__global__ void k_bnfinal(const float* __restrict__ gamma,
                          const float* __restrict__ beta) {
    int j = threadIdx.x;
    if (j >= HID) return;
    float mean = g_sum[j] / (float)N_NODES;
    float var = g_sumsq[j] / (float)N_NODES - mean * mean;
    float sc = gamma[j] * rsqrtf(var + BN_EPS);
    g_bnscale[j] = sc;
    g_bnshift[j] = beta[j] - mean * sc;
}

// ---------------- log_softmax (in place on d_out) --------------------------
__global__ __launch_bounds__(128) void k_logsoftmax(float* __restrict__ out) {
    int n = blockIdx.x;
    float* row = out + (size_t)n * OUTD;
    int j = threadIdx.x;
    float v0 = row[j];
    float v1 = (j + 128 < OUTD) ? row[j + 128] : -1e30f;
    float v2 = (j + 256 < OUTD) ? row[j + 256] : -1e30f;
    __shared__ float red[128];
    float m = fmaxf(v0, fmaxf(v1, v2));
    red[j] = m;
    __syncthreads();
#pragma unroll
    for (int s = 64; s > 0; s >>= 1) {
        if (j < s) red[j] = fmaxf(red[j], red[j + s]);
        __syncthreads();
    }
    float mx = red[0];
    __syncthreads();
    float e = expf(v0 - mx);
    if (j + 128 < OUTD) e += expf(v1 - mx);
    if (j + 256 < OUTD) e += expf(v2 - mx);
    red[j] = e;
    __syncthreads();
#pragma unroll
    for (int s = 64; s > 0; s >>= 1) {
        if (j < s) red[j] += red[j + s];
        __syncthreads();
    }
    float lse = logf(red[0]) + mx;
    row[j] = v0 - lse;
    if (j + 128 < OUTD) row[j + 128] = v1 - lse;
    if (j + 256 < OUTD) row[j + 256] = v2 - lse;
}

// ---------------- launch ---------------------------------------------------
extern "C" void kernel_launch(void* const* d_in, const int* in_sizes, int n_in,
                              void* d_out, int out_size) {
    const float* x0 = (const float*)d_in[0];
    const float* x1 = (const float*)d_in[1];
    const int* edge_index = (const int*)d_in[2];
    const int* edge_type = (const int*)d_in[3];
    const int* node_type = (const int*)d_in[4];
    const int* lidx = (const int*)d_in[5];
    const float* lin0_w = (const float*)d_in[6];
    const float* lin0_b = (const float*)d_in[7];
    const float* lin1_w = (const float*)d_in[8];
    const float* lin1_b = (const float*)d_in[9];
    const float* conv0_w = (const float*)d_in[10];
    const float* conv0_b = (const float*)d_in[11];
    const float* conv0_rw = (const float*)d_in[12];
    const float* conv1_w = (const float*)d_in[13];
    const float* conv1_b = (const float*)d_in[14];
    const float* conv1_rw = (const float*)d_in[15];
    const float* bn_g = (const float*)d_in[16];
    const float* bn_b = (const float*)d_in[17];
    const float* prelu_a = (const float*)d_in[18];
    float* out = (float*)d_out;

    cudaFuncSetAttribute(k_mma_input, cudaFuncAttributeMaxDynamicSharedMemorySize, SMEM_MMA);
    cudaFuncSetAttribute(k_mma_gemm0, cudaFuncAttributeMaxDynamicSharedMemorySize, SMEM_MMA);
    cudaFuncSetAttribute(k_mma_gemm1, cudaFuncAttributeMaxDynamicSharedMemorySize, SMEM_MMA);

    k_init<<<(N_NODES + 255) / 256, 256>>>(conv0_rw, conv1_rw);
    k_zero_aggs<<<2048, 256>>>();
    k_partition<<<(N_NODES + 255) / 256, 256>>>(node_type);
    k_deg<<<(N_EDGES + 255) / 256, 256>>>(edge_index, edge_type);
    k_ew<<<(N_EDGES + 255) / 256, 256>>>(edge_index, edge_type);
    k_prep_all<<<384, 256>>>(lin0_w, lin1_w, conv0_w, conv1_w);

    // input linears (compacted by node type)
    k_mma_input<<<NTILES_M, 256, SMEM_MMA>>>(x0, lidx, lin0_b, 0);
    k_mma_input<<<NTILES_M, 256, SMEM_MMA>>>(x1, lidx, lin1_b, 1);

    const int SC_BLOCKS = (int)(((long long)N_EDGES * 32 + 255) / 256);

    // layer 0 (BN stats fused into gemm0 epilogue)
    k_scatter<<<SC_BLOCKS, 256>>>(edge_index, prelu_a, 0);
    k_mma_gemm0<<<NTILES_M, 256, SMEM_MMA>>>(conv0_b);
    k_bnfinal<<<1, 128>>>(bn_g, bn_b);

    // layer 1 (BN+PReLU fused into scatter load)
    k_scatter<<<SC_BLOCKS, 256>>>(edge_index, prelu_a, 1);
    k_mma_gemm1<<<NTILES_M, 256, SMEM_MMA>>>(conv1_b, out);

    k_logsoftmax<<<N_NODES, 128>>>(out);
}

// round 10
// speedup vs baseline: 2.5081x; 1.0335x over previous
#include <cuda_runtime.h>
#include <cuda_bf16.h>
#include <cstdint>

#define N_NODES 100000
#define N_EDGES 500000
#define HID 128
#define OUTD 349
#define NET 8
#define BN_EPS 1e-5f
#define MTILE 64
#define NTILES_M ((N_NODES + MTILE - 1) / MTILE)  // 1563
#define NSCAN1 ((N_NODES + 1023) / 1024)          // 98

// ---------------- scratch (static device globals; no allocation) ----------
__device__ float g_h[N_NODES * HID];     // input-linear output (residual source)
__device__ float g_x[N_NODES * HID];     // conv0 out + residual (BN input)
__device__ float g_deg0[N_NODES], g_deg1[N_NODES];
__device__ int   g_count[N_NODES];       // in-degree counts
__device__ int   g_csroff[N_NODES + 1];  // CSR offsets (by destination)
__device__ int   g_cursor[N_NODES];      // fill cursors
__device__ int   g_bsum[NSCAN1], g_bsumx[NSCAN1];
__device__ int   g_csrsrc[N_EDGES];
__device__ float g_csrw0[N_EDGES], g_csrw1[N_EDGES];
__device__ float g_rws[2 * NET];
__device__ float g_sum[HID], g_sumsq[HID];
__device__ float g_bnscale[HID], g_bnshift[HID];
__device__ int   g_cnt[2];
__device__ int   g_list0[N_NODES], g_list1[N_NODES];

// bf16 hi/lo weight images, layout [tile][k=128][n=128] row-major
__device__ __nv_bfloat16 g_wI0h[16384], g_wI0l[16384];       // lin0_w
__device__ __nv_bfloat16 g_wI1h[16384], g_wI1l[16384];       // lin1_w
__device__ __nv_bfloat16 g_wC0h[16384], g_wC0l[16384];       // conv0_w
__device__ __nv_bfloat16 g_wC1h[3 * 16384], g_wC1l[3 * 16384];  // conv1_w (3 tiles)

// ---------------- mma.sync GEMM machinery ----------------------------------
#define ROWB 272                    // 136 bf16 padded row (conflict-free LDSM)
#define OFF_A_HI 0
#define OFF_A_LO 17408
#define OFF_B_HI 34816
#define OFF_B_LO 69632
#define SMEM_MMA 104448             // 102KB -> 2 CTAs/SM

__device__ __forceinline__ uint32_t smem_u32(const void* p) {
    uint32_t a;
    asm("{ .reg .u64 t; cvta.to.shared.u64 t, %1; cvt.u32.u64 %0, t; }"
        : "=r"(a) : "l"(p));
    return a;
}

__device__ __forceinline__ void ldsm4(uint32_t addr, uint32_t* r) {
    asm volatile("ldmatrix.sync.aligned.m8n8.x4.shared.b16 {%0,%1,%2,%3}, [%4];"
                 : "=r"(r[0]), "=r"(r[1]), "=r"(r[2]), "=r"(r[3]) : "r"(addr));
}
__device__ __forceinline__ void ldsm2t(uint32_t addr, uint32_t* r) {
    asm volatile("ldmatrix.sync.aligned.m8n8.x2.trans.shared.b16 {%0,%1}, [%2];"
                 : "=r"(r[0]), "=r"(r[1]) : "r"(addr));
}
__device__ __forceinline__ void mma16816(float* d, const uint32_t* a, const uint32_t* b) {
    asm volatile(
        "mma.sync.aligned.m16n8k16.row.col.f32.bf16.bf16.f32 "
        "{%0,%1,%2,%3}, {%4,%5,%6,%7}, {%8,%9}, {%0,%1,%2,%3};"
        : "+f"(d[0]), "+f"(d[1]), "+f"(d[2]), "+f"(d[3])
        : "r"(a[0]), "r"(a[1]), "r"(a[2]), "r"(a[3]), "r"(b[0]), "r"(b[1]));
}

// packed hi/lo split: two floats -> bf16x2 hi + bf16x2 lo
__device__ __forceinline__ void cvt_hilo(float f0, float f1,
                                         uint32_t& hi2, uint32_t& lo2) {
    asm("cvt.rn.bf16x2.f32 %0, %1, %2;" : "=r"(hi2) : "f"(f1), "f"(f0));
    float h0 = __uint_as_float(hi2 << 16);
    float h1 = __uint_as_float(hi2 & 0xffff0000u);
    float l0 = f0 - h0, l1 = f1 - h1;
    asm("cvt.rn.bf16x2.f32 %0, %1, %2;" : "=r"(lo2) : "f"(l1), "f"(l0));
}

// write 32 accumulated fp32 (one quarter-row) as bf16 hi/lo into A tiles
__device__ __forceinline__ void stage_write(char* smem, int row, int q,
                                            const float* a) {
    uint32_t off = (uint32_t)row * ROWB + q * 64;
#pragma unroll
    for (int g = 0; g < 4; g++) {
        uint32_t hp[4], lp[4];
#pragma unroll
        for (int i = 0; i < 4; i++)
            cvt_hilo(a[g * 8 + 2 * i], a[g * 8 + 2 * i + 1], hp[i], lp[i]);
        *reinterpret_cast<uint4*>(smem + OFF_A_HI + off + g * 16) =
            make_uint4(hp[0], hp[1], hp[2], hp[3]);
        *reinterpret_cast<uint4*>(smem + OFF_A_LO + off + g * 16) =
            make_uint4(lp[0], lp[1], lp[2], lp[3]);
    }
}

// stage 32 fp32 (quarter row) from a contiguous source row
__device__ __forceinline__ void stage_quarter(char* smem, int row, int q,
                                              const float* src) {
    float f[32];
    if (src) {
#pragma unroll
        for (int g = 0; g < 8; g++) {
            float4 v = ((const float4*)src)[g];
            f[g * 4 + 0] = v.x; f[g * 4 + 1] = v.y;
            f[g * 4 + 2] = v.z; f[g * 4 + 3] = v.w;
        }
    } else {
#pragma unroll
        for (int i = 0; i < 32; i++) f[i] = 0.f;
    }
    stage_write(smem, row, q, f);
}

// gather-aggregate a quarter row over incoming edges: sum w * src[csrsrc][q*32..]
__device__ __forceinline__ void stage_gather(char* smem, int row, int q, int gr,
                                             const float* srcbase,
                                             const float* warr) {
    float a[32];
#pragma unroll
    for (int i = 0; i < 32; i++) a[i] = 0.f;
    if (gr < N_NODES) {
        int s0 = g_csroff[gr], s1 = g_csroff[gr + 1];
        for (int e = s0; e < s1; e++) {
            int src = g_csrsrc[e];
            float w = warr[e];
            const float4* p = (const float4*)(srcbase + (size_t)src * HID + q * 32);
#pragma unroll
            for (int g = 0; g < 8; g++) {
                float4 v = __ldg(&p[g]);
                a[g * 4 + 0] += w * v.x; a[g * 4 + 1] += w * v.y;
                a[g * 4 + 2] += w * v.z; a[g * 4 + 3] += w * v.w;
            }
        }
    }
    stage_write(smem, row, q, a);
}

// gather with fused bn+prelu on the source values (layer 1)
__device__ __forceinline__ void stage_gather_bn(char* smem, int row, int q, int gr,
                                                float pa) {
    float a[32];
#pragma unroll
    for (int i = 0; i < 32; i++) a[i] = 0.f;
    if (gr < N_NODES) {
        float4 scv[8], shv[8];
#pragma unroll
        for (int g = 0; g < 8; g++) {
            scv[g] = ((const float4*)g_bnscale)[q * 8 + g];
            shv[g] = ((const float4*)g_bnshift)[q * 8 + g];
        }
        int s0 = g_csroff[gr], s1 = g_csroff[gr + 1];
        for (int e = s0; e < s1; e++) {
            int src = g_csrsrc[e];
            float w = g_csrw1[e];
            const float4* p = (const float4*)(g_x + (size_t)src * HID + q * 32);
#pragma unroll
            for (int g = 0; g < 8; g++) {
                float4 v = __ldg(&p[g]);
                float z0 = v.x * scv[g].x + shv[g].x;
                float z1 = v.y * scv[g].y + shv[g].y;
                float z2 = v.z * scv[g].z + shv[g].z;
                float z3 = v.w * scv[g].w + shv[g].w;
                z0 = (z0 >= 0.f) ? z0 : pa * z0;
                z1 = (z1 >= 0.f) ? z1 : pa * z1;
                z2 = (z2 >= 0.f) ? z2 : pa * z2;
                z3 = (z3 >= 0.f) ? z3 : pa * z3;
                a[g * 4 + 0] += w * z0; a[g * 4 + 1] += w * z1;
                a[g * 4 + 2] += w * z2; a[g * 4 + 3] += w * z3;
            }
        }
    }
    stage_write(smem, row, q, a);
}

// copy one pre-split B tile (hi/lo [k][n] images) into padded smem rows
__device__ __forceinline__ void stage_b(char* smem, const __nv_bfloat16* bh,
                                        const __nv_bfloat16* bl, int tid) {
    const uint4* h4 = (const uint4*)bh;
    const uint4* l4 = (const uint4*)bl;
    for (int i = tid; i < 2048; i += 256) {
        int k = i >> 4, s = i & 15;
        *(uint4*)(smem + OFF_B_HI + k * ROWB + s * 16) = h4[i];
        *(uint4*)(smem + OFF_B_LO + k * ROWB + s * 16) = l4[i];
    }
}

// core: 8 warps; warp (wm=w&1, wn=w>>1): rows wm*32..+31, cols wn*32..+31
__device__ __forceinline__ void mma_core(uint32_t sb, float acc[8][4]) {
    int lane = threadIdx.x & 31;
    int w = threadIdx.x >> 5;
    int wm = w & 1, wn = w >> 1;
    uint32_t aaddr[2], baddr[4];
#pragma unroll
    for (int mt = 0; mt < 2; mt++)
        aaddr[mt] = sb + OFF_A_HI +
                    (uint32_t)(wm * 32 + mt * 16 + (lane & 15)) * ROWB +
                    (lane >> 4) * 16;
#pragma unroll
    for (int nt = 0; nt < 4; nt++)
        baddr[nt] = sb + OFF_B_HI + (uint32_t)(lane & 15) * ROWB +
                    (wn * 32 + nt * 8) * 2;
#pragma unroll 2
    for (int ks = 0; ks < 8; ks++) {
        uint32_t bh[4][2], bl[4][2];
#pragma unroll
        for (int nt = 0; nt < 4; nt++) {
            uint32_t ba = baddr[nt] + ks * (16 * ROWB);
            ldsm2t(ba, bh[nt]);
            ldsm2t(ba + (OFF_B_LO - OFF_B_HI), bl[nt]);
        }
#pragma unroll
        for (int mt = 0; mt < 2; mt++) {
            uint32_t ah[4], al[4];
            uint32_t aa = aaddr[mt] + ks * 32;
            ldsm4(aa, ah);
            ldsm4(aa + (OFF_A_LO - OFF_A_HI), al);
#pragma unroll
            for (int nt = 0; nt < 4; nt++) {
                mma16816(acc[mt * 4 + nt], ah, bh[nt]);
                mma16816(acc[mt * 4 + nt], ah, bl[nt]);
                mma16816(acc[mt * 4 + nt], al, bh[nt]);
            }
        }
    }
}

// ---------------- prep ----------------------------------------------------
__global__ void k_init(const float* __restrict__ rw0, const float* __restrict__ rw1) {
    int i = blockIdx.x * blockDim.x + threadIdx.x;
    if (i < N_NODES) { g_deg0[i] = 0.0f; g_deg1[i] = 0.0f; g_count[i] = 0; }
    if (i < HID)     { g_sum[i] = 0.0f;  g_sumsq[i] = 0.0f; }
    if (i < 2)       { g_cnt[i] = 0; }
    if (i < NET) {
        float v = rw0[i] * 100.0f;
        g_rws[i] = (v >= 0.0f) ? v : 0.01f * v;
    } else if (i < 2 * NET) {
        float v = rw1[i - NET] * 100.0f;
        g_rws[i] = (v >= 0.0f) ? v : 0.01f * v;
    }
}

// warp-aggregated two-way partition
__global__ void k_partition(const int* __restrict__ ntype) {
    int n = blockIdx.x * blockDim.x + threadIdx.x;
    bool valid = n < N_NODES;
    int t = valid ? ntype[n] : -1;
    int lane = threadIdx.x & 31;
#pragma unroll
    for (int tt = 0; tt < 2; tt++) {
        unsigned m = __ballot_sync(0xffffffffu, t == tt);
        if (t == tt) {
            int leader = __ffs(m) - 1;
            int pos = 0;
            if (lane == leader) pos = atomicAdd(&g_cnt[tt], __popc(m));
            pos = __shfl_sync(m, pos, leader);
            pos += __popc(m & ((1u << lane) - 1u));
            if (tt == 0) g_list0[pos] = n; else g_list1[pos] = n;
        }
    }
}

__global__ void k_deg(const int* __restrict__ ei, const int* __restrict__ et) {
    int e = blockIdx.x * blockDim.x + threadIdx.x;
    if (e >= N_EDGES) return;
    int c = ei[N_EDGES + e];
    int t = et[e];
    atomicAdd(&g_deg0[c], g_rws[t]);
    atomicAdd(&g_deg1[c], g_rws[NET + t]);
    atomicAdd(&g_count[c], 1);
}

// exclusive scan over g_count -> g_csroff (3 phases)
__global__ __launch_bounds__(1024) void k_scan1() {
    __shared__ int s[1024];
    int tid = threadIdx.x;
    int i = blockIdx.x * 1024 + tid;
    int v = (i < N_NODES) ? g_count[i] : 0;
    s[tid] = v;
    __syncthreads();
#pragma unroll
    for (int d = 1; d < 1024; d <<= 1) {
        int t = (tid >= d) ? s[tid - d] : 0;
        __syncthreads();
        s[tid] += t;
        __syncthreads();
    }
    if (i < N_NODES) g_csroff[i] = s[tid] - v;
    if (tid == 1023) g_bsum[blockIdx.x] = s[1023];
}

__global__ __launch_bounds__(128) void k_scan2() {
    __shared__ int s[128];
    int tid = threadIdx.x;
    int v = (tid < NSCAN1) ? g_bsum[tid] : 0;
    s[tid] = v;
    __syncthreads();
#pragma unroll
    for (int d = 1; d < 128; d <<= 1) {
        int t = (tid >= d) ? s[tid - d] : 0;
        __syncthreads();
        s[tid] += t;
        __syncthreads();
    }
    if (tid < NSCAN1) g_bsumx[tid] = s[tid] - v;
}

__global__ void k_scan3() {
    int i = blockIdx.x * blockDim.x + threadIdx.x;
    if (i < N_NODES) {
        int o = g_csroff[i] + g_bsumx[i >> 10];
        g_csroff[i] = o;
        g_cursor[i] = o;
    }
    if (i == 0) g_csroff[N_NODES] = N_EDGES;
}

__global__ void k_fill(const int* __restrict__ ei, const int* __restrict__ et) {
    int e = blockIdx.x * blockDim.x + threadIdx.x;
    if (e >= N_EDGES) return;
    int r = ei[e];
    int c = ei[N_EDGES + e];
    int t = et[e];
    int pos = atomicAdd(&g_cursor[c], 1);
    g_csrsrc[pos] = r;
    g_csrw0[pos] = g_rws[t] / fabsf(g_deg0[c]);
    g_csrw1[pos] = g_rws[NET + t] / fabsf(g_deg1[c]);
}

// all weight hi/lo images in one launch (6 tile-images)
__global__ void k_prep_all(const float* __restrict__ lin0_w,
                           const float* __restrict__ lin1_w,
                           const float* __restrict__ conv0_w,
                           const float* __restrict__ conv1_w) {
    int idx = blockIdx.x * blockDim.x + threadIdx.x;
    if (idx >= 6 * 16384) return;
    int img = idx >> 14;
    int rem = idx & 16383;
    int k = rem >> 7, n = rem & 127;
    const float* W;
    int ncols, col, off;
    __nv_bfloat16 *hi, *lo;
    if (img == 0)      { W = lin0_w;  ncols = HID;  col = n; hi = g_wI0h; lo = g_wI0l; off = rem; }
    else if (img == 1) { W = lin1_w;  ncols = HID;  col = n; hi = g_wI1h; lo = g_wI1l; off = rem; }
    else if (img == 2) { W = conv0_w; ncols = HID;  col = n; hi = g_wC0h; lo = g_wC0l; off = rem; }
    else { int t = img - 3; W = conv1_w; ncols = OUTD; col = t * 128 + n;
           hi = g_wC1h; lo = g_wC1l; off = t * 16384 + rem; }
    float v = (col < ncols) ? W[(size_t)k * ncols + col] : 0.f;
    __nv_bfloat16 h = __float2bfloat16(v);
    hi[off] = h;
    lo[off] = __float2bfloat16(v - __bfloat162float(h));
}

// ---------------- mma GEMM kernels ----------------------------------------

// input linear (compacted rows of one type): h[n] = x_k[lidx[n]] @ W + b
__global__ __launch_bounds__(256, 2) void k_mma_input(
    const float* __restrict__ xk, const int* __restrict__ lidx,
    const float* __restrict__ b, int pass) {
    const int cnt = g_cnt[pass];
    const int m0 = blockIdx.x * MTILE;
    if (m0 >= cnt) return;
    const int* list = pass ? g_list1 : g_list0;
    extern __shared__ char smem[];
    int tid = threadIdx.x;

    stage_b(smem, pass ? g_wI1h : g_wI0h, pass ? g_wI1l : g_wI0l, tid);
    {
        int row = tid >> 2, q = tid & 3;
        int lr = m0 + row;
        const float* src = nullptr;
        if (lr < cnt) src = xk + (size_t)lidx[list[lr]] * HID + q * 32;
        stage_quarter(smem, row, q, src);
    }
    __syncthreads();

    float acc[8][4] = {};
    mma_core(smem_u32(smem), acc);

    int lane = tid & 31, w = tid >> 5, wm = w & 1, wn = w >> 1;
#pragma unroll
    for (int mt = 0; mt < 2; mt++)
#pragma unroll
        for (int half = 0; half < 2; half++) {
            int lr = m0 + wm * 32 + mt * 16 + (lane >> 2) + half * 8;
            if (lr >= cnt) continue;
            float* dst = g_h + (size_t)list[lr] * HID;
#pragma unroll
            for (int nt = 0; nt < 4; nt++) {
                int c = wn * 32 + nt * 8 + (lane & 3) * 2;
                float2 bb = *(const float2*)(b + c);
                float2 o = {acc[mt * 4 + nt][half * 2 + 0] + bb.x,
                            acc[mt * 4 + nt][half * 2 + 1] + bb.y};
                *(float2*)(dst + c) = o;
            }
        }
}

// g_x = gather(h) @ conv0_w + b + g_h ; BN stats fused in epilogue
__global__ __launch_bounds__(256, 2) void k_mma_gemm0(const float* __restrict__ b) {
    const int m0 = blockIdx.x * MTILE;
    extern __shared__ char smem[];
    int tid = threadIdx.x;

    stage_b(smem, g_wC0h, g_wC0l, tid);
    stage_gather(smem, tid >> 2, tid & 3, m0 + (tid >> 2), g_h, g_csrw0);
    __syncthreads();

    float acc[8][4] = {};
    mma_core(smem_u32(smem), acc);

    int lane = tid & 31, w = tid >> 5, wm = w & 1, wn = w >> 1;
    float s[4][2] = {}, s2[4][2] = {};
#pragma unroll
    for (int mt = 0; mt < 2; mt++)
#pragma unroll
        for (int half = 0; half < 2; half++) {
            int gr = m0 + wm * 32 + mt * 16 + (lane >> 2) + half * 8;
            if (gr >= N_NODES) continue;
            float* dst = g_x + (size_t)gr * HID;
            const float* hres = g_h + (size_t)gr * HID;
#pragma unroll
            for (int nt = 0; nt < 4; nt++) {
                int c = wn * 32 + nt * 8 + (lane & 3) * 2;
                float2 bb = *(const float2*)(b + c);
                float2 hv = *(const float2*)(hres + c);
                float2 o = {acc[mt * 4 + nt][half * 2 + 0] + bb.x + hv.x,
                            acc[mt * 4 + nt][half * 2 + 1] + bb.y + hv.y};
                *(float2*)(dst + c) = o;
                s[nt][0] += o.x;  s2[nt][0] += o.x * o.x;
                s[nt][1] += o.y;  s2[nt][1] += o.y * o.y;
            }
        }
#pragma unroll
    for (int d = 4; d < 32; d <<= 1)
#pragma unroll
        for (int nt = 0; nt < 4; nt++) {
            s[nt][0]  += __shfl_xor_sync(0xffffffffu, s[nt][0],  d);
            s[nt][1]  += __shfl_xor_sync(0xffffffffu, s[nt][1],  d);
            s2[nt][0] += __shfl_xor_sync(0xffffffffu, s2[nt][0], d);
            s2[nt][1] += __shfl_xor_sync(0xffffffffu, s2[nt][1], d);
        }
    if ((lane >> 2) == 0) {
#pragma unroll
        for (int nt = 0; nt < 4; nt++) {
            int c = wn * 32 + nt * 8 + (lane & 3) * 2;
            atomicAdd(&g_sum[c],       s[nt][0]);
            atomicAdd(&g_sum[c + 1],   s[nt][1]);
            atomicAdd(&g_sumsq[c],     s2[nt][0]);
            atomicAdd(&g_sumsq[c + 1], s2[nt][1]);
        }
    }
}

// out = gather(prelu(bn(x))) @ conv1_w + b : A staged once, 3 N-tiles in-kernel
__global__ __launch_bounds__(256, 2) void k_mma_gemm1(const float* __restrict__ b,
                                                      const float* __restrict__ prelu_a,
                                                      float* __restrict__ out) {
    const int m0 = blockIdx.x * MTILE;
    extern __shared__ char smem[];
    int tid = threadIdx.x;

    stage_gather_bn(smem, tid >> 2, tid & 3, m0 + (tid >> 2), __ldg(prelu_a));

    int lane = tid & 31, w = tid >> 5, wm = w & 1, wn = w >> 1;

    for (int ny = 0; ny < 3; ny++) {
        if (ny) __syncthreads();  // prior mma reads of B done
        stage_b(smem, g_wC1h + (size_t)ny * 16384, g_wC1l + (size_t)ny * 16384, tid);
        __syncthreads();

        float acc[8][4] = {};
        mma_core(smem_u32(smem), acc);

        int n0 = ny * 128;
#pragma unroll
        for (int mt = 0; mt < 2; mt++)
#pragma unroll
            for (int half = 0; half < 2; half++) {
                int gr = m0 + wm * 32 + mt * 16 + (lane >> 2) + half * 8;
                if (gr >= N_NODES) continue;
                float* dst = out + (size_t)gr * OUTD;
#pragma unroll
                for (int nt = 0; nt < 4; nt++) {
                    int c = n0 + wn * 32 + nt * 8 + (lane & 3) * 2;
                    if (c < OUTD)
                        dst[c] = acc[mt * 4 + nt][half * 2 + 0] + b[c];
                    if (c + 1 < OUTD)
                        dst[c + 1] = acc[mt * 4 + nt][half * 2 + 1] + b[c + 1];
                }
            }
    }
}

// ---------------- BN finalize ----------------------------------------------
__global__ void k_bnfinal(const float* __restrict__ gamma,
                          const float* __restrict__ beta) {
    int j = threadIdx.x;
    if (j >= HID) return;
    float mean = g_sum[j] / (float)N_NODES;
    float var = g_sumsq[j] / (float)N_NODES - mean * mean;
    float sc = gamma[j] * rsqrtf(var + BN_EPS);
    g_bnscale[j] = sc;
    g_bnshift[j] = beta[j] - mean * sc;
}

// ---------------- log_softmax (in place on d_out) --------------------------
__global__ __launch_bounds__(128) void k_logsoftmax(float* __restrict__ out) {
    int n = blockIdx.x;
    float* row = out + (size_t)n * OUTD;
    int j = threadIdx.x;
    float v0 = row[j];
    float v1 = (j + 128 < OUTD) ? row[j + 128] : -1e30f;
    float v2 = (j + 256 < OUTD) ? row[j + 256] : -1e30f;
    __shared__ float red[128];
    float m = fmaxf(v0, fmaxf(v1, v2));
    red[j] = m;
    __syncthreads();
#pragma unroll
    for (int s = 64; s > 0; s >>= 1) {
        if (j < s) red[j] = fmaxf(red[j], red[j + s]);
        __syncthreads();
    }
    float mx = red[0];
    __syncthreads();
    float e = expf(v0 - mx);
    if (j + 128 < OUTD) e += expf(v1 - mx);
    if (j + 256 < OUTD) e += expf(v2 - mx);
    red[j] = e;
    __syncthreads();
#pragma unroll
    for (int s = 64; s > 0; s >>= 1) {
        if (j < s) red[j] += red[j + s];
        __syncthreads();
    }
    float lse = logf(red[0]) + mx;
    row[j] = v0 - lse;
    if (j + 128 < OUTD) row[j + 128] = v1 - lse;
    if (j + 256 < OUTD) row[j + 256] = v2 - lse;
}

// ---------------- launch ---------------------------------------------------
extern "C" void kernel_launch(void* const* d_in, const int* in_sizes, int n_in,
                              void* d_out, int out_size) {
    const float* x0 = (const float*)d_in[0];
    const float* x1 = (const float*)d_in[1];
    const int* edge_index = (const int*)d_in[2];
    const int* edge_type = (const int*)d_in[3];
    const int* node_type = (const int*)d_in[4];
    const int* lidx = (const int*)d_in[5];
    const float* lin0_w = (const float*)d_in[6];
    const float* lin0_b = (const float*)d_in[7];
    const float* lin1_w = (const float*)d_in[8];
    const float* lin1_b = (const float*)d_in[9];
    const float* conv0_w = (const float*)d_in[10];
    const float* conv0_b = (const float*)d_in[11];
    const float* conv0_rw = (const float*)d_in[12];
    const float* conv1_w = (const float*)d_in[13];
    const float* conv1_b = (const float*)d_in[14];
    const float* conv1_rw = (const float*)d_in[15];
    const float* bn_g = (const float*)d_in[16];
    const float* bn_b = (const float*)d_in[17];
    const float* prelu_a = (const float*)d_in[18];
    float* out = (float*)d_out;

    cudaFuncSetAttribute(k_mma_input, cudaFuncAttributeMaxDynamicSharedMemorySize, SMEM_MMA);
    cudaFuncSetAttribute(k_mma_gemm0, cudaFuncAttributeMaxDynamicSharedMemorySize, SMEM_MMA);
    cudaFuncSetAttribute(k_mma_gemm1, cudaFuncAttributeMaxDynamicSharedMemorySize, SMEM_MMA);

    k_init<<<(N_NODES + 255) / 256, 256>>>(conv0_rw, conv1_rw);
    k_partition<<<(N_NODES + 255) / 256, 256>>>(node_type);
    k_deg<<<(N_EDGES + 255) / 256, 256>>>(edge_index, edge_type);
    k_scan1<<<NSCAN1, 1024>>>();
    k_scan2<<<1, 128>>>();
    k_scan3<<<(N_NODES + 255) / 256, 256>>>();
    k_fill<<<(N_EDGES + 255) / 256, 256>>>(edge_index, edge_type);
    k_prep_all<<<384, 256>>>(lin0_w, lin1_w, conv0_w, conv1_w);

    // input linears (compacted by node type)
    k_mma_input<<<NTILES_M, 256, SMEM_MMA>>>(x0, lidx, lin0_b, 0);
    k_mma_input<<<NTILES_M, 256, SMEM_MMA>>>(x1, lidx, lin1_b, 1);

    // layer 0: gather fused into GEMM staging; BN stats fused in epilogue
    k_mma_gemm0<<<NTILES_M, 256, SMEM_MMA>>>(conv0_b);
    k_bnfinal<<<1, 128>>>(bn_g, bn_b);

    // layer 1: gather + BN + PReLU fused into GEMM staging
    k_mma_gemm1<<<NTILES_M, 256, SMEM_MMA>>>(conv1_b, prelu_a, out);

    k_logsoftmax<<<N_NODES, 128>>>(out);
}

// round 11
// speedup vs baseline: 2.5353x; 1.0108x over previous
#include <cuda_runtime.h>
#include <cuda_fp16.h>
#include <cstdint>

#define N_NODES 100000
#define N_EDGES 500000
#define HID 128
#define OUTD 349
#define NET 8
#define BN_EPS 1e-5f
#define MTILE 64
#define NTILES_M ((N_NODES + MTILE - 1) / MTILE)  // 1563
#define NSCAN1 ((N_NODES + 1023) / 1024)          // 98

// ---------------- scratch (static device globals; no allocation) ----------
__device__ float g_h[N_NODES * HID];     // input-linear output; later y = prelu(bn(x))
__device__ float g_x[N_NODES * HID];     // conv0 out + residual (BN input)
__device__ float g_deg0[N_NODES], g_deg1[N_NODES];
__device__ int   g_count[N_NODES];
__device__ int   g_csroff[N_NODES + 1];
__device__ int   g_cursor[N_NODES];
__device__ int   g_bsum[NSCAN1], g_bsumx[NSCAN1];
__device__ int   g_csrsrc[N_EDGES];
__device__ float g_csrw0[N_EDGES], g_csrw1[N_EDGES];
__device__ float g_rws[2 * NET];
__device__ float g_sum[HID], g_sumsq[HID];
__device__ float g_bnscale[HID], g_bnshift[HID];
__device__ int   g_cnt[2];
__device__ int   g_list0[N_NODES], g_list1[N_NODES];

// fp16 hi/lo weight images, layout [tile][k=128][n=128] row-major
__device__ __half g_wI0h[16384], g_wI0l[16384];       // lin0_w
__device__ __half g_wI1h[16384], g_wI1l[16384];       // lin1_w
__device__ __half g_wC0h[16384], g_wC0l[16384];       // conv0_w
__device__ __half g_wC1h[3 * 16384], g_wC1l[3 * 16384];  // conv1_w (3 tiles)

// ---------------- mma.sync GEMM machinery ----------------------------------
// A in fp16 (truncated), W split hi+lo fp16 -> 2 mma terms.
#define ROWB 272                    // 136 fp16 padded row (conflict-free LDSM)
#define OFF_A    0                  // 64 x 272 = 17408
#define OFF_B_HI 17408              // 128 x 272 = 34816
#define OFF_B_LO 52224
#define SMEM_MMA 87040              // 85KB -> 2 CTAs/SM

__device__ __forceinline__ uint32_t smem_u32(const void* p) {
    uint32_t a;
    asm("{ .reg .u64 t; cvta.to.shared.u64 t, %1; cvt.u32.u64 %0, t; }"
        : "=r"(a) : "l"(p));
    return a;
}

__device__ __forceinline__ void ldsm4(uint32_t addr, uint32_t* r) {
    asm volatile("ldmatrix.sync.aligned.m8n8.x4.shared.b16 {%0,%1,%2,%3}, [%4];"
                 : "=r"(r[0]), "=r"(r[1]), "=r"(r[2]), "=r"(r[3]) : "r"(addr));
}
__device__ __forceinline__ void ldsm2t(uint32_t addr, uint32_t* r) {
    asm volatile("ldmatrix.sync.aligned.m8n8.x2.trans.shared.b16 {%0,%1}, [%2];"
                 : "=r"(r[0]), "=r"(r[1]) : "r"(addr));
}
__device__ __forceinline__ void mma16816(float* d, const uint32_t* a, const uint32_t* b) {
    asm volatile(
        "mma.sync.aligned.m16n8k16.row.col.f32.f16.f16.f32 "
        "{%0,%1,%2,%3}, {%4,%5,%6,%7}, {%8,%9}, {%0,%1,%2,%3};"
        : "+f"(d[0]), "+f"(d[1]), "+f"(d[2]), "+f"(d[3])
        : "r"(a[0]), "r"(a[1]), "r"(a[2]), "r"(a[3]), "r"(b[0]), "r"(b[1]));
}

// write 32 fp32 (one quarter-row) as packed fp16 into the A tile
__device__ __forceinline__ void stage_write(char* smem, int row, int q,
                                            const float* a) {
    uint32_t off = (uint32_t)row * ROWB + q * 64;
#pragma unroll
    for (int g = 0; g < 4; g++) {
        uint32_t p[4];
#pragma unroll
        for (int i = 0; i < 4; i++)
            asm("cvt.rn.f16x2.f32 %0, %1, %2;"
                : "=r"(p[i]) : "f"(a[g * 8 + 2 * i + 1]), "f"(a[g * 8 + 2 * i]));
        *reinterpret_cast<uint4*>(smem + OFF_A + off + g * 16) =
            make_uint4(p[0], p[1], p[2], p[3]);
    }
}

// stage 32 fp32 (quarter row) from a contiguous source row
__device__ __forceinline__ void stage_quarter(char* smem, int row, int q,
                                              const float* src) {
    float f[32];
    if (src) {
#pragma unroll
        for (int g = 0; g < 8; g++) {
            float4 v = ((const float4*)src)[g];
            f[g * 4 + 0] = v.x; f[g * 4 + 1] = v.y;
            f[g * 4 + 2] = v.z; f[g * 4 + 3] = v.w;
        }
    } else {
#pragma unroll
        for (int i = 0; i < 32; i++) f[i] = 0.f;
    }
    stage_write(smem, row, q, f);
}

// gather-aggregate a quarter row over incoming edges: sum w * src[csrsrc][q*32..]
__device__ __forceinline__ void stage_gather(char* smem, int row, int q, int gr,
                                             const float* srcbase,
                                             const float* warr) {
    float a[32];
#pragma unroll
    for (int i = 0; i < 32; i++) a[i] = 0.f;
    if (gr < N_NODES) {
        int s0 = g_csroff[gr], s1 = g_csroff[gr + 1];
        for (int e = s0; e < s1; e++) {
            int src = g_csrsrc[e];
            float w = warr[e];
            const float4* p = (const float4*)(srcbase + (size_t)src * HID + q * 32);
#pragma unroll
            for (int g = 0; g < 8; g++) {
                float4 v = __ldg(&p[g]);
                a[g * 4 + 0] += w * v.x; a[g * 4 + 1] += w * v.y;
                a[g * 4 + 2] += w * v.z; a[g * 4 + 3] += w * v.w;
            }
        }
    }
    stage_write(smem, row, q, a);
}

// copy one pre-split B tile (hi/lo [k][n] images) into padded smem rows
__device__ __forceinline__ void stage_b(char* smem, const __half* bh,
                                        const __half* bl, int tid) {
    const uint4* h4 = (const uint4*)bh;
    const uint4* l4 = (const uint4*)bl;
    for (int i = tid; i < 2048; i += 256) {
        int k = i >> 4, s = i & 15;
        *(uint4*)(smem + OFF_B_HI + k * ROWB + s * 16) = h4[i];
        *(uint4*)(smem + OFF_B_LO + k * ROWB + s * 16) = l4[i];
    }
}

// core: 8 warps; warp (wm=w&1, wn=w>>1): rows wm*32..+31, cols wn*32..+31
__device__ __forceinline__ void mma_core(uint32_t sb, float acc[8][4]) {
    int lane = threadIdx.x & 31;
    int w = threadIdx.x >> 5;
    int wm = w & 1, wn = w >> 1;
    uint32_t aaddr[2], baddr[4];
#pragma unroll
    for (int mt = 0; mt < 2; mt++)
        aaddr[mt] = sb + OFF_A +
                    (uint32_t)(wm * 32 + mt * 16 + (lane & 15)) * ROWB +
                    (lane >> 4) * 16;
#pragma unroll
    for (int nt = 0; nt < 4; nt++)
        baddr[nt] = sb + OFF_B_HI + (uint32_t)(lane & 15) * ROWB +
                    (wn * 32 + nt * 8) * 2;
#pragma unroll
    for (int ks = 0; ks < 8; ks++) {
        uint32_t bh[4][2], bl[4][2];
#pragma unroll
        for (int nt = 0; nt < 4; nt++) {
            uint32_t ba = baddr[nt] + ks * (16 * ROWB);
            ldsm2t(ba, bh[nt]);
            ldsm2t(ba + (OFF_B_LO - OFF_B_HI), bl[nt]);
        }
#pragma unroll
        for (int mt = 0; mt < 2; mt++) {
            uint32_t ah[4];
            ldsm4(aaddr[mt] + ks * 32, ah);
#pragma unroll
            for (int nt = 0; nt < 4; nt++) {
                mma16816(acc[mt * 4 + nt], ah, bh[nt]);
                mma16816(acc[mt * 4 + nt], ah, bl[nt]);
            }
        }
    }
}

// ---------------- prep ----------------------------------------------------
__global__ void k_init(const float* __restrict__ rw0, const float* __restrict__ rw1) {
    int i = blockIdx.x * blockDim.x + threadIdx.x;
    if (i < N_NODES) { g_deg0[i] = 0.0f; g_deg1[i] = 0.0f; g_count[i] = 0; }
    if (i < HID)     { g_sum[i] = 0.0f;  g_sumsq[i] = 0.0f; }
    if (i < 2)       { g_cnt[i] = 0; }
    if (i < NET) {
        float v = rw0[i] * 100.0f;
        g_rws[i] = (v >= 0.0f) ? v : 0.01f * v;
    } else if (i < 2 * NET) {
        float v = rw1[i - NET] * 100.0f;
        g_rws[i] = (v >= 0.0f) ? v : 0.01f * v;
    }
}

// warp-aggregated two-way partition
__global__ void k_partition(const int* __restrict__ ntype) {
    int n = blockIdx.x * blockDim.x + threadIdx.x;
    bool valid = n < N_NODES;
    int t = valid ? ntype[n] : -1;
    int lane = threadIdx.x & 31;
#pragma unroll
    for (int tt = 0; tt < 2; tt++) {
        unsigned m = __ballot_sync(0xffffffffu, t == tt);
        if (t == tt) {
            int leader = __ffs(m) - 1;
            int pos = 0;
            if (lane == leader) pos = atomicAdd(&g_cnt[tt], __popc(m));
            pos = __shfl_sync(m, pos, leader);
            pos += __popc(m & ((1u << lane) - 1u));
            if (tt == 0) g_list0[pos] = n; else g_list1[pos] = n;
        }
    }
}

__global__ void k_deg(const int* __restrict__ ei, const int* __restrict__ et) {
    int e = blockIdx.x * blockDim.x + threadIdx.x;
    if (e >= N_EDGES) return;
    int c = ei[N_EDGES + e];
    int t = et[e];
    atomicAdd(&g_deg0[c], g_rws[t]);
    atomicAdd(&g_deg1[c], g_rws[NET + t]);
    atomicAdd(&g_count[c], 1);
}

// exclusive scan over g_count -> g_csroff (3 phases)
__global__ __launch_bounds__(1024) void k_scan1() {
    __shared__ int s[1024];
    int tid = threadIdx.x;
    int i = blockIdx.x * 1024 + tid;
    int v = (i < N_NODES) ? g_count[i] : 0;
    s[tid] = v;
    __syncthreads();
#pragma unroll
    for (int d = 1; d < 1024; d <<= 1) {
        int t = (tid >= d) ? s[tid - d] : 0;
        __syncthreads();
        s[tid] += t;
        __syncthreads();
    }
    if (i < N_NODES) g_csroff[i] = s[tid] - v;
    if (tid == 1023) g_bsum[blockIdx.x] = s[1023];
}

__global__ __launch_bounds__(128) void k_scan2() {
    __shared__ int s[128];
    int tid = threadIdx.x;
    int v = (tid < NSCAN1) ? g_bsum[tid] : 0;
    s[tid] = v;
    __syncthreads();
#pragma unroll
    for (int d = 1; d < 128; d <<= 1) {
        int t = (tid >= d) ? s[tid - d] : 0;
        __syncthreads();
        s[tid] += t;
        __syncthreads();
    }
    if (tid < NSCAN1) g_bsumx[tid] = s[tid] - v;
}

__global__ void k_scan3() {
    int i = blockIdx.x * blockDim.x + threadIdx.x;
    if (i < N_NODES) {
        int o = g_csroff[i] + g_bsumx[i >> 10];
        g_csroff[i] = o;
        g_cursor[i] = o;
    }
    if (i == 0) g_csroff[N_NODES] = N_EDGES;
}

__global__ void k_fill(const int* __restrict__ ei, const int* __restrict__ et) {
    int e = blockIdx.x * blockDim.x + threadIdx.x;
    if (e >= N_EDGES) return;
    int r = ei[e];
    int c = ei[N_EDGES + e];
    int t = et[e];
    int pos = atomicAdd(&g_cursor[c], 1);
    g_csrsrc[pos] = r;
    g_csrw0[pos] = g_rws[t] / fabsf(g_deg0[c]);
    g_csrw1[pos] = g_rws[NET + t] / fabsf(g_deg1[c]);
}

// all weight hi/lo images in one launch (6 tile-images), fp16 split
__global__ void k_prep_all(const float* __restrict__ lin0_w,
                           const float* __restrict__ lin1_w,
                           const float* __restrict__ conv0_w,
                           const float* __restrict__ conv1_w) {
    int idx = blockIdx.x * blockDim.x + threadIdx.x;
    if (idx >= 6 * 16384) return;
    int img = idx >> 14;
    int rem = idx & 16383;
    int k = rem >> 7, n = rem & 127;
    const float* W;
    int ncols, col, off;
    __half *hi, *lo;
    if (img == 0)      { W = lin0_w;  ncols = HID;  col = n; hi = g_wI0h; lo = g_wI0l; off = rem; }
    else if (img == 1) { W = lin1_w;  ncols = HID;  col = n; hi = g_wI1h; lo = g_wI1l; off = rem; }
    else if (img == 2) { W = conv0_w; ncols = HID;  col = n; hi = g_wC0h; lo = g_wC0l; off = rem; }
    else { int t = img - 3; W = conv1_w; ncols = OUTD; col = t * 128 + n;
           hi = g_wC1h; lo = g_wC1l; off = t * 16384 + rem; }
    float v = (col < ncols) ? W[(size_t)k * ncols + col] : 0.f;
    __half h = __float2half_rn(v);
    hi[off] = h;
    lo[off] = __float2half_rn(v - __half2float(h));
}

// ---------------- mma GEMM kernels ----------------------------------------

// input linear (compacted rows of one type): h[n] = x_k[lidx[n]] @ W + b
__global__ __launch_bounds__(256, 2) void k_mma_input(
    const float* __restrict__ xk, const int* __restrict__ lidx,
    const float* __restrict__ b, int pass) {
    const int cnt = g_cnt[pass];
    const int m0 = blockIdx.x * MTILE;
    if (m0 >= cnt) return;
    const int* list = pass ? g_list1 : g_list0;
    extern __shared__ char smem[];
    int tid = threadIdx.x;

    stage_b(smem, pass ? g_wI1h : g_wI0h, pass ? g_wI1l : g_wI0l, tid);
    {
        int row = tid >> 2, q = tid & 3;
        int lr = m0 + row;
        const float* src = nullptr;
        if (lr < cnt) src = xk + (size_t)lidx[list[lr]] * HID + q * 32;
        stage_quarter(smem, row, q, src);
    }
    __syncthreads();

    float acc[8][4] = {};
    mma_core(smem_u32(smem), acc);

    int lane = tid & 31, w = tid >> 5, wm = w & 1, wn = w >> 1;
#pragma unroll
    for (int mt = 0; mt < 2; mt++)
#pragma unroll
        for (int half = 0; half < 2; half++) {
            int lr = m0 + wm * 32 + mt * 16 + (lane >> 2) + half * 8;
            if (lr >= cnt) continue;
            float* dst = g_h + (size_t)list[lr] * HID;
#pragma unroll
            for (int nt = 0; nt < 4; nt++) {
                int c = wn * 32 + nt * 8 + (lane & 3) * 2;
                float2 bb = *(const float2*)(b + c);
                float2 o = {acc[mt * 4 + nt][half * 2 + 0] + bb.x,
                            acc[mt * 4 + nt][half * 2 + 1] + bb.y};
                *(float2*)(dst + c) = o;
            }
        }
}

// g_x = gather(h) @ conv0_w + b + g_h ; BN stats fused in epilogue
__global__ __launch_bounds__(256, 2) void k_mma_gemm0(const float* __restrict__ b) {
    const int m0 = blockIdx.x * MTILE;
    extern __shared__ char smem[];
    int tid = threadIdx.x;

    stage_b(smem, g_wC0h, g_wC0l, tid);
    stage_gather(smem, tid >> 2, tid & 3, m0 + (tid >> 2), g_h, g_csrw0);
    __syncthreads();

    float acc[8][4] = {};
    mma_core(smem_u32(smem), acc);

    int lane = tid & 31, w = tid >> 5, wm = w & 1, wn = w >> 1;
    float s[4][2] = {}, s2[4][2] = {};
#pragma unroll
    for (int mt = 0; mt < 2; mt++)
#pragma unroll
        for (int half = 0; half < 2; half++) {
            int gr = m0 + wm * 32 + mt * 16 + (lane >> 2) + half * 8;
            if (gr >= N_NODES) continue;
            float* dst = g_x + (size_t)gr * HID;
            const float* hres = g_h + (size_t)gr * HID;
#pragma unroll
            for (int nt = 0; nt < 4; nt++) {
                int c = wn * 32 + nt * 8 + (lane & 3) * 2;
                float2 bb = *(const float2*)(b + c);
                float2 hv = *(const float2*)(hres + c);
                float2 o = {acc[mt * 4 + nt][half * 2 + 0] + bb.x + hv.x,
                            acc[mt * 4 + nt][half * 2 + 1] + bb.y + hv.y};
                *(float2*)(dst + c) = o;
                s[nt][0] += o.x;  s2[nt][0] += o.x * o.x;
                s[nt][1] += o.y;  s2[nt][1] += o.y * o.y;
            }
        }
#pragma unroll
    for (int d = 4; d < 32; d <<= 1)
#pragma unroll
        for (int nt = 0; nt < 4; nt++) {
            s[nt][0]  += __shfl_xor_sync(0xffffffffu, s[nt][0],  d);
            s[nt][1]  += __shfl_xor_sync(0xffffffffu, s[nt][1],  d);
            s2[nt][0] += __shfl_xor_sync(0xffffffffu, s2[nt][0], d);
            s2[nt][1] += __shfl_xor_sync(0xffffffffu, s2[nt][1], d);
        }
    if ((lane >> 2) == 0) {
#pragma unroll
        for (int nt = 0; nt < 4; nt++) {
            int c = wn * 32 + nt * 8 + (lane & 3) * 2;
            atomicAdd(&g_sum[c],       s[nt][0]);
            atomicAdd(&g_sum[c + 1],   s[nt][1]);
            atomicAdd(&g_sumsq[c],     s2[nt][0]);
            atomicAdd(&g_sumsq[c + 1], s2[nt][1]);
        }
    }
}

// out = gather(y) @ conv1_w + b : A staged once, 3 N-tiles in-kernel
__global__ __launch_bounds__(256, 2) void k_mma_gemm1(const float* __restrict__ b,
                                                      float* __restrict__ out) {
    const int m0 = blockIdx.x * MTILE;
    extern __shared__ char smem[];
    int tid = threadIdx.x;

    stage_gather(smem, tid >> 2, tid & 3, m0 + (tid >> 2), g_h, g_csrw1);

    int lane = tid & 31, w = tid >> 5, wm = w & 1, wn = w >> 1;

    for (int ny = 0; ny < 3; ny++) {
        if (ny) __syncthreads();  // prior mma reads of B done
        stage_b(smem, g_wC1h + (size_t)ny * 16384, g_wC1l + (size_t)ny * 16384, tid);
        __syncthreads();

        float acc[8][4] = {};
        mma_core(smem_u32(smem), acc);

        int n0 = ny * 128;
#pragma unroll
        for (int mt = 0; mt < 2; mt++)
#pragma unroll
            for (int half = 0; half < 2; half++) {
                int gr = m0 + wm * 32 + mt * 16 + (lane >> 2) + half * 8;
                if (gr >= N_NODES) continue;
                float* dst = out + (size_t)gr * OUTD;
#pragma unroll
                for (int nt = 0; nt < 4; nt++) {
                    int c = n0 + wn * 32 + nt * 8 + (lane & 3) * 2;
                    if (c < OUTD)
                        dst[c] = acc[mt * 4 + nt][half * 2 + 0] + b[c];
                    if (c + 1 < OUTD)
                        dst[c + 1] = acc[mt * 4 + nt][half * 2 + 1] + b[c + 1];
                }
            }
    }
}

// ---------------- BN ------------------------------------------------------
__global__ void k_bnfinal(const float* __restrict__ gamma,
                          const float* __restrict__ beta) {
    int j = threadIdx.x;
    if (j >= HID) return;
    float mean = g_sum[j] / (float)N_NODES;
    float var = g_sumsq[j] / (float)N_NODES - mean * mean;
    float sc = gamma[j] * rsqrtf(var + BN_EPS);
    g_bnscale[j] = sc;
    g_bnshift[j] = beta[j] - mean * sc;
}

// y = prelu(bn(x)) -> overwrite g_h (h is dead after gemm0's residual read)
__global__ void k_bnapply(const float* __restrict__ prelu_a) {
    const float a = __ldg(prelu_a);
    const int total = N_NODES * HID / 4;
    for (int i = blockIdx.x * blockDim.x + threadIdx.x; i < total;
         i += gridDim.x * blockDim.x) {
        int kk = i & 31;
        float4 x = ((const float4*)g_x)[i];
        float4 sc = ((const float4*)g_bnscale)[kk];
        float4 sh = ((const float4*)g_bnshift)[kk];
        float4 v;
        v.x = x.x * sc.x + sh.x;
        v.y = x.y * sc.y + sh.y;
        v.z = x.z * sc.z + sh.z;
        v.w = x.w * sc.w + sh.w;
        v.x = (v.x >= 0.f) ? v.x : a * v.x;
        v.y = (v.y >= 0.f) ? v.y : a * v.y;
        v.z = (v.z >= 0.f) ? v.z : a * v.z;
        v.w = (v.w >= 0.f) ? v.w : a * v.w;
        ((float4*)g_h)[i] = v;
    }
}

// ---------------- log_softmax (in place on d_out) --------------------------
__global__ __launch_bounds__(128) void k_logsoftmax(float* __restrict__ out) {
    int n = blockIdx.x;
    float* row = out + (size_t)n * OUTD;
    int j = threadIdx.x;
    float v0 = row[j];
    float v1 = (j + 128 < OUTD) ? row[j + 128] : -1e30f;
    float v2 = (j + 256 < OUTD) ? row[j + 256] : -1e30f;
    __shared__ float red[128];
    float m = fmaxf(v0, fmaxf(v1, v2));
    red[j] = m;
    __syncthreads();
#pragma unroll
    for (int s = 64; s > 0; s >>= 1) {
        if (j < s) red[j] = fmaxf(red[j], red[j + s]);
        __syncthreads();
    }
    float mx = red[0];
    __syncthreads();
    float e = expf(v0 - mx);
    if (j + 128 < OUTD) e += expf(v1 - mx);
    if (j + 256 < OUTD) e += expf(v2 - mx);
    red[j] = e;
    __syncthreads();
#pragma unroll
    for (int s = 64; s > 0; s >>= 1) {
        if (j < s) red[j] += red[j + s];
        __syncthreads();
    }
    float lse = logf(red[0]) + mx;
    row[j] = v0 - lse;
    if (j + 128 < OUTD) row[j + 128] = v1 - lse;
    if (j + 256 < OUTD) row[j + 256] = v2 - lse;
}

// ---------------- launch ---------------------------------------------------
extern "C" void kernel_launch(void* const* d_in, const int* in_sizes, int n_in,
                              void* d_out, int out_size) {
    const float* x0 = (const float*)d_in[0];
    const float* x1 = (const float*)d_in[1];
    const int* edge_index = (const int*)d_in[2];
    const int* edge_type = (const int*)d_in[3];
    const int* node_type = (const int*)d_in[4];
    const int* lidx = (const int*)d_in[5];
    const float* lin0_w = (const float*)d_in[6];
    const float* lin0_b = (const float*)d_in[7];
    const float* lin1_w = (const float*)d_in[8];
    const float* lin1_b = (const float*)d_in[9];
    const float* conv0_w = (const float*)d_in[10];
    const float* conv0_b = (const float*)d_in[11];
    const float* conv0_rw = (const float*)d_in[12];
    const float* conv1_w = (const float*)d_in[13];
    const float* conv1_b = (const float*)d_in[14];
    const float* conv1_rw = (const float*)d_in[15];
    const float* bn_g = (const float*)d_in[16];
    const float* bn_b = (const float*)d_in[17];
    const float* prelu_a = (const float*)d_in[18];
    float* out = (float*)d_out;

    cudaFuncSetAttribute(k_mma_input, cudaFuncAttributeMaxDynamicSharedMemorySize, SMEM_MMA);
    cudaFuncSetAttribute(k_mma_gemm0, cudaFuncAttributeMaxDynamicSharedMemorySize, SMEM_MMA);
    cudaFuncSetAttribute(k_mma_gemm1, cudaFuncAttributeMaxDynamicSharedMemorySize, SMEM_MMA);

    k_init<<<(N_NODES + 255) / 256, 256>>>(conv0_rw, conv1_rw);
    k_partition<<<(N_NODES + 255) / 256, 256>>>(node_type);
    k_deg<<<(N_EDGES + 255) / 256, 256>>>(edge_index, edge_type);
    k_scan1<<<NSCAN1, 1024>>>();
    k_scan2<<<1, 128>>>();
    k_scan3<<<(N_NODES + 255) / 256, 256>>>();
    k_fill<<<(N_EDGES + 255) / 256, 256>>>(edge_index, edge_type);
    k_prep_all<<<384, 256>>>(lin0_w, lin1_w, conv0_w, conv1_w);

    // input linears (compacted by node type)
    k_mma_input<<<NTILES_M, 256, SMEM_MMA>>>(x0, lidx, lin0_b, 0);
    k_mma_input<<<NTILES_M, 256, SMEM_MMA>>>(x1, lidx, lin1_b, 1);

    // layer 0: gather fused into GEMM staging; BN stats fused in epilogue
    k_mma_gemm0<<<NTILES_M, 256, SMEM_MMA>>>(conv0_b);
    k_bnfinal<<<1, 128>>>(bn_g, bn_b);
    k_bnapply<<<2048, 256>>>(prelu_a);

    // layer 1: gather of y fused into GEMM staging
    k_mma_gemm1<<<NTILES_M, 256, SMEM_MMA>>>(conv1_b, out);

    k_logsoftmax<<<N_NODES, 128>>>(out);
}

// round 12
// speedup vs baseline: 3.0181x; 1.1905x over previous
#include <cuda_runtime.h>
#include <cuda_fp16.h>
#include <cstdint>

#define N_NODES 100000
#define N_EDGES 500000
#define HID 128
#define OUTD 349
#define NET 8
#define BN_EPS 1e-5f
#define MTILE 64
#define NTILES_M ((N_NODES + MTILE - 1) / MTILE)  // 1563
#define NSCAN1 ((N_NODES + 1023) / 1024)          // 98

// ---------------- scratch (static device globals; no allocation) ----------
__device__ float g_h[N_NODES * HID];     // input-linear output; later y = prelu(bn(x))
__device__ float g_x[N_NODES * HID];     // conv0 out + residual (BN input)
__device__ float g_deg0[N_NODES], g_deg1[N_NODES];
__device__ int   g_count[N_NODES];
__device__ int   g_csroff[N_NODES + 1];
__device__ int   g_cursor[N_NODES];
__device__ int   g_bsum[NSCAN1], g_bsumx[NSCAN1];
__device__ int   g_csrsrc[N_EDGES];
__device__ float g_csrw0[N_EDGES], g_csrw1[N_EDGES];
__device__ float g_rws[2 * NET];
__device__ float g_sum[HID], g_sumsq[HID];
__device__ float g_bnscale[HID], g_bnshift[HID];
__device__ int   g_cnt[2];
__device__ int   g_list0[N_NODES], g_list1[N_NODES];

// fp16 hi/lo weight images, layout [tile][k=128][n=128] row-major
__device__ __half g_wI0h[16384], g_wI0l[16384];       // lin0_w
__device__ __half g_wI1h[16384], g_wI1l[16384];       // lin1_w
__device__ __half g_wC0h[16384], g_wC0l[16384];       // conv0_w
__device__ __half g_wC1h[3 * 16384], g_wC1l[3 * 16384];  // conv1_w (3 tiles)

// ---------------- mma.sync GEMM machinery ----------------------------------
// A in fp16 (truncated), W split hi+lo fp16 -> 2 mma terms.
#define ROWB 272                    // 136 fp16 padded row (conflict-free LDSM)
#define OFF_A    0                  // 64 x 272 = 17408
#define OFF_B_HI 17408              // 128 x 272 = 34816
#define OFF_B_LO 52224
#define SMEM_MMA 87040              // 85KB -> 2 CTAs/SM

__device__ __forceinline__ uint32_t smem_u32(const void* p) {
    uint32_t a;
    asm("{ .reg .u64 t; cvta.to.shared.u64 t, %1; cvt.u32.u64 %0, t; }"
        : "=r"(a) : "l"(p));
    return a;
}

__device__ __forceinline__ void ldsm4(uint32_t addr, uint32_t* r) {
    asm volatile("ldmatrix.sync.aligned.m8n8.x4.shared.b16 {%0,%1,%2,%3}, [%4];"
                 : "=r"(r[0]), "=r"(r[1]), "=r"(r[2]), "=r"(r[3]) : "r"(addr));
}
__device__ __forceinline__ void ldsm2t(uint32_t addr, uint32_t* r) {
    asm volatile("ldmatrix.sync.aligned.m8n8.x2.trans.shared.b16 {%0,%1}, [%2];"
                 : "=r"(r[0]), "=r"(r[1]) : "r"(addr));
}
__device__ __forceinline__ void mma16816(float* d, const uint32_t* a, const uint32_t* b) {
    asm volatile(
        "mma.sync.aligned.m16n8k16.row.col.f32.f16.f16.f32 "
        "{%0,%1,%2,%3}, {%4,%5,%6,%7}, {%8,%9}, {%0,%1,%2,%3};"
        : "+f"(d[0]), "+f"(d[1]), "+f"(d[2]), "+f"(d[3])
        : "r"(a[0]), "r"(a[1]), "r"(a[2]), "r"(a[3]), "r"(b[0]), "r"(b[1]));
}

// write 32 fp32 (one quarter-row) as packed fp16 into the A tile
__device__ __forceinline__ void stage_write(char* smem, int row, int q,
                                            const float* a) {
    uint32_t off = (uint32_t)row * ROWB + q * 64;
#pragma unroll
    for (int g = 0; g < 4; g++) {
        uint32_t p[4];
#pragma unroll
        for (int i = 0; i < 4; i++)
            asm("cvt.rn.f16x2.f32 %0, %1, %2;"
                : "=r"(p[i]) : "f"(a[g * 8 + 2 * i + 1]), "f"(a[g * 8 + 2 * i]));
        *reinterpret_cast<uint4*>(smem + OFF_A + off + g * 16) =
            make_uint4(p[0], p[1], p[2], p[3]);
    }
}

// stage 32 fp32 (quarter row) from a contiguous source row
__device__ __forceinline__ void stage_quarter(char* smem, int row, int q,
                                              const float* src) {
    float f[32];
    if (src) {
#pragma unroll
        for (int g = 0; g < 8; g++) {
            float4 v = ((const float4*)src)[g];
            f[g * 4 + 0] = v.x; f[g * 4 + 1] = v.y;
            f[g * 4 + 2] = v.z; f[g * 4 + 3] = v.w;
        }
    } else {
#pragma unroll
        for (int i = 0; i < 32; i++) f[i] = 0.f;
    }
    stage_write(smem, row, q, f);
}

// gather-aggregate a quarter row over incoming edges: sum w * src[csrsrc][q*32..]
__device__ __forceinline__ void stage_gather(char* smem, int row, int q, int gr,
                                             const float* srcbase,
                                             const float* warr) {
    float a[32];
#pragma unroll
    for (int i = 0; i < 32; i++) a[i] = 0.f;
    if (gr < N_NODES) {
        int s0 = g_csroff[gr], s1 = g_csroff[gr + 1];
#pragma unroll 2
        for (int e = s0; e < s1; e++) {
            int src = g_csrsrc[e];
            float w = warr[e];
            const float4* p = (const float4*)(srcbase + (size_t)src * HID + q * 32);
#pragma unroll
            for (int g = 0; g < 8; g++) {
                float4 v = __ldg(&p[g]);
                a[g * 4 + 0] += w * v.x; a[g * 4 + 1] += w * v.y;
                a[g * 4 + 2] += w * v.z; a[g * 4 + 3] += w * v.w;
            }
        }
    }
    stage_write(smem, row, q, a);
}

// copy one pre-split B tile (hi/lo [k][n] images) into padded smem rows
__device__ __forceinline__ void stage_b(char* smem, const __half* bh,
                                        const __half* bl, int tid) {
    const uint4* h4 = (const uint4*)bh;
    const uint4* l4 = (const uint4*)bl;
    for (int i = tid; i < 2048; i += 256) {
        int k = i >> 4, s = i & 15;
        *(uint4*)(smem + OFF_B_HI + k * ROWB + s * 16) = h4[i];
        *(uint4*)(smem + OFF_B_LO + k * ROWB + s * 16) = l4[i];
    }
}

// core: 8 warps; warp (wm=w&1, wn=w>>1): rows wm*32..+31, cols wn*32..+31
__device__ __forceinline__ void mma_core(uint32_t sb, float acc[8][4]) {
    int lane = threadIdx.x & 31;
    int w = threadIdx.x >> 5;
    int wm = w & 1, wn = w >> 1;
    uint32_t aaddr[2], baddr[4];
#pragma unroll
    for (int mt = 0; mt < 2; mt++)
        aaddr[mt] = sb + OFF_A +
                    (uint32_t)(wm * 32 + mt * 16 + (lane & 15)) * ROWB +
                    (lane >> 4) * 16;
#pragma unroll
    for (int nt = 0; nt < 4; nt++)
        baddr[nt] = sb + OFF_B_HI + (uint32_t)(lane & 15) * ROWB +
                    (wn * 32 + nt * 8) * 2;
#pragma unroll
    for (int ks = 0; ks < 8; ks++) {
        uint32_t bh[4][2], bl[4][2];
#pragma unroll
        for (int nt = 0; nt < 4; nt++) {
            uint32_t ba = baddr[nt] + ks * (16 * ROWB);
            ldsm2t(ba, bh[nt]);
            ldsm2t(ba + (OFF_B_LO - OFF_B_HI), bl[nt]);
        }
#pragma unroll
        for (int mt = 0; mt < 2; mt++) {
            uint32_t ah[4];
            ldsm4(aaddr[mt] + ks * 32, ah);
#pragma unroll
            for (int nt = 0; nt < 4; nt++) {
                mma16816(acc[mt * 4 + nt], ah, bh[nt]);
                mma16816(acc[mt * 4 + nt], ah, bl[nt]);
            }
        }
    }
}

// ---------------- prep ----------------------------------------------------
__global__ void k_init(const float* __restrict__ rw0, const float* __restrict__ rw1) {
    int i = blockIdx.x * blockDim.x + threadIdx.x;
    if (i < N_NODES) { g_deg0[i] = 0.0f; g_deg1[i] = 0.0f; g_count[i] = 0; }
    if (i < HID)     { g_sum[i] = 0.0f;  g_sumsq[i] = 0.0f; }
    if (i < 2)       { g_cnt[i] = 0; }
    if (i < NET) {
        float v = rw0[i] * 100.0f;
        g_rws[i] = (v >= 0.0f) ? v : 0.01f * v;
    } else if (i < 2 * NET) {
        float v = rw1[i - NET] * 100.0f;
        g_rws[i] = (v >= 0.0f) ? v : 0.01f * v;
    }
}

// warp-aggregated two-way partition
__global__ void k_partition(const int* __restrict__ ntype) {
    int n = blockIdx.x * blockDim.x + threadIdx.x;
    bool valid = n < N_NODES;
    int t = valid ? ntype[n] : -1;
    int lane = threadIdx.x & 31;
#pragma unroll
    for (int tt = 0; tt < 2; tt++) {
        unsigned m = __ballot_sync(0xffffffffu, t == tt);
        if (t == tt) {
            int leader = __ffs(m) - 1;
            int pos = 0;
            if (lane == leader) pos = atomicAdd(&g_cnt[tt], __popc(m));
            pos = __shfl_sync(m, pos, leader);
            pos += __popc(m & ((1u << lane) - 1u));
            if (tt == 0) g_list0[pos] = n; else g_list1[pos] = n;
        }
    }
}

__global__ void k_deg(const int* __restrict__ ei, const int* __restrict__ et) {
    int e = blockIdx.x * blockDim.x + threadIdx.x;
    if (e >= N_EDGES) return;
    int c = ei[N_EDGES + e];
    int t = et[e];
    atomicAdd(&g_deg0[c], g_rws[t]);
    atomicAdd(&g_deg1[c], g_rws[NET + t]);
    atomicAdd(&g_count[c], 1);
}

// exclusive scan over g_count -> g_csroff (3 phases)
__global__ __launch_bounds__(1024) void k_scan1() {
    __shared__ int s[1024];
    int tid = threadIdx.x;
    int i = blockIdx.x * 1024 + tid;
    int v = (i < N_NODES) ? g_count[i] : 0;
    s[tid] = v;
    __syncthreads();
#pragma unroll
    for (int d = 1; d < 1024; d <<= 1) {
        int t = (tid >= d) ? s[tid - d] : 0;
        __syncthreads();
        s[tid] += t;
        __syncthreads();
    }
    if (i < N_NODES) g_csroff[i] = s[tid] - v;
    if (tid == 1023) g_bsum[blockIdx.x] = s[1023];
}

__global__ __launch_bounds__(128) void k_scan2() {
    __shared__ int s[128];
    int tid = threadIdx.x;
    int v = (tid < NSCAN1) ? g_bsum[tid] : 0;
    s[tid] = v;
    __syncthreads();
#pragma unroll
    for (int d = 1; d < 128; d <<= 1) {
        int t = (tid >= d) ? s[tid - d] : 0;
        __syncthreads();
        s[tid] += t;
        __syncthreads();
    }
    if (tid < NSCAN1) g_bsumx[tid] = s[tid] - v;
}

__global__ void k_scan3() {
    int i = blockIdx.x * blockDim.x + threadIdx.x;
    if (i < N_NODES) {
        int o = g_csroff[i] + g_bsumx[i >> 10];
        g_csroff[i] = o;
        g_cursor[i] = o;
    }
    if (i == 0) g_csroff[N_NODES] = N_EDGES;
}

__global__ void k_fill(const int* __restrict__ ei, const int* __restrict__ et) {
    int e = blockIdx.x * blockDim.x + threadIdx.x;
    if (e >= N_EDGES) return;
    int r = ei[e];
    int c = ei[N_EDGES + e];
    int t = et[e];
    int pos = atomicAdd(&g_cursor[c], 1);
    g_csrsrc[pos] = r;
    g_csrw0[pos] = g_rws[t] / fabsf(g_deg0[c]);
    g_csrw1[pos] = g_rws[NET + t] / fabsf(g_deg1[c]);
}

// all weight hi/lo images in one launch (6 tile-images), fp16 split
__global__ void k_prep_all(const float* __restrict__ lin0_w,
                           const float* __restrict__ lin1_w,
                           const float* __restrict__ conv0_w,
                           const float* __restrict__ conv1_w) {
    int idx = blockIdx.x * blockDim.x + threadIdx.x;
    if (idx >= 6 * 16384) return;
    int img = idx >> 14;
    int rem = idx & 16383;
    int k = rem >> 7, n = rem & 127;
    const float* W;
    int ncols, col, off;
    __half *hi, *lo;
    if (img == 0)      { W = lin0_w;  ncols = HID;  col = n; hi = g_wI0h; lo = g_wI0l; off = rem; }
    else if (img == 1) { W = lin1_w;  ncols = HID;  col = n; hi = g_wI1h; lo = g_wI1l; off = rem; }
    else if (img == 2) { W = conv0_w; ncols = HID;  col = n; hi = g_wC0h; lo = g_wC0l; off = rem; }
    else { int t = img - 3; W = conv1_w; ncols = OUTD; col = t * 128 + n;
           hi = g_wC1h; lo = g_wC1l; off = t * 16384 + rem; }
    float v = (col < ncols) ? W[(size_t)k * ncols + col] : 0.f;
    __half h = __float2half_rn(v);
    hi[off] = h;
    lo[off] = __float2half_rn(v - __half2float(h));
}

// ---------------- mma GEMM kernels ----------------------------------------

// both input linears in ONE launch: blocks [0, nt0) do type 0, rest type 1
__global__ __launch_bounds__(256, 2) void k_mma_input(
    const float* __restrict__ x0, const float* __restrict__ x1,
    const int* __restrict__ lidx,
    const float* __restrict__ b0, const float* __restrict__ b1) {
    const int cnt0 = g_cnt[0], cnt1 = g_cnt[1];
    const int nt0 = (cnt0 + MTILE - 1) / MTILE;
    int pass, tile;
    if ((int)blockIdx.x < nt0) { pass = 0; tile = blockIdx.x; }
    else { pass = 1; tile = blockIdx.x - nt0; }
    const int cnt = pass ? cnt1 : cnt0;
    const int m0 = tile * MTILE;
    if (m0 >= cnt) return;
    const int* list = pass ? g_list1 : g_list0;
    const float* xk = pass ? x1 : x0;
    const float* b = pass ? b1 : b0;
    extern __shared__ char smem[];
    int tid = threadIdx.x;

    stage_b(smem, pass ? g_wI1h : g_wI0h, pass ? g_wI1l : g_wI0l, tid);
    {
        int row = tid >> 2, q = tid & 3;
        int lr = m0 + row;
        const float* src = nullptr;
        if (lr < cnt) src = xk + (size_t)lidx[list[lr]] * HID + q * 32;
        stage_quarter(smem, row, q, src);
    }
    __syncthreads();

    float acc[8][4] = {};
    mma_core(smem_u32(smem), acc);

    int lane = tid & 31, w = tid >> 5, wm = w & 1, wn = w >> 1;
#pragma unroll
    for (int mt = 0; mt < 2; mt++)
#pragma unroll
        for (int half = 0; half < 2; half++) {
            int lr = m0 + wm * 32 + mt * 16 + (lane >> 2) + half * 8;
            if (lr >= cnt) continue;
            float* dst = g_h + (size_t)list[lr] * HID;
#pragma unroll
            for (int nt = 0; nt < 4; nt++) {
                int c = wn * 32 + nt * 8 + (lane & 3) * 2;
                float2 bb = *(const float2*)(b + c);
                float2 o = {acc[mt * 4 + nt][half * 2 + 0] + bb.x,
                            acc[mt * 4 + nt][half * 2 + 1] + bb.y};
                *(float2*)(dst + c) = o;
            }
        }
}

// g_x = gather(h) @ conv0_w + b + g_h ; BN stats fused in epilogue
__global__ __launch_bounds__(256, 2) void k_mma_gemm0(const float* __restrict__ b) {
    const int m0 = blockIdx.x * MTILE;
    extern __shared__ char smem[];
    int tid = threadIdx.x;

    stage_b(smem, g_wC0h, g_wC0l, tid);
    stage_gather(smem, tid >> 2, tid & 3, m0 + (tid >> 2), g_h, g_csrw0);
    __syncthreads();

    float acc[8][4] = {};
    mma_core(smem_u32(smem), acc);

    int lane = tid & 31, w = tid >> 5, wm = w & 1, wn = w >> 1;
    float s[4][2] = {}, s2[4][2] = {};
#pragma unroll
    for (int mt = 0; mt < 2; mt++)
#pragma unroll
        for (int half = 0; half < 2; half++) {
            int gr = m0 + wm * 32 + mt * 16 + (lane >> 2) + half * 8;
            if (gr >= N_NODES) continue;
            float* dst = g_x + (size_t)gr * HID;
            const float* hres = g_h + (size_t)gr * HID;
#pragma unroll
            for (int nt = 0; nt < 4; nt++) {
                int c = wn * 32 + nt * 8 + (lane & 3) * 2;
                float2 bb = *(const float2*)(b + c);
                float2 hv = *(const float2*)(hres + c);
                float2 o = {acc[mt * 4 + nt][half * 2 + 0] + bb.x + hv.x,
                            acc[mt * 4 + nt][half * 2 + 1] + bb.y + hv.y};
                *(float2*)(dst + c) = o;
                s[nt][0] += o.x;  s2[nt][0] += o.x * o.x;
                s[nt][1] += o.y;  s2[nt][1] += o.y * o.y;
            }
        }
#pragma unroll
    for (int d = 4; d < 32; d <<= 1)
#pragma unroll
        for (int nt = 0; nt < 4; nt++) {
            s[nt][0]  += __shfl_xor_sync(0xffffffffu, s[nt][0],  d);
            s[nt][1]  += __shfl_xor_sync(0xffffffffu, s[nt][1],  d);
            s2[nt][0] += __shfl_xor_sync(0xffffffffu, s2[nt][0], d);
            s2[nt][1] += __shfl_xor_sync(0xffffffffu, s2[nt][1], d);
        }
    if ((lane >> 2) == 0) {
#pragma unroll
        for (int nt = 0; nt < 4; nt++) {
            int c = wn * 32 + nt * 8 + (lane & 3) * 2;
            atomicAdd(&g_sum[c],       s[nt][0]);
            atomicAdd(&g_sum[c + 1],   s[nt][1]);
            atomicAdd(&g_sumsq[c],     s2[nt][0]);
            atomicAdd(&g_sumsq[c + 1], s2[nt][1]);
        }
    }
}

// out = gather(y) @ conv1_w + b, then log-softmax in the same kernel
__global__ __launch_bounds__(256, 2) void k_mma_gemm1(const float* __restrict__ b,
                                                      float* __restrict__ out) {
    const int m0 = blockIdx.x * MTILE;
    extern __shared__ char smem[];
    int tid = threadIdx.x;

    stage_gather(smem, tid >> 2, tid & 3, m0 + (tid >> 2), g_h, g_csrw1);

    int lane = tid & 31, w = tid >> 5, wm = w & 1, wn = w >> 1;

    for (int ny = 0; ny < 3; ny++) {
        if (ny) __syncthreads();  // prior mma reads of B done
        stage_b(smem, g_wC1h + (size_t)ny * 16384, g_wC1l + (size_t)ny * 16384, tid);
        __syncthreads();

        float acc[8][4] = {};
        mma_core(smem_u32(smem), acc);

        int n0 = ny * 128;
#pragma unroll
        for (int mt = 0; mt < 2; mt++)
#pragma unroll
            for (int half = 0; half < 2; half++) {
                int gr = m0 + wm * 32 + mt * 16 + (lane >> 2) + half * 8;
                if (gr >= N_NODES) continue;
                float* dst = out + (size_t)gr * OUTD;
#pragma unroll
                for (int nt = 0; nt < 4; nt++) {
                    int c = n0 + wn * 32 + nt * 8 + (lane & 3) * 2;
                    if (c < OUTD)
                        dst[c] = acc[mt * 4 + nt][half * 2 + 0] + b[c];
                    if (c + 1 < OUTD)
                        dst[c + 1] = acc[mt * 4 + nt][half * 2 + 1] + b[c + 1];
                }
            }
    }

    // ---- fused log-softmax over this CTA's 64 rows (out writes visible
    // after __syncthreads per CUDA memory model) ----
    __syncthreads();
    for (int r8 = 0; r8 < 8; r8++) {
        int gr = m0 + w * 8 + r8;
        if (gr >= N_NODES) continue;
        float* row = out + (size_t)gr * OUTD;
        float v[11];
        float mx = -1e30f;
#pragma unroll
        for (int i = 0; i < 11; i++) {
            int c = lane + i * 32;
            v[i] = (c < OUTD) ? row[c] : -1e30f;
            mx = fmaxf(mx, v[i]);
        }
#pragma unroll
        for (int d = 16; d > 0; d >>= 1)
            mx = fmaxf(mx, __shfl_xor_sync(0xffffffffu, mx, d));
        float se = 0.f;
#pragma unroll
        for (int i = 0; i < 11; i++) se += __expf(v[i] - mx);
#pragma unroll
        for (int d = 16; d > 0; d >>= 1)
            se += __shfl_xor_sync(0xffffffffu, se, d);
        float lse = __logf(se) + mx;
#pragma unroll
        for (int i = 0; i < 11; i++) {
            int c = lane + i * 32;
            if (c < OUTD) row[c] = v[i] - lse;
        }
    }
}

// ---------------- BN ------------------------------------------------------
__global__ void k_bnfinal(const float* __restrict__ gamma,
                          const float* __restrict__ beta) {
    int j = threadIdx.x;
    if (j >= HID) return;
    float mean = g_sum[j] / (float)N_NODES;
    float var = g_sumsq[j] / (float)N_NODES - mean * mean;
    float sc = gamma[j] * rsqrtf(var + BN_EPS);
    g_bnscale[j] = sc;
    g_bnshift[j] = beta[j] - mean * sc;
}

// y = prelu(bn(x)) -> overwrite g_h (h is dead after gemm0's residual read)
__global__ void k_bnapply(const float* __restrict__ prelu_a) {
    const float a = __ldg(prelu_a);
    const int total = N_NODES * HID / 4;
    for (int i = blockIdx.x * blockDim.x + threadIdx.x; i < total;
         i += gridDim.x * blockDim.x) {
        int kk = i & 31;
        float4 x = ((const float4*)g_x)[i];
        float4 sc = ((const float4*)g_bnscale)[kk];
        float4 sh = ((const float4*)g_bnshift)[kk];
        float4 v;
        v.x = x.x * sc.x + sh.x;
        v.y = x.y * sc.y + sh.y;
        v.z = x.z * sc.z + sh.z;
        v.w = x.w * sc.w + sh.w;
        v.x = (v.x >= 0.f) ? v.x : a * v.x;
        v.y = (v.y >= 0.f) ? v.y : a * v.y;
        v.z = (v.z >= 0.f) ? v.z : a * v.z;
        v.w = (v.w >= 0.f) ? v.w : a * v.w;
        ((float4*)g_h)[i] = v;
    }
}

// ---------------- launch ---------------------------------------------------
extern "C" void kernel_launch(void* const* d_in, const int* in_sizes, int n_in,
                              void* d_out, int out_size) {
    const float* x0 = (const float*)d_in[0];
    const float* x1 = (const float*)d_in[1];
    const int* edge_index = (const int*)d_in[2];
    const int* edge_type = (const int*)d_in[3];
    const int* node_type = (const int*)d_in[4];
    const int* lidx = (const int*)d_in[5];
    const float* lin0_w = (const float*)d_in[6];
    const float* lin0_b = (const float*)d_in[7];
    const float* lin1_w = (const float*)d_in[8];
    const float* lin1_b = (const float*)d_in[9];
    const float* conv0_w = (const float*)d_in[10];
    const float* conv0_b = (const float*)d_in[11];
    const float* conv0_rw = (const float*)d_in[12];
    const float* conv1_w = (const float*)d_in[13];
    const float* conv1_b = (const float*)d_in[14];
    const float* conv1_rw = (const float*)d_in[15];
    const float* bn_g = (const float*)d_in[16];
    const float* bn_b = (const float*)d_in[17];
    const float* prelu_a = (const float*)d_in[18];
    float* out = (float*)d_out;

    cudaFuncSetAttribute(k_mma_input, cudaFuncAttributeMaxDynamicSharedMemorySize, SMEM_MMA);
    cudaFuncSetAttribute(k_mma_gemm0, cudaFuncAttributeMaxDynamicSharedMemorySize, SMEM_MMA);
    cudaFuncSetAttribute(k_mma_gemm1, cudaFuncAttributeMaxDynamicSharedMemorySize, SMEM_MMA);

    k_init<<<(N_NODES + 255) / 256, 256>>>(conv0_rw, conv1_rw);
    k_partition<<<(N_NODES + 255) / 256, 256>>>(node_type);
    k_deg<<<(N_EDGES + 255) / 256, 256>>>(edge_index, edge_type);
    k_scan1<<<NSCAN1, 1024>>>();
    k_scan2<<<1, 128>>>();
    k_scan3<<<(N_NODES + 255) / 256, 256>>>();
    k_fill<<<(N_EDGES + 255) / 256, 256>>>(edge_index, edge_type);
    k_prep_all<<<384, 256>>>(lin0_w, lin1_w, conv0_w, conv1_w);

    // both input linears in one launch (+2 slack blocks for tile split)
    k_mma_input<<<NTILES_M + 2, 256, SMEM_MMA>>>(x0, x1, lidx, lin0_b, lin1_b);

    // layer 0: gather fused into GEMM staging; BN stats fused in epilogue
    k_mma_gemm0<<<NTILES_M, 256, SMEM_MMA>>>(conv0_b);
    k_bnfinal<<<1, 128>>>(bn_g, bn_b);
    k_bnapply<<<2048, 256>>>(prelu_a);

    // layer 1: gather + GEMM + fused log-softmax
    k_mma_gemm1<<<NTILES_M, 256, SMEM_MMA>>>(conv1_b, out);
}

// round 13
// speedup vs baseline: 3.6732x; 1.2170x over previous
#include <cuda_runtime.h>
#include <cuda_fp16.h>
#include <cstdint>

#define N_NODES 100000
#define N_EDGES 500000
#define HID 128
#define OUTD 349
#define NET 8
#define BN_EPS 1e-5f
#define MTILE 64
#define NTILES_M ((N_NODES + MTILE - 1) / MTILE)  // 1563
#define NSCAN1 ((N_NODES + 1023) / 1024)          // 98

// ---------------- scratch (static device globals; no allocation) ----------
__device__ float g_h[N_NODES * HID];     // input-linear output; later y = prelu(bn(x))
__device__ float g_x[N_NODES * HID];     // conv0 out + residual (BN input)
__device__ float g_deg0[N_NODES], g_deg1[N_NODES];
__device__ int   g_count[N_NODES];
__device__ int   g_csroff[N_NODES + 1];
__device__ int   g_cursor[N_NODES];
__device__ int   g_bsum[NSCAN1], g_bsumx[NSCAN1];
__device__ int   g_csrsrc[N_EDGES];
__device__ float g_csrw0[N_EDGES], g_csrw1[N_EDGES];
__device__ float g_rws[2 * NET];
__device__ float g_sum[HID], g_sumsq[HID];
__device__ int   g_cnt[2];
__device__ int   g_list0[N_NODES], g_list1[N_NODES];

// fp16 hi/lo weight images, layout [tile][k=128][n=128] row-major
__device__ __half g_wI0h[16384], g_wI0l[16384];       // lin0_w
__device__ __half g_wI1h[16384], g_wI1l[16384];       // lin1_w
__device__ __half g_wC0h[16384], g_wC0l[16384];       // conv0_w
__device__ __half g_wC1h[3 * 16384], g_wC1l[3 * 16384];  // conv1_w (3 tiles)

// ---------------- mma.sync GEMM machinery ----------------------------------
// A in fp16 (truncated), W split hi+lo fp16 -> 2 mma terms. 512 threads/CTA.
#define ROWB 272                    // 136 fp16 padded row (conflict-free LDSM)
#define OFF_A    0                  // 64 x 272 = 17408
#define OFF_B_HI 17408              // 128 x 272 = 34816
#define OFF_B_LO 52224
#define SMEM_MMA 87040              // 85KB -> 2 CTAs/SM

__device__ __forceinline__ uint32_t smem_u32(const void* p) {
    uint32_t a;
    asm("{ .reg .u64 t; cvta.to.shared.u64 t, %1; cvt.u32.u64 %0, t; }"
        : "=r"(a) : "l"(p));
    return a;
}

__device__ __forceinline__ void ldsm4(uint32_t addr, uint32_t* r) {
    asm volatile("ldmatrix.sync.aligned.m8n8.x4.shared.b16 {%0,%1,%2,%3}, [%4];"
                 : "=r"(r[0]), "=r"(r[1]), "=r"(r[2]), "=r"(r[3]) : "r"(addr));
}
__device__ __forceinline__ void ldsm2t(uint32_t addr, uint32_t* r) {
    asm volatile("ldmatrix.sync.aligned.m8n8.x2.trans.shared.b16 {%0,%1}, [%2];"
                 : "=r"(r[0]), "=r"(r[1]) : "r"(addr));
}
__device__ __forceinline__ void mma16816(float* d, const uint32_t* a, const uint32_t* b) {
    asm volatile(
        "mma.sync.aligned.m16n8k16.row.col.f32.f16.f16.f32 "
        "{%0,%1,%2,%3}, {%4,%5,%6,%7}, {%8,%9}, {%0,%1,%2,%3};"
        : "+f"(d[0]), "+f"(d[1]), "+f"(d[2]), "+f"(d[3])
        : "r"(a[0]), "r"(a[1]), "r"(a[2]), "r"(a[3]), "r"(b[0]), "r"(b[1]));
}

// write 16 fp32 (one eighth-row) as packed fp16 into the A tile
__device__ __forceinline__ void stage_write16(char* smem, int row, int oct,
                                              const float* a) {
    uint32_t off = (uint32_t)row * ROWB + oct * 32;
#pragma unroll
    for (int g = 0; g < 2; g++) {
        uint32_t p[4];
#pragma unroll
        for (int i = 0; i < 4; i++)
            asm("cvt.rn.f16x2.f32 %0, %1, %2;"
                : "=r"(p[i]) : "f"(a[g * 8 + 2 * i + 1]), "f"(a[g * 8 + 2 * i]));
        *reinterpret_cast<uint4*>(smem + OFF_A + off + g * 16) =
            make_uint4(p[0], p[1], p[2], p[3]);
    }
}

// stage 16 fp32 (eighth row) from a contiguous source row
__device__ __forceinline__ void stage_plain16(char* smem, int row, int oct,
                                              const float* src) {
    float f[16];
    if (src) {
#pragma unroll
        for (int g = 0; g < 4; g++) {
            float4 v = ((const float4*)src)[g];
            f[g * 4 + 0] = v.x; f[g * 4 + 1] = v.y;
            f[g * 4 + 2] = v.z; f[g * 4 + 3] = v.w;
        }
    } else {
#pragma unroll
        for (int i = 0; i < 16; i++) f[i] = 0.f;
    }
    stage_write16(smem, row, oct, f);
}

// gather-aggregate an eighth row over incoming edges
__device__ __forceinline__ void stage_gather16(char* smem, int row, int oct, int gr,
                                               const float* srcbase,
                                               const float* warr) {
    float a[16];
#pragma unroll
    for (int i = 0; i < 16; i++) a[i] = 0.f;
    if (gr < N_NODES) {
        int s0 = g_csroff[gr], s1 = g_csroff[gr + 1];
#pragma unroll 2
        for (int e = s0; e < s1; e++) {
            int src = g_csrsrc[e];
            float w = warr[e];
            const float4* p = (const float4*)(srcbase + (size_t)src * HID + oct * 16);
#pragma unroll
            for (int g = 0; g < 4; g++) {
                float4 v = __ldg(&p[g]);
                a[g * 4 + 0] += w * v.x; a[g * 4 + 1] += w * v.y;
                a[g * 4 + 2] += w * v.z; a[g * 4 + 3] += w * v.w;
            }
        }
    }
    stage_write16(smem, row, oct, a);
}

// copy one pre-split B tile (hi/lo [k][n] images) into padded smem rows
__device__ __forceinline__ void stage_b(char* smem, const __half* bh,
                                        const __half* bl, int tid) {
    const uint4* h4 = (const uint4*)bh;
    const uint4* l4 = (const uint4*)bl;
    for (int i = tid; i < 2048; i += 512) {
        int k = i >> 4, s = i & 15;
        *(uint4*)(smem + OFF_B_HI + k * ROWB + s * 16) = h4[i];
        *(uint4*)(smem + OFF_B_LO + k * ROWB + s * 16) = l4[i];
    }
}

// core: 16 warps; warp (wm=w&1, wn=w>>1 in 0..7): rows wm*32..+31, cols wn*16..+15
__device__ __forceinline__ void mma_core(uint32_t sb, float acc[4][4]) {
    int lane = threadIdx.x & 31;
    int w = threadIdx.x >> 5;
    int wm = w & 1, wn = w >> 1;
    uint32_t aaddr[2], baddr[2];
#pragma unroll
    for (int mt = 0; mt < 2; mt++)
        aaddr[mt] = sb + OFF_A +
                    (uint32_t)(wm * 32 + mt * 16 + (lane & 15)) * ROWB +
                    (lane >> 4) * 16;
#pragma unroll
    for (int nt = 0; nt < 2; nt++)
        baddr[nt] = sb + OFF_B_HI + (uint32_t)(lane & 15) * ROWB +
                    (wn * 16 + nt * 8) * 2;
#pragma unroll
    for (int ks = 0; ks < 8; ks++) {
        uint32_t bh[2][2], bl[2][2];
#pragma unroll
        for (int nt = 0; nt < 2; nt++) {
            uint32_t ba = baddr[nt] + ks * (16 * ROWB);
            ldsm2t(ba, bh[nt]);
            ldsm2t(ba + (OFF_B_LO - OFF_B_HI), bl[nt]);
        }
#pragma unroll
        for (int mt = 0; mt < 2; mt++) {
            uint32_t ah[4];
            ldsm4(aaddr[mt] + ks * 32, ah);
#pragma unroll
            for (int nt = 0; nt < 2; nt++) {
                mma16816(acc[mt * 2 + nt], ah, bh[nt]);
                mma16816(acc[mt * 2 + nt], ah, bl[nt]);
            }
        }
    }
}

// ---------------- prep ----------------------------------------------------
// zero/init + relation weights + ALL weight hi/lo images in one launch
__global__ void k_init(const float* __restrict__ rw0, const float* __restrict__ rw1,
                       const float* __restrict__ lin0_w,
                       const float* __restrict__ lin1_w,
                       const float* __restrict__ conv0_w,
                       const float* __restrict__ conv1_w) {
    int i = blockIdx.x * blockDim.x + threadIdx.x;
    if (i < N_NODES) { g_deg0[i] = 0.0f; g_deg1[i] = 0.0f; g_count[i] = 0; }
    if (i < HID)     { g_sum[i] = 0.0f;  g_sumsq[i] = 0.0f; }
    if (i < 2)       { g_cnt[i] = 0; }
    if (i < NET) {
        float v = rw0[i] * 100.0f;
        g_rws[i] = (v >= 0.0f) ? v : 0.01f * v;
    } else if (i < 2 * NET) {
        float v = rw1[i - NET] * 100.0f;
        g_rws[i] = (v >= 0.0f) ? v : 0.01f * v;
    }
    if (i < 6 * 16384) {
        int img = i >> 14;
        int rem = i & 16383;
        int k = rem >> 7, n = rem & 127;
        const float* W;
        int ncols, col, off;
        __half *hi, *lo;
        if (img == 0)      { W = lin0_w;  ncols = HID;  col = n; hi = g_wI0h; lo = g_wI0l; off = rem; }
        else if (img == 1) { W = lin1_w;  ncols = HID;  col = n; hi = g_wI1h; lo = g_wI1l; off = rem; }
        else if (img == 2) { W = conv0_w; ncols = HID;  col = n; hi = g_wC0h; lo = g_wC0l; off = rem; }
        else { int t = img - 3; W = conv1_w; ncols = OUTD; col = t * 128 + n;
               hi = g_wC1h; lo = g_wC1l; off = t * 16384 + rem; }
        float v = (col < ncols) ? W[(size_t)k * ncols + col] : 0.f;
        __half h = __float2half_rn(v);
        hi[off] = h;
        lo[off] = __float2half_rn(v - __half2float(h));
    }
}

// partition (warp-aggregated) + degree/count accumulation in one launch
__global__ void k_part_deg(const int* __restrict__ ntype,
                           const int* __restrict__ ei,
                           const int* __restrict__ et) {
    int i = blockIdx.x * blockDim.x + threadIdx.x;
    int lane = threadIdx.x & 31;
    int t = (i < N_NODES) ? ntype[i] : -1;
#pragma unroll
    for (int tt = 0; tt < 2; tt++) {
        unsigned m = __ballot_sync(0xffffffffu, t == tt);
        if (t == tt) {
            int leader = __ffs(m) - 1;
            int pos = 0;
            if (lane == leader) pos = atomicAdd(&g_cnt[tt], __popc(m));
            pos = __shfl_sync(m, pos, leader);
            pos += __popc(m & ((1u << lane) - 1u));
            if (tt == 0) g_list0[pos] = i; else g_list1[pos] = i;
        }
    }
    if (i < N_EDGES) {
        int c = ei[N_EDGES + i];
        int ty = et[i];
        atomicAdd(&g_deg0[c], g_rws[ty]);
        atomicAdd(&g_deg1[c], g_rws[NET + ty]);
        atomicAdd(&g_count[c], 1);
    }
}

// exclusive scan over g_count -> g_csroff (3 phases)
__global__ __launch_bounds__(1024) void k_scan1() {
    __shared__ int s[1024];
    int tid = threadIdx.x;
    int i = blockIdx.x * 1024 + tid;
    int v = (i < N_NODES) ? g_count[i] : 0;
    s[tid] = v;
    __syncthreads();
#pragma unroll
    for (int d = 1; d < 1024; d <<= 1) {
        int t = (tid >= d) ? s[tid - d] : 0;
        __syncthreads();
        s[tid] += t;
        __syncthreads();
    }
    if (i < N_NODES) g_csroff[i] = s[tid] - v;
    if (tid == 1023) g_bsum[blockIdx.x] = s[1023];
}

__global__ __launch_bounds__(128) void k_scan2() {
    __shared__ int s[128];
    int tid = threadIdx.x;
    int v = (tid < NSCAN1) ? g_bsum[tid] : 0;
    s[tid] = v;
    __syncthreads();
#pragma unroll
    for (int d = 1; d < 128; d <<= 1) {
        int t = (tid >= d) ? s[tid - d] : 0;
        __syncthreads();
        s[tid] += t;
        __syncthreads();
    }
    if (tid < NSCAN1) g_bsumx[tid] = s[tid] - v;
}

__global__ void k_scan3() {
    int i = blockIdx.x * blockDim.x + threadIdx.x;
    if (i < N_NODES) {
        int o = g_csroff[i] + g_bsumx[i >> 10];
        g_csroff[i] = o;
        g_cursor[i] = o;
    }
    if (i == 0) g_csroff[N_NODES] = N_EDGES;
}

__global__ void k_fill(const int* __restrict__ ei, const int* __restrict__ et) {
    int e = blockIdx.x * blockDim.x + threadIdx.x;
    if (e >= N_EDGES) return;
    int r = ei[e];
    int c = ei[N_EDGES + e];
    int t = et[e];
    int pos = atomicAdd(&g_cursor[c], 1);
    g_csrsrc[pos] = r;
    g_csrw0[pos] = g_rws[t] / fabsf(g_deg0[c]);
    g_csrw1[pos] = g_rws[NET + t] / fabsf(g_deg1[c]);
}

// ---------------- mma GEMM kernels (512 threads) ---------------------------

// both input linears in ONE launch: blocks [0, nt0) do type 0, rest type 1
__global__ __launch_bounds__(512, 2) void k_mma_input(
    const float* __restrict__ x0, const float* __restrict__ x1,
    const int* __restrict__ lidx,
    const float* __restrict__ b0, const float* __restrict__ b1) {
    const int cnt0 = g_cnt[0], cnt1 = g_cnt[1];
    const int nt0 = (cnt0 + MTILE - 1) / MTILE;
    int pass, tile;
    if ((int)blockIdx.x < nt0) { pass = 0; tile = blockIdx.x; }
    else { pass = 1; tile = blockIdx.x - nt0; }
    const int cnt = pass ? cnt1 : cnt0;
    const int m0 = tile * MTILE;
    if (m0 >= cnt) return;
    const int* list = pass ? g_list1 : g_list0;
    const float* xk = pass ? x1 : x0;
    const float* b = pass ? b1 : b0;
    extern __shared__ char smem[];
    int tid = threadIdx.x;

    stage_b(smem, pass ? g_wI1h : g_wI0h, pass ? g_wI1l : g_wI0l, tid);
    {
        int row = tid >> 3, oct = tid & 7;
        int lr = m0 + row;
        const float* src = nullptr;
        if (lr < cnt) src = xk + (size_t)lidx[list[lr]] * HID + oct * 16;
        stage_plain16(smem, row, oct, src);
    }
    __syncthreads();

    float acc[4][4] = {};
    mma_core(smem_u32(smem), acc);

    int lane = tid & 31, w = tid >> 5, wm = w & 1, wn = w >> 1;
#pragma unroll
    for (int mt = 0; mt < 2; mt++)
#pragma unroll
        for (int half = 0; half < 2; half++) {
            int lr = m0 + wm * 32 + mt * 16 + (lane >> 2) + half * 8;
            if (lr >= cnt) continue;
            float* dst = g_h + (size_t)list[lr] * HID;
#pragma unroll
            for (int nt = 0; nt < 2; nt++) {
                int c = wn * 16 + nt * 8 + (lane & 3) * 2;
                float2 bb = *(const float2*)(b + c);
                float2 o = {acc[mt * 2 + nt][half * 2 + 0] + bb.x,
                            acc[mt * 2 + nt][half * 2 + 1] + bb.y};
                *(float2*)(dst + c) = o;
            }
        }
}

// g_x = gather(h) @ conv0_w + b + g_h ; BN stats fused in epilogue
__global__ __launch_bounds__(512, 2) void k_mma_gemm0(const float* __restrict__ b) {
    const int m0 = blockIdx.x * MTILE;
    extern __shared__ char smem[];
    int tid = threadIdx.x;

    stage_b(smem, g_wC0h, g_wC0l, tid);
    stage_gather16(smem, tid >> 3, tid & 7, m0 + (tid >> 3), g_h, g_csrw0);
    __syncthreads();

    float acc[4][4] = {};
    mma_core(smem_u32(smem), acc);

    int lane = tid & 31, w = tid >> 5, wm = w & 1, wn = w >> 1;
    float s[2][2] = {}, s2[2][2] = {};
#pragma unroll
    for (int mt = 0; mt < 2; mt++)
#pragma unroll
        for (int half = 0; half < 2; half++) {
            int gr = m0 + wm * 32 + mt * 16 + (lane >> 2) + half * 8;
            if (gr >= N_NODES) continue;
            float* dst = g_x + (size_t)gr * HID;
            const float* hres = g_h + (size_t)gr * HID;
#pragma unroll
            for (int nt = 0; nt < 2; nt++) {
                int c = wn * 16 + nt * 8 + (lane & 3) * 2;
                float2 bb = *(const float2*)(b + c);
                float2 hv = *(const float2*)(hres + c);
                float2 o = {acc[mt * 2 + nt][half * 2 + 0] + bb.x + hv.x,
                            acc[mt * 2 + nt][half * 2 + 1] + bb.y + hv.y};
                *(float2*)(dst + c) = o;
                s[nt][0] += o.x;  s2[nt][0] += o.x * o.x;
                s[nt][1] += o.y;  s2[nt][1] += o.y * o.y;
            }
        }
#pragma unroll
    for (int d = 4; d < 32; d <<= 1)
#pragma unroll
        for (int nt = 0; nt < 2; nt++) {
            s[nt][0]  += __shfl_xor_sync(0xffffffffu, s[nt][0],  d);
            s[nt][1]  += __shfl_xor_sync(0xffffffffu, s[nt][1],  d);
            s2[nt][0] += __shfl_xor_sync(0xffffffffu, s2[nt][0], d);
            s2[nt][1] += __shfl_xor_sync(0xffffffffu, s2[nt][1], d);
        }
    if ((lane >> 2) == 0) {
#pragma unroll
        for (int nt = 0; nt < 2; nt++) {
            int c = wn * 16 + nt * 8 + (lane & 3) * 2;
            atomicAdd(&g_sum[c],       s[nt][0]);
            atomicAdd(&g_sum[c + 1],   s[nt][1]);
            atomicAdd(&g_sumsq[c],     s2[nt][0]);
            atomicAdd(&g_sumsq[c + 1], s2[nt][1]);
        }
    }
}

// out = gather(y) @ conv1_w + b, then log-softmax in the same kernel
__global__ __launch_bounds__(512, 2) void k_mma_gemm1(const float* __restrict__ b,
                                                      float* __restrict__ out) {
    const int m0 = blockIdx.x * MTILE;
    extern __shared__ char smem[];
    int tid = threadIdx.x;

    stage_gather16(smem, tid >> 3, tid & 7, m0 + (tid >> 3), g_h, g_csrw1);

    int lane = tid & 31, w = tid >> 5, wm = w & 1, wn = w >> 1;

    for (int ny = 0; ny < 3; ny++) {
        if (ny) __syncthreads();  // prior mma reads of B done
        stage_b(smem, g_wC1h + (size_t)ny * 16384, g_wC1l + (size_t)ny * 16384, tid);
        __syncthreads();

        float acc[4][4] = {};
        mma_core(smem_u32(smem), acc);

        int n0 = ny * 128;
#pragma unroll
        for (int mt = 0; mt < 2; mt++)
#pragma unroll
            for (int half = 0; half < 2; half++) {
                int gr = m0 + wm * 32 + mt * 16 + (lane >> 2) + half * 8;
                if (gr >= N_NODES) continue;
                float* dst = out + (size_t)gr * OUTD;
#pragma unroll
                for (int nt = 0; nt < 2; nt++) {
                    int c = n0 + wn * 16 + nt * 8 + (lane & 3) * 2;
                    if (c < OUTD)
                        dst[c] = acc[mt * 2 + nt][half * 2 + 0] + b[c];
                    if (c + 1 < OUTD)
                        dst[c + 1] = acc[mt * 2 + nt][half * 2 + 1] + b[c + 1];
                }
            }
    }

    // ---- fused log-softmax over this CTA's 64 rows ----
    __syncthreads();
#pragma unroll
    for (int r4 = 0; r4 < 4; r4++) {
        int gr = m0 + w * 4 + r4;
        if (gr >= N_NODES) continue;
        float* row = out + (size_t)gr * OUTD;
        float v[11];
        float mx = -1e30f;
#pragma unroll
        for (int i = 0; i < 11; i++) {
            int c = lane + i * 32;
            v[i] = (c < OUTD) ? row[c] : -1e30f;
            mx = fmaxf(mx, v[i]);
        }
#pragma unroll
        for (int d = 16; d > 0; d >>= 1)
            mx = fmaxf(mx, __shfl_xor_sync(0xffffffffu, mx, d));
        float se = 0.f;
#pragma unroll
        for (int i = 0; i < 11; i++) se += __expf(v[i] - mx);
#pragma unroll
        for (int d = 16; d > 0; d >>= 1)
            se += __shfl_xor_sync(0xffffffffu, se, d);
        float lse = __logf(se) + mx;
#pragma unroll
        for (int i = 0; i < 11; i++) {
            int c = lane + i * 32;
            if (c < OUTD) row[c] = v[i] - lse;
        }
    }
}

// ---------------- BN (finalize + apply in one kernel) ----------------------
__global__ void k_bnapply(const float* __restrict__ gamma,
                          const float* __restrict__ beta,
                          const float* __restrict__ prelu_a) {
    __shared__ float ssc[HID], ssh[HID];
    if (threadIdx.x < HID) {
        int j = threadIdx.x;
        float mean = g_sum[j] / (float)N_NODES;
        float var = g_sumsq[j] / (float)N_NODES - mean * mean;
        float sc = gamma[j] * rsqrtf(var + BN_EPS);
        ssc[j] = sc;
        ssh[j] = beta[j] - mean * sc;
    }
    __syncthreads();
    const float a = __ldg(prelu_a);
    const int total = N_NODES * HID / 4;
    for (int i = blockIdx.x * blockDim.x + threadIdx.x; i < total;
         i += gridDim.x * blockDim.x) {
        int kk = i & 31;
        float4 x = ((const float4*)g_x)[i];
        float4 sc = ((const float4*)ssc)[kk];
        float4 sh = ((const float4*)ssh)[kk];
        float4 v;
        v.x = x.x * sc.x + sh.x;
        v.y = x.y * sc.y + sh.y;
        v.z = x.z * sc.z + sh.z;
        v.w = x.w * sc.w + sh.w;
        v.x = (v.x >= 0.f) ? v.x : a * v.x;
        v.y = (v.y >= 0.f) ? v.y : a * v.y;
        v.z = (v.z >= 0.f) ? v.z : a * v.z;
        v.w = (v.w >= 0.f) ? v.w : a * v.w;
        ((float4*)g_h)[i] = v;
    }
}

// ---------------- launch ---------------------------------------------------
extern "C" void kernel_launch(void* const* d_in, const int* in_sizes, int n_in,
                              void* d_out, int out_size) {
    const float* x0 = (const float*)d_in[0];
    const float* x1 = (const float*)d_in[1];
    const int* edge_index = (const int*)d_in[2];
    const int* edge_type = (const int*)d_in[3];
    const int* node_type = (const int*)d_in[4];
    const int* lidx = (const int*)d_in[5];
    const float* lin0_w = (const float*)d_in[6];
    const float* lin0_b = (const float*)d_in[7];
    const float* lin1_w = (const float*)d_in[8];
    const float* lin1_b = (const float*)d_in[9];
    const float* conv0_w = (const float*)d_in[10];
    const float* conv0_b = (const float*)d_in[11];
    const float* conv0_rw = (const float*)d_in[12];
    const float* conv1_w = (const float*)d_in[13];
    const float* conv1_b = (const float*)d_in[14];
    const float* conv1_rw = (const float*)d_in[15];
    const float* bn_g = (const float*)d_in[16];
    const float* bn_b = (const float*)d_in[17];
    const float* prelu_a = (const float*)d_in[18];
    float* out = (float*)d_out;

    cudaFuncSetAttribute(k_mma_input, cudaFuncAttributeMaxDynamicSharedMemorySize, SMEM_MMA);
    cudaFuncSetAttribute(k_mma_gemm0, cudaFuncAttributeMaxDynamicSharedMemorySize, SMEM_MMA);
    cudaFuncSetAttribute(k_mma_gemm1, cudaFuncAttributeMaxDynamicSharedMemorySize, SMEM_MMA);

    // init covers: zeroing, rws, and all 6 weight images (6*16384 = 98304 idx)
    k_init<<<(N_NODES + 255) / 256, 256>>>(conv0_rw, conv1_rw,
                                           lin0_w, lin1_w, conv0_w, conv1_w);
    k_part_deg<<<(N_EDGES + 255) / 256, 256>>>(node_type, edge_index, edge_type);
    k_scan1<<<NSCAN1, 1024>>>();
    k_scan2<<<1, 128>>>();
    k_scan3<<<(N_NODES + 255) / 256, 256>>>();
    k_fill<<<(N_EDGES + 255) / 256, 256>>>(edge_index, edge_type);

    // both input linears in one launch (+2 slack blocks for tile split)
    k_mma_input<<<NTILES_M + 2, 512, SMEM_MMA>>>(x0, x1, lidx, lin0_b, lin1_b);

    // layer 0: gather fused into GEMM staging; BN stats fused in epilogue
    k_mma_gemm0<<<NTILES_M, 512, SMEM_MMA>>>(conv0_b);
    k_bnapply<<<2048, 256>>>(bn_g, bn_b, prelu_a);

    // layer 1: gather + GEMM + fused log-softmax
    k_mma_gemm1<<<NTILES_M, 512, SMEM_MMA>>>(conv1_b, out);
}